// round 1
// baseline (speedup 1.0000x reference)
#include <cuda_runtime.h>
#include <cstdint>

#define BSZ   512
#define TLEN  128
#define ISZ   256
#define HSZ   256
#define NCLS  100
#define NSTEP 26
#define XDIM  512   // context(256) | h(256)
#define GDIM  1024  // 4*H
#define WIH_LD 356  // INPUT_SIZE + NUM_CLASSES
#define BLANK_ID 3

// ------------------------- device scratch (static: no allocs) ---------------
__device__ float g_projH[BSZ * TLEN * HSZ];      // 67 MB
__device__ float g_projh[BSZ * HSZ];
__device__ float g_h[BSZ * HSZ];
__device__ float g_c[BSZ * HSZ];
__device__ float g_X[BSZ * XDIM];
__device__ float g_gates[BSZ * GDIM];
__device__ float g_hs[BSZ * NSTEP * HSZ];        // [b][s][h]
__device__ float g_Wcat[GDIM * XDIM];            // [W_ih[:, :256] | W_hh]
__device__ float g_bias2[GDIM];                  // b_ih + b_hh

// ------------------------- fast math (MUFU, err ~1e-6) ----------------------
__device__ __forceinline__ float fast_tanh(float x) {
    // tanh(x) = 1 - 2/(exp(2x)+1); exp via ex2.approx, div via rcp.approx.
    float e;
    asm("ex2.approx.f32 %0, %1;" : "=f"(e) : "f"(x * 2.88539008177792681f));
    float r;
    asm("rcp.approx.f32 %0, %1;" : "=f"(r) : "f"(e + 1.0f));
    return 1.0f - 2.0f * r;
}

__device__ __forceinline__ float fast_sigmoid(float x) {
    float e;
    asm("ex2.approx.f32 %0, %1;" : "=f"(e) : "f"(-1.44269504088896341f * x));
    float r;
    asm("rcp.approx.f32 %0, %1;" : "=f"(r) : "f"(1.0f + e));
    return r;
}

// ------------------------- init: Wcat, bias2, zero state --------------------
__global__ void init_kernel(const float* __restrict__ W_ih,
                            const float* __restrict__ W_hh,
                            const float* __restrict__ b_ih,
                            const float* __restrict__ b_hh) {
    int idx = blockIdx.x * 256 + threadIdx.x;   // grid covers 524288
    if (idx < GDIM * XDIM) {
        int j = idx >> 9, k = idx & 511;
        g_Wcat[idx] = (k < 256) ? W_ih[j * WIH_LD + k] : W_hh[j * 256 + (k - 256)];
    }
    if (idx < GDIM) g_bias2[idx] = b_ih[idx] + b_hh[idx];
    if (idx < BSZ * HSZ) {
        g_h[idx] = 0.0f;
        g_c[idx] = 0.0f;
        int b = idx >> 8, j = idx & 255;
        g_X[b * XDIM + 256 + j] = 0.0f;   // h-half of X for step 0
    }
}

// ------------------------- generic tiled SGEMM  C = A * B^T -----------------
// A[M,K] row-major (lda), Bw[N,K] row-major (ldb), C[M,N] (ldc).
// MODE 0: plain   MODE 1: +bias[n]   MODE 2: +bias[n] + gsrc[n*gld + 256 + gidx[m*gstr]]
// MODE 3: +bias[n], col BLANK_ID forced to -10000
template <int MODE>
__global__ __launch_bounds__(256) void gemm_nt(
    const float* __restrict__ A, const float* __restrict__ Bw,
    float* __restrict__ Cm,
    int M, int N, int K, int lda, int ldb, int ldc,
    const float* __restrict__ bias,
    const float* __restrict__ gsrc, const int* __restrict__ gidx,
    int gstr, int gld) {

    __shared__ __align__(16) float As[16][64];
    __shared__ __align__(16) float Bs[16][64];

    const int m0 = blockIdx.y * 64, n0 = blockIdx.x * 64;
    const int tid = threadIdx.x;
    const int tx = tid & 15, ty = tid >> 4;
    const int lr = tid >> 2;          // 0..63 : tile row
    const int lc = (tid & 3) << 2;    // 0,4,8,12 : k offset (float4)

    float acc[4][4];
#pragma unroll
    for (int i = 0; i < 4; i++)
#pragma unroll
        for (int j = 0; j < 4; j++) acc[i][j] = 0.0f;

    for (int k0 = 0; k0 < K; k0 += 16) {
        float4 av = make_float4(0.f, 0.f, 0.f, 0.f);
        float4 bv = make_float4(0.f, 0.f, 0.f, 0.f);
        int gm = m0 + lr;
        if (gm < M) av = *(const float4*)(A + (size_t)gm * lda + k0 + lc);
        int gn = n0 + lr;
        if (gn < N) bv = *(const float4*)(Bw + (size_t)gn * ldb + k0 + lc);

        __syncthreads();
        As[lc + 0][lr] = av.x; As[lc + 1][lr] = av.y;
        As[lc + 2][lr] = av.z; As[lc + 3][lr] = av.w;
        Bs[lc + 0][lr] = bv.x; Bs[lc + 1][lr] = bv.y;
        Bs[lc + 2][lr] = bv.z; Bs[lc + 3][lr] = bv.w;
        __syncthreads();

#pragma unroll
        for (int k = 0; k < 16; k++) {
            float4 a = *(const float4*)&As[k][ty * 4];
            float4 b = *(const float4*)&Bs[k][tx * 4];
            acc[0][0] = fmaf(a.x, b.x, acc[0][0]);
            acc[0][1] = fmaf(a.x, b.y, acc[0][1]);
            acc[0][2] = fmaf(a.x, b.z, acc[0][2]);
            acc[0][3] = fmaf(a.x, b.w, acc[0][3]);
            acc[1][0] = fmaf(a.y, b.x, acc[1][0]);
            acc[1][1] = fmaf(a.y, b.y, acc[1][1]);
            acc[1][2] = fmaf(a.y, b.z, acc[1][2]);
            acc[1][3] = fmaf(a.y, b.w, acc[1][3]);
            acc[2][0] = fmaf(a.z, b.x, acc[2][0]);
            acc[2][1] = fmaf(a.z, b.y, acc[2][1]);
            acc[2][2] = fmaf(a.z, b.z, acc[2][2]);
            acc[2][3] = fmaf(a.z, b.w, acc[2][3]);
            acc[3][0] = fmaf(a.w, b.x, acc[3][0]);
            acc[3][1] = fmaf(a.w, b.y, acc[3][1]);
            acc[3][2] = fmaf(a.w, b.z, acc[3][2]);
            acc[3][3] = fmaf(a.w, b.w, acc[3][3]);
        }
    }

#pragma unroll
    for (int i = 0; i < 4; i++) {
        int m = m0 + ty * 4 + i;
        if (m >= M) continue;
        float gval = 0.0f;
        int tgt = 0;
        if (MODE == 2) tgt = gidx[(size_t)m * gstr];
#pragma unroll
        for (int j = 0; j < 4; j++) {
            int n = n0 + tx * 4 + j;
            if (n >= N) continue;
            float v = acc[i][j];
            if (MODE >= 1) v += bias[n];
            if (MODE == 2) v += gsrc[(size_t)n * gld + 256 + tgt];
            if (MODE == 3 && n == BLANK_ID) v = -10000.0f;
            Cm[(size_t)m * ldc + n] = v;
            (void)gval;
        }
    }
}

// ------------------------- attention: score + softmax + context -------------
// One block per batch row b. Writes context into g_X[b][0:256].
__global__ __launch_bounds__(256) void attention_step(
    const float* __restrict__ batchH, const float* __restrict__ wscore) {
    int b = blockIdx.x;
    int tid = threadIdx.x, lane = tid & 31, warp = tid >> 5;

    __shared__ __align__(16) float sh[HSZ];
    __shared__ __align__(16) float sw[HSZ];
    __shared__ float se[TLEN];

    sh[tid] = g_projh[b * HSZ + tid];
    sw[tid] = wscore[tid];
    __syncthreads();

    const float* pH = g_projH + (size_t)b * TLEN * HSZ;
    for (int t = warp; t < TLEN; t += 8) {
        const float4* row = (const float4*)(pH + t * HSZ);
        float acc = 0.0f;
#pragma unroll
        for (int u = 0; u < 2; u++) {
            int idx = lane + u * 32;
            float4 v = row[idx];
            float4 s = *(const float4*)&sh[idx * 4];
            float4 w = *(const float4*)&sw[idx * 4];
            acc = fmaf(w.x, fast_tanh(v.x + s.x), acc);
            acc = fmaf(w.y, fast_tanh(v.y + s.y), acc);
            acc = fmaf(w.z, fast_tanh(v.z + s.z), acc);
            acc = fmaf(w.w, fast_tanh(v.w + s.w), acc);
        }
#pragma unroll
        for (int o = 16; o; o >>= 1) acc += __shfl_xor_sync(0xffffffffu, acc, o);
        if (lane == 0) se[t] = acc;
    }
    __syncthreads();

    // softmax over T=128 (warp 0 handles 4 values/lane)
    if (warp == 0) {
        float v0 = se[lane], v1 = se[lane + 32], v2 = se[lane + 64], v3 = se[lane + 96];
        float mx = fmaxf(fmaxf(v0, v1), fmaxf(v2, v3));
#pragma unroll
        for (int o = 16; o; o >>= 1) mx = fmaxf(mx, __shfl_xor_sync(0xffffffffu, mx, o));
        float e0 = __expf(v0 - mx), e1 = __expf(v1 - mx);
        float e2 = __expf(v2 - mx), e3 = __expf(v3 - mx);
        float sum = e0 + e1 + e2 + e3;
#pragma unroll
        for (int o = 16; o; o >>= 1) sum += __shfl_xor_sync(0xffffffffu, sum, o);
        float inv = 1.0f / sum;
        se[lane] = e0 * inv; se[lane + 32] = e1 * inv;
        se[lane + 64] = e2 * inv; se[lane + 96] = e3 * inv;
    }
    __syncthreads();

    // context[b][tid] = sum_t alpha[t] * batchH[b][t][tid]
    float acc = 0.0f;
    const float* bH = batchH + (size_t)b * TLEN * ISZ + tid;
#pragma unroll 8
    for (int t = 0; t < TLEN; t++) acc = fmaf(se[t], bH[t * ISZ], acc);
    g_X[b * XDIM + tid] = acc;
}

// ------------------------- LSTM pointwise -----------------------------------
__global__ __launch_bounds__(256) void lstm_pointwise(int s) {
    int idx = blockIdx.x * 256 + threadIdx.x;   // BSZ*HSZ threads
    int b = idx >> 8, j = idx & 255;
    const float* g = g_gates + b * GDIM;
    float ig = fast_sigmoid(g[j]);
    float fg = fast_sigmoid(g[256 + j]);
    float gg = fast_tanh(g[512 + j]);
    float og = fast_sigmoid(g[768 + j]);
    float cn = fg * g_c[idx] + ig * gg;
    float hn = og * fast_tanh(cn);
    g_c[idx] = cn;
    g_h[idx] = hn;
    g_X[b * XDIM + 256 + j] = hn;
    g_hs[((size_t)b * NSTEP + s) * HSZ + j] = hn;
}

// ------------------------- launch -------------------------------------------
extern "C" void kernel_launch(void* const* d_in, const int* in_sizes, int n_in,
                              void* d_out, int out_size) {
    const float* batch_H = (const float*)d_in[0];
    const int*   text    = (const int*)d_in[1];
    // d_in[2] = batch_max_length (unused; steps fixed at 26)
    const float* W_i2h   = (const float*)d_in[3];
    const float* W_h2h   = (const float*)d_in[4];
    const float* b_h2h   = (const float*)d_in[5];
    const float* W_score = (const float*)d_in[6];
    const float* W_ih    = (const float*)d_in[7];
    const float* b_ih    = (const float*)d_in[9];
    const float* b_hh    = (const float*)d_in[10];
    const float* W_gen   = (const float*)d_in[11];
    const float* b_gen   = (const float*)d_in[12];
    const float* W_hh    = (const float*)d_in[8];
    float* out = (float*)d_out;

    float *projH, *projh, *h, *X, *gates, *hs, *Wcat, *bias2;
    cudaGetSymbolAddress((void**)&projH, g_projH);
    cudaGetSymbolAddress((void**)&projh, g_projh);
    cudaGetSymbolAddress((void**)&h,     g_h);
    cudaGetSymbolAddress((void**)&X,     g_X);
    cudaGetSymbolAddress((void**)&gates, g_gates);
    cudaGetSymbolAddress((void**)&hs,    g_hs);
    cudaGetSymbolAddress((void**)&Wcat,  g_Wcat);
    cudaGetSymbolAddress((void**)&bias2, g_bias2);

    init_kernel<<<(GDIM * XDIM) / 256, 256>>>(W_ih, W_hh, b_ih, b_hh);

    // proj_H = batch_H @ W_i2h^T   [65536,256] x [256,256]
    gemm_nt<0><<<dim3(HSZ / 64, (BSZ * TLEN) / 64), 256>>>(
        batch_H, W_i2h, projH, BSZ * TLEN, HSZ, ISZ, ISZ, ISZ, HSZ,
        nullptr, nullptr, nullptr, 0, 0);

    for (int s = 0; s < NSTEP; s++) {
        // proj_h = h @ W_h2h^T + b_h2h
        gemm_nt<1><<<dim3(HSZ / 64, BSZ / 64), 256>>>(
            h, W_h2h, projh, BSZ, HSZ, HSZ, HSZ, HSZ, HSZ,
            b_h2h, nullptr, nullptr, 0, 0);
        // attention -> context into X[:, :256]
        attention_step<<<BSZ, 256>>>(batch_H, W_score);
        // gates = X @ Wcat^T + (b_ih+b_hh) + W_ih[:, 256+tgt]
        gemm_nt<2><<<dim3(GDIM / 64, BSZ / 64), 256>>>(
            X, Wcat, gates, BSZ, GDIM, XDIM, XDIM, XDIM, GDIM,
            bias2, W_ih, text + s, NSTEP, WIH_LD);
        // LSTM pointwise -> h, c, X[:, 256:], hs
        lstm_pointwise<<<BSZ, 256>>>(s);
    }

    // logits = hs @ W_gen^T + b_gen, blank col masked; hs rows are (b*26+s)
    gemm_nt<3><<<dim3(2, (BSZ * NSTEP) / 64), 256>>>(
        hs, W_gen, out, BSZ * NSTEP, NCLS, HSZ, HSZ, HSZ, NCLS,
        b_gen, nullptr, nullptr, 0, 0);
}

// round 2
// speedup vs baseline: 1.5925x; 1.5925x over previous
#include <cuda_runtime.h>
#include <cuda_fp16.h>
#include <cstdint>

#define BSZ   512
#define TLEN  128
#define ISZ   256
#define HSZ   256
#define NCLS  100
#define NSTEP 26
#define XDIM  512   // context(256) | h(256)
#define GDIM  1024  // 4*H
#define WIH_LD 356  // INPUT_SIZE + NUM_CLASSES
#define BLANK_ID 3

// ------------------------- device scratch (static: no allocs) ---------------
__device__ __half g_projH_h[BSZ * TLEN * HSZ];   // 33.5 MB (fp16)
__device__ __half g_batchH_h[BSZ * TLEN * ISZ];  // 33.5 MB (fp16)
__device__ float g_projh[BSZ * HSZ];
__device__ float g_h[BSZ * HSZ];
__device__ float g_c[BSZ * HSZ];
__device__ float g_X[BSZ * XDIM];
__device__ float g_gates[BSZ * GDIM];
__device__ float g_hs[BSZ * NSTEP * HSZ];        // [b][s][h]
__device__ float g_Wcat[GDIM * XDIM];            // [W_ih[:, :256] | W_hh]
__device__ float g_bias2[GDIM];                  // b_ih + b_hh

// ------------------------- fast math ----------------------------------------
__device__ __forceinline__ float tanh_fast(float x) {
    float y;
    asm("tanh.approx.f32 %0, %1;" : "=f"(y) : "f"(x));
    return y;
}
__device__ __forceinline__ float fast_sigmoid(float x) {
    // sigmoid(x) = 0.5*(1 + tanh(x/2)) : single MUFU
    return 0.5f * (1.0f + tanh_fast(0.5f * x));
}
__device__ __forceinline__ float to_tf32(float x) {
    uint32_t u;
    asm("cvt.rna.tf32.f32 %0, %1;" : "=r"(u) : "f"(x));
    return __uint_as_float(u);
}

// ------------------------- init: Wcat, bias2, zero state --------------------
__global__ void init_kernel(const float* __restrict__ W_ih,
                            const float* __restrict__ W_hh,
                            const float* __restrict__ b_ih,
                            const float* __restrict__ b_hh) {
    int idx = blockIdx.x * 256 + threadIdx.x;   // grid covers 524288
    if (idx < GDIM * XDIM) {
        int j = idx >> 9, k = idx & 511;
        g_Wcat[idx] = (k < 256) ? W_ih[j * WIH_LD + k] : W_hh[j * 256 + (k - 256)];
    }
    if (idx < GDIM) g_bias2[idx] = b_ih[idx] + b_hh[idx];
    if (idx < BSZ * HSZ) {
        g_h[idx] = 0.0f;
        g_c[idx] = 0.0f;
        int b = idx >> 8, j = idx & 255;
        g_X[b * XDIM + 256 + j] = 0.0f;   // h-half of X for step 0
    }
}

// convert batch_H fp32 -> fp16 (vectorized)
__global__ void convert_half_kernel(const float* __restrict__ src) {
    int i = blockIdx.x * 256 + threadIdx.x;   // each handles 4 floats
    float4 v = ((const float4*)src)[i];
    __half2* dst = (__half2*)g_batchH_h;
    dst[i * 2 + 0] = __floats2half2_rn(v.x, v.y);
    dst[i * 2 + 1] = __floats2half2_rn(v.z, v.w);
}

// ------------------------- tf32 tensor-core GEMM  C = A * B^T ---------------
// A[M,K] row-major (lda), Bw[N,K] row-major (ldb), C[M,N] (ldc).
// Block tile 64x64, 8 warps (4 M x 2 N), warp tile 16x32, mma m16n8k8 tf32.
// MODE 0: plain   MODE 1: +bias[n]
// MODE 2: +bias[n] + gsrc[n*gld + 256 + gidx[m*gstr]]
// MODE 3: +bias[n], col BLANK_ID forced to -10000
// OUT_HALF: write __half instead of float
template <int MODE, bool OUT_HALF>
__global__ __launch_bounds__(256) void mma_gemm(
    const float* __restrict__ A, const float* __restrict__ Bw,
    void* __restrict__ Cm,
    int M, int N, int K, int lda, int ldb, int ldc,
    const float* __restrict__ bias,
    const float* __restrict__ gsrc, const int* __restrict__ gidx,
    int gstr, int gld) {

    __shared__ float As[64][20];   // stride 20 -> conflict-free frag loads
    __shared__ float Bs[64][20];

    const int m0 = blockIdx.y * 64, n0 = blockIdx.x * 64;
    const int tid = threadIdx.x, lane = tid & 31, warp = tid >> 5;
    const int wm = (warp >> 1) * 16;     // warp M offset (0,16,32,48)
    const int wn = (warp & 1) * 32;      // warp N offset (0,32)
    const int gID = lane >> 2, tig = lane & 3;
    const int lr = tid >> 2, lc = (tid & 3) << 2;   // global load map

    float acc[4][4];
#pragma unroll
    for (int i = 0; i < 4; i++)
#pragma unroll
        for (int j = 0; j < 4; j++) acc[i][j] = 0.0f;

    for (int k0 = 0; k0 < K; k0 += 16) {
        float4 av = make_float4(0.f, 0.f, 0.f, 0.f);
        float4 bv = make_float4(0.f, 0.f, 0.f, 0.f);
        if (m0 + lr < M) av = *(const float4*)(A + (size_t)(m0 + lr) * lda + k0 + lc);
        if (n0 + lr < N) bv = *(const float4*)(Bw + (size_t)(n0 + lr) * ldb + k0 + lc);

        __syncthreads();
        As[lr][lc + 0] = to_tf32(av.x); As[lr][lc + 1] = to_tf32(av.y);
        As[lr][lc + 2] = to_tf32(av.z); As[lr][lc + 3] = to_tf32(av.w);
        Bs[lr][lc + 0] = to_tf32(bv.x); Bs[lr][lc + 1] = to_tf32(bv.y);
        Bs[lr][lc + 2] = to_tf32(bv.z); Bs[lr][lc + 3] = to_tf32(bv.w);
        __syncthreads();

#pragma unroll
        for (int kk = 0; kk < 16; kk += 8) {
            uint32_t a0 = __float_as_uint(As[wm + gID][kk + tig]);
            uint32_t a1 = __float_as_uint(As[wm + gID + 8][kk + tig]);
            uint32_t a2 = __float_as_uint(As[wm + gID][kk + tig + 4]);
            uint32_t a3 = __float_as_uint(As[wm + gID + 8][kk + tig + 4]);
#pragma unroll
            for (int nt = 0; nt < 4; nt++) {
                uint32_t b0 = __float_as_uint(Bs[wn + nt * 8 + gID][kk + tig]);
                uint32_t b1 = __float_as_uint(Bs[wn + nt * 8 + gID][kk + tig + 4]);
                asm volatile(
                    "mma.sync.aligned.m16n8k8.row.col.f32.tf32.tf32.f32 "
                    "{%0,%1,%2,%3}, {%4,%5,%6,%7}, {%8,%9}, {%0,%1,%2,%3};"
                    : "+f"(acc[nt][0]), "+f"(acc[nt][1]),
                      "+f"(acc[nt][2]), "+f"(acc[nt][3])
                    : "r"(a0), "r"(a1), "r"(a2), "r"(a3), "r"(b0), "r"(b1));
            }
        }
    }

    // epilogue: thread owns (r0,r1) x (c0,c1) per n-tile
    const int r0 = m0 + wm + gID, r1 = r0 + 8;
    int tgt0 = 0, tgt1 = 0;
    if (MODE == 2) {
        if (r0 < M) tgt0 = gidx[(size_t)r0 * gstr];
        if (r1 < M) tgt1 = gidx[(size_t)r1 * gstr];
    }
#pragma unroll
    for (int nt = 0; nt < 4; nt++) {
        int c0 = n0 + wn + nt * 8 + 2 * tig;
#pragma unroll
        for (int half_r = 0; half_r < 2; half_r++) {
            int r = half_r ? r1 : r0;
            if (r >= M) continue;
            int tgt = half_r ? tgt1 : tgt0;
#pragma unroll
            for (int jj = 0; jj < 2; jj++) {
                int c = c0 + jj;
                if (c >= N) continue;
                float v = acc[nt][half_r * 2 + jj];
                if (MODE >= 1) v += bias[c];
                if (MODE == 2) v += gsrc[(size_t)c * gld + 256 + tgt];
                if (MODE == 3 && c == BLANK_ID) v = -10000.0f;
                if (OUT_HALF)
                    ((__half*)Cm)[(size_t)r * ldc + c] = __float2half_rn(v);
                else
                    ((float*)Cm)[(size_t)r * ldc + c] = v;
            }
        }
    }
}

// ------------------------- attention: score + softmax + context -------------
// One block per batch row b. Reads fp16 projH/batchH. Writes g_X[b][0:256].
__global__ __launch_bounds__(256) void attention_step(
    const float* __restrict__ wscore) {
    int b = blockIdx.x;
    int tid = threadIdx.x, lane = tid & 31, warp = tid >> 5;

    __shared__ __align__(16) float sh[HSZ];
    __shared__ __align__(16) float sw[HSZ];
    __shared__ float se[TLEN];

    sh[tid] = g_projh[b * HSZ + tid];
    sw[tid] = wscore[tid];
    __syncthreads();

    // hoist per-lane slices (avoids 8-way smem conflicts in the t-loop)
    float shl[8], swl[8];
#pragma unroll
    for (int p = 0; p < 8; p++) {
        shl[p] = sh[lane * 8 + p];
        swl[p] = sw[lane * 8 + p];
    }

    const __half* pH = g_projH_h + (size_t)b * TLEN * HSZ;
    for (int t = warp; t < TLEN; t += 8) {
        uint4 v = *(const uint4*)(pH + t * HSZ + lane * 8);   // 8 halves
        const __half2* hv = (const __half2*)&v;
        float acc = 0.0f;
#pragma unroll
        for (int p = 0; p < 4; p++) {
            float2 f = __half22float2(hv[p]);
            acc = fmaf(swl[2 * p], tanh_fast(f.x + shl[2 * p]), acc);
            acc = fmaf(swl[2 * p + 1], tanh_fast(f.y + shl[2 * p + 1]), acc);
        }
#pragma unroll
        for (int o = 16; o; o >>= 1) acc += __shfl_xor_sync(0xffffffffu, acc, o);
        if (lane == 0) se[t] = acc;
    }
    __syncthreads();

    // softmax over T=128 (warp 0, 4 values per lane)
    if (warp == 0) {
        float v0 = se[lane], v1 = se[lane + 32], v2 = se[lane + 64], v3 = se[lane + 96];
        float mx = fmaxf(fmaxf(v0, v1), fmaxf(v2, v3));
#pragma unroll
        for (int o = 16; o; o >>= 1) mx = fmaxf(mx, __shfl_xor_sync(0xffffffffu, mx, o));
        float e0 = __expf(v0 - mx), e1 = __expf(v1 - mx);
        float e2 = __expf(v2 - mx), e3 = __expf(v3 - mx);
        float sum = e0 + e1 + e2 + e3;
#pragma unroll
        for (int o = 16; o; o >>= 1) sum += __shfl_xor_sync(0xffffffffu, sum, o);
        float inv = 1.0f / sum;
        se[lane] = e0 * inv; se[lane + 32] = e1 * inv;
        se[lane + 64] = e2 * inv; se[lane + 96] = e3 * inv;
    }
    __syncthreads();

    // context[b][tid] = sum_t alpha[t] * batchH[b][t][tid]
    float acc = 0.0f;
    const __half* bH = g_batchH_h + (size_t)b * TLEN * ISZ + tid;
#pragma unroll 8
    for (int t = 0; t < TLEN; t++)
        acc = fmaf(se[t], __half2float(bH[t * ISZ]), acc);
    g_X[b * XDIM + tid] = acc;
}

// ------------------------- LSTM pointwise -----------------------------------
__global__ __launch_bounds__(256) void lstm_pointwise(int s) {
    int idx = blockIdx.x * 256 + threadIdx.x;   // BSZ*HSZ threads
    int b = idx >> 8, j = idx & 255;
    const float* g = g_gates + b * GDIM;
    float ig = fast_sigmoid(g[j]);
    float fg = fast_sigmoid(g[256 + j]);
    float gg = tanh_fast(g[512 + j]);
    float og = fast_sigmoid(g[768 + j]);
    float cn = fg * g_c[idx] + ig * gg;
    float hn = og * tanh_fast(cn);
    g_c[idx] = cn;
    g_h[idx] = hn;
    g_X[b * XDIM + 256 + j] = hn;
    g_hs[((size_t)b * NSTEP + s) * HSZ + j] = hn;
}

// ------------------------- launch -------------------------------------------
extern "C" void kernel_launch(void* const* d_in, const int* in_sizes, int n_in,
                              void* d_out, int out_size) {
    const float* batch_H = (const float*)d_in[0];
    const int*   text    = (const int*)d_in[1];
    // d_in[2] = batch_max_length (unused; steps fixed at 26)
    const float* W_i2h   = (const float*)d_in[3];
    const float* W_h2h   = (const float*)d_in[4];
    const float* b_h2h   = (const float*)d_in[5];
    const float* W_score = (const float*)d_in[6];
    const float* W_ih    = (const float*)d_in[7];
    const float* W_hh    = (const float*)d_in[8];
    const float* b_ih    = (const float*)d_in[9];
    const float* b_hh    = (const float*)d_in[10];
    const float* W_gen   = (const float*)d_in[11];
    const float* b_gen   = (const float*)d_in[12];
    float* out = (float*)d_out;

    float *projh, *h, *X, *gates, *hs, *Wcat, *bias2;
    __half* projH_h;
    cudaGetSymbolAddress((void**)&projH_h, g_projH_h);
    cudaGetSymbolAddress((void**)&projh,   g_projh);
    cudaGetSymbolAddress((void**)&h,       g_h);
    cudaGetSymbolAddress((void**)&X,       g_X);
    cudaGetSymbolAddress((void**)&gates,   g_gates);
    cudaGetSymbolAddress((void**)&hs,      g_hs);
    cudaGetSymbolAddress((void**)&Wcat,    g_Wcat);
    cudaGetSymbolAddress((void**)&bias2,   g_bias2);

    init_kernel<<<(GDIM * XDIM) / 256, 256>>>(W_ih, W_hh, b_ih, b_hh);
    convert_half_kernel<<<(BSZ * TLEN * ISZ / 4) / 256, 256>>>(batch_H);

    // proj_H = batch_H @ W_i2h^T -> fp16   [65536,256] x [256,256]
    mma_gemm<0, true><<<dim3(HSZ / 64, (BSZ * TLEN) / 64), 256>>>(
        batch_H, W_i2h, projH_h, BSZ * TLEN, HSZ, ISZ, ISZ, ISZ, HSZ,
        nullptr, nullptr, nullptr, 0, 0);

    for (int s = 0; s < NSTEP; s++) {
        // proj_h = h @ W_h2h^T + b_h2h
        mma_gemm<1, false><<<dim3(HSZ / 64, BSZ / 64), 256>>>(
            h, W_h2h, projh, BSZ, HSZ, HSZ, HSZ, HSZ, HSZ,
            b_h2h, nullptr, nullptr, 0, 0);
        // attention -> context into X[:, :256]
        attention_step<<<BSZ, 256>>>(W_score);
        // gates = X @ Wcat^T + (b_ih+b_hh) + W_ih[:, 256+tgt]
        mma_gemm<2, false><<<dim3(GDIM / 64, BSZ / 64), 256>>>(
            X, Wcat, gates, BSZ, GDIM, XDIM, XDIM, XDIM, GDIM,
            bias2, W_ih, text + s, NSTEP, WIH_LD);
        // LSTM pointwise -> h, c, X[:, 256:], hs
        lstm_pointwise<<<BSZ, 256>>>(s);
    }

    // logits = hs @ W_gen^T + b_gen, blank col masked
    mma_gemm<3, false><<<dim3(2, (BSZ * NSTEP) / 64), 256>>>(
        hs, W_gen, out, BSZ * NSTEP, NCLS, HSZ, HSZ, HSZ, NCLS,
        b_gen, nullptr, nullptr, 0, 0);
}

// round 3
// speedup vs baseline: 2.5112x; 1.5769x over previous
#include <cuda_runtime.h>
#include <cuda_fp16.h>
#include <cstdint>

#define BSZ   512
#define TLEN  128
#define ISZ   256
#define HSZ   256
#define NCLS  100
#define NSTEP 26
#define XDIM  512
#define GDIM  1024
#define WIH_LD 356
#define BLANK_ID 3
#define RPB   4      // rows per block in step_fused

// ------------------------- device scratch -----------------------------------
__device__ __half g_projH_h[BSZ * TLEN * HSZ];
__device__ __half g_batchH_h[BSZ * TLEN * ISZ];
__device__ __half g_X_h[BSZ * XDIM];
__device__ float  g_gates[BSZ * GDIM];
__device__ float  g_c[BSZ * HSZ];
__device__ __half g_hs_h[BSZ * NSTEP * HSZ];
__device__ __half g_Wcat_h[GDIM * XDIM];
__device__ __half g_Wh2h_h[HSZ * HSZ];
__device__ __half g_Wi2h_h[HSZ * ISZ];
__device__ __half g_Wgen_h[NCLS * HSZ];
__device__ float  g_bias2[GDIM];

// ------------------------- fast math ----------------------------------------
__device__ __forceinline__ float tanh_fast(float x) {
    float y;
    asm("tanh.approx.f32 %0, %1;" : "=f"(y) : "f"(x));
    return y;
}
__device__ __forceinline__ float fast_sigmoid(float x) {
    return 0.5f * (1.0f + tanh_fast(0.5f * x));
}

// ------------------------- init ----------------------------------------------
__global__ void init_kernel(const float* __restrict__ W_ih,
                            const float* __restrict__ W_hh,
                            const float* __restrict__ b_ih,
                            const float* __restrict__ b_hh,
                            const float* __restrict__ W_i2h,
                            const float* __restrict__ W_h2h,
                            const float* __restrict__ W_gen) {
    int idx = blockIdx.x * 256 + threadIdx.x;   // 2048 blocks -> 524288
    if (idx < GDIM * XDIM) {
        int j = idx >> 9, k = idx & 511;
        float v = (k < 256) ? W_ih[j * WIH_LD + k] : W_hh[j * 256 + (k - 256)];
        g_Wcat_h[idx] = __float2half_rn(v);
    }
    if (idx < HSZ * HSZ) {
        g_Wh2h_h[idx] = __float2half_rn(W_h2h[idx]);
        g_Wi2h_h[idx] = __float2half_rn(W_i2h[idx]);
    }
    if (idx < NCLS * HSZ) g_Wgen_h[idx] = __float2half_rn(W_gen[idx]);
    if (idx < GDIM) g_bias2[idx] = b_ih[idx] + b_hh[idx];
    if (idx < BSZ * HSZ) g_c[idx] = 0.0f;
}

// ------------------------- fp16 MMA GEMM  C = A * B^T -----------------------
// Block 64x64, 8 warps (4M x 2N), warp tile 16x32, mma m16n8k16 f16->f32.
// Register-prefetch pipelined K loop (chunks of 32).
// M must be a multiple of 64; N/K guards as noted.
// MODE 0: plain  1: +bias[n]  2: +bias[n]+gsrc[n*gld+256+gidx[m*gstr]]
// MODE 3: +bias[n], col BLANK_ID := -10000
template <int MODE, bool OUT_HALF, bool A_HALF, bool DUMP_A>
__global__ __launch_bounds__(256) void hgemm(
    const void* __restrict__ Aptr, const __half* __restrict__ Bw,
    void* __restrict__ Cm,
    int M, int N, int K, int lda, int ldb, int ldc,
    const float* __restrict__ bias,
    const float* __restrict__ gsrc, const int* __restrict__ gidx,
    int gstr, int gld) {

    __shared__ __half As[64 * 40];   // stride 40 halves: 16B-aligned, conflict-free
    __shared__ __half Bs[64 * 40];

    const int m0 = blockIdx.y * 64, n0 = blockIdx.x * 64;
    const int tid = threadIdx.x, lane = tid & 31, warp = tid >> 5;
    const int wm = (warp >> 1) * 16, wn = (warp & 1) * 32;
    const int gID = lane >> 2, tig = lane & 3;
    const int lr = tid >> 2, lc = (tid & 3) * 8;

    float acc[4][4];
#pragma unroll
    for (int i = 0; i < 4; i++)
#pragma unroll
        for (int j = 0; j < 4; j++) acc[i][j] = 0.0f;

    auto loadA = [&](int k0) -> uint4 {
        if (A_HALF) {
            const __half* A = (const __half*)Aptr;
            return *(const uint4*)(A + (size_t)(m0 + lr) * lda + k0 + lc);
        } else {
            const float* A = (const float*)Aptr;
            const float* p = A + (size_t)(m0 + lr) * lda + k0 + lc;
            float4 f0 = *(const float4*)p;
            float4 f1 = *(const float4*)(p + 4);
            uint4 r;
            __half2 h;
            h = __floats2half2_rn(f0.x, f0.y); r.x = *(uint32_t*)&h;
            h = __floats2half2_rn(f0.z, f0.w); r.y = *(uint32_t*)&h;
            h = __floats2half2_rn(f1.x, f1.y); r.z = *(uint32_t*)&h;
            h = __floats2half2_rn(f1.z, f1.w); r.w = *(uint32_t*)&h;
            return r;
        }
    };
    auto loadB = [&](int k0) -> uint4 {
        if (n0 + lr < N)
            return *(const uint4*)(Bw + (size_t)(n0 + lr) * ldb + k0 + lc);
        return make_uint4(0u, 0u, 0u, 0u);
    };

    uint4 aR = loadA(0), bR = loadB(0);
    const int iters = K >> 5;

    for (int it = 0; it < iters; it++) {
        __syncthreads();
        *(uint4*)&As[lr * 40 + lc] = aR;
        *(uint4*)&Bs[lr * 40 + lc] = bR;
        if (DUMP_A && blockIdx.x == 0) {
            *(uint4*)(g_batchH_h + (size_t)(m0 + lr) * ISZ + it * 32 + lc) = aR;
        }
        __syncthreads();
        if (it + 1 < iters) {
            aR = loadA((it + 1) << 5);
            bR = loadB((it + 1) << 5);
        }
#pragma unroll
        for (int kk = 0; kk < 32; kk += 16) {
            uint32_t a0 = *(uint32_t*)&As[(wm + gID) * 40 + kk + tig * 2];
            uint32_t a1 = *(uint32_t*)&As[(wm + gID + 8) * 40 + kk + tig * 2];
            uint32_t a2 = *(uint32_t*)&As[(wm + gID) * 40 + kk + 8 + tig * 2];
            uint32_t a3 = *(uint32_t*)&As[(wm + gID + 8) * 40 + kk + 8 + tig * 2];
#pragma unroll
            for (int nt = 0; nt < 4; nt++) {
                uint32_t b0 = *(uint32_t*)&Bs[(wn + nt * 8 + gID) * 40 + kk + tig * 2];
                uint32_t b1 = *(uint32_t*)&Bs[(wn + nt * 8 + gID) * 40 + kk + 8 + tig * 2];
                asm volatile(
                    "mma.sync.aligned.m16n8k16.row.col.f32.f16.f16.f32 "
                    "{%0,%1,%2,%3}, {%4,%5,%6,%7}, {%8,%9}, {%0,%1,%2,%3};"
                    : "+f"(acc[nt][0]), "+f"(acc[nt][1]),
                      "+f"(acc[nt][2]), "+f"(acc[nt][3])
                    : "r"(a0), "r"(a1), "r"(a2), "r"(a3), "r"(b0), "r"(b1));
            }
        }
    }

    const int r0 = m0 + wm + gID, r1 = r0 + 8;
    int tgt0 = 0, tgt1 = 0;
    if (MODE == 2) {
        tgt0 = gidx[(size_t)r0 * gstr];
        tgt1 = gidx[(size_t)r1 * gstr];
    }
#pragma unroll
    for (int nt = 0; nt < 4; nt++) {
        int cbase = n0 + wn + nt * 8 + 2 * tig;
#pragma unroll
        for (int hr = 0; hr < 2; hr++) {
            int r = hr ? r1 : r0;
            int tgt = hr ? tgt1 : tgt0;
#pragma unroll
            for (int jj = 0; jj < 2; jj++) {
                int c = cbase + jj;
                if (c >= N) continue;
                float v = acc[nt][hr * 2 + jj];
                if (MODE >= 1) v += bias[c];
                if (MODE == 2) v += gsrc[(size_t)c * gld + 256 + tgt];
                if (MODE == 3 && c == BLANK_ID) v = -10000.0f;
                if (OUT_HALF)
                    ((__half*)Cm)[(size_t)r * ldc + c] = __float2half_rn(v);
                else
                    ((float*)Cm)[(size_t)r * ldc + c] = v;
            }
        }
    }
}

// ------------------------- fused per-step kernel -----------------------------
// Block handles RPB=4 batch rows: LSTM(s-1) -> h; projh = h@W_h2h^T + b;
// scores+softmax+context; writes context & h halves of g_X_h, hs.
__global__ __launch_bounds__(256) void step_fused(
    int s, const float* __restrict__ b_h2h, const float* __restrict__ wscore) {
    const int tid = threadIdx.x, lane = tid & 31, warp = tid >> 5;
    const int b0 = blockIdx.x * RPB;

    __shared__ float sh_h[RPB][HSZ];
    __shared__ float sp[RPB][HSZ];
    __shared__ float sw[HSZ];
    __shared__ float se[RPB][TLEN];
    __shared__ float red[4][RPB][64][4];

    sw[tid] = wscore[tid];

    // ---- LSTM from gates(s-1)
    {
        const int r = tid >> 6, jb = tid & 63;
        const int row = b0 + r;
        if (s > 0) {
            const float* g = g_gates + (size_t)row * GDIM;
            float* cp = g_c + (size_t)row * HSZ;
#pragma unroll
            for (int jj = 0; jj < 4; jj++) {
                int j = jb + (jj << 6);
                float ig = fast_sigmoid(g[j]);
                float fg = fast_sigmoid(g[j + 256]);
                float gg = tanh_fast(g[j + 512]);
                float og = fast_sigmoid(g[j + 768]);
                float cn = fg * cp[j] + ig * gg;
                float hn = og * tanh_fast(cn);
                cp[j] = cn;
                sh_h[r][j] = hn;
                __half hh = __float2half_rn(hn);
                g_X_h[(size_t)row * XDIM + 256 + j] = hh;
                g_hs_h[((size_t)row * NSTEP + (s - 1)) * HSZ + j] = hh;
            }
        } else {
#pragma unroll
            for (int jj = 0; jj < 4; jj++) {
                int j = jb + (jj << 6);
                sh_h[r][j] = 0.0f;
                g_X_h[(size_t)row * XDIM + 256 + j] = __float2half_rn(0.0f);
            }
        }
    }
    __syncthreads();

    // ---- projh: k-split (q = k-quarter), thread owns 4 j's for all 4 rows
    {
        const int q = tid >> 6, jb = tid & 63;
        const int kbase = q << 6;
        float a[4][RPB];
#pragma unroll
        for (int jj = 0; jj < 4; jj++)
#pragma unroll
            for (int r = 0; r < RPB; r++) a[jj][r] = 0.0f;

        for (int kk = 0; kk < 64; kk += 8) {
            float4 hA[RPB], hB[RPB];
#pragma unroll
            for (int r = 0; r < RPB; r++) {
                hA[r] = *(const float4*)&sh_h[r][kbase + kk];
                hB[r] = *(const float4*)&sh_h[r][kbase + kk + 4];
            }
#pragma unroll
            for (int jj = 0; jj < 4; jj++) {
                int j = jb + (jj << 6);
                uint4 wv = *(const uint4*)(g_Wh2h_h + (size_t)j * HSZ + kbase + kk);
                const __half2* wh = (const __half2*)&wv;
                float2 w0 = __half22float2(wh[0]);
                float2 w1 = __half22float2(wh[1]);
                float2 w2 = __half22float2(wh[2]);
                float2 w3 = __half22float2(wh[3]);
#pragma unroll
                for (int r = 0; r < RPB; r++) {
                    float t0 = fmaf(w0.x, hA[r].x, w0.y * hA[r].y);
                    float t1 = fmaf(w1.x, hA[r].z, w1.y * hA[r].w);
                    float t2 = fmaf(w2.x, hB[r].x, w2.y * hB[r].y);
                    float t3 = fmaf(w3.x, hB[r].z, w3.y * hB[r].w);
                    a[jj][r] += (t0 + t1) + (t2 + t3);
                }
            }
        }
#pragma unroll
        for (int r = 0; r < RPB; r++) {
            float4 v = make_float4(a[0][r], a[1][r], a[2][r], a[3][r]);
            *(float4*)&red[q][r][jb][0] = v;
        }
    }
    __syncthreads();
    {
        const int r = tid >> 6, jb = tid & 63;
        float4 v0 = *(const float4*)&red[0][r][jb][0];
        float4 v1 = *(const float4*)&red[1][r][jb][0];
        float4 v2 = *(const float4*)&red[2][r][jb][0];
        float4 v3 = *(const float4*)&red[3][r][jb][0];
        sp[r][jb]       = v0.x + v1.x + v2.x + v3.x + b_h2h[jb];
        sp[r][jb + 64]  = v0.y + v1.y + v2.y + v3.y + b_h2h[jb + 64];
        sp[r][jb + 128] = v0.z + v1.z + v2.z + v3.z + b_h2h[jb + 128];
        sp[r][jb + 192] = v0.w + v1.w + v2.w + v3.w + b_h2h[jb + 192];
    }
    __syncthreads();

    // ---- scores: warp pair per row, 64 t's per warp
    {
        const int r = warp >> 1;
        const int tb = (warp & 1) << 6;
        float spl[8], swl[8];
#pragma unroll
        for (int p = 0; p < 8; p++) {
            spl[p] = sp[r][lane * 8 + p];
            swl[p] = sw[lane * 8 + p];
        }
        const __half* pH = g_projH_h + ((size_t)(b0 + r) * TLEN + tb) * HSZ + lane * 8;
#pragma unroll 2
        for (int t = 0; t < 64; t++) {
            uint4 v = *(const uint4*)(pH + t * HSZ);
            const __half2* hv = (const __half2*)&v;
            float acc = 0.0f;
#pragma unroll
            for (int p = 0; p < 4; p++) {
                float2 f = __half22float2(hv[p]);
                acc = fmaf(swl[2 * p],     tanh_fast(f.x + spl[2 * p]),     acc);
                acc = fmaf(swl[2 * p + 1], tanh_fast(f.y + spl[2 * p + 1]), acc);
            }
#pragma unroll
            for (int o = 16; o; o >>= 1) acc += __shfl_xor_sync(0xffffffffu, acc, o);
            if (lane == 0) se[r][tb + t] = acc;
        }
    }
    __syncthreads();

    // ---- softmax per row (warps 0..3)
    if (warp < RPB) {
        float v0 = se[warp][lane], v1 = se[warp][lane + 32];
        float v2 = se[warp][lane + 64], v3 = se[warp][lane + 96];
        float mx = fmaxf(fmaxf(v0, v1), fmaxf(v2, v3));
#pragma unroll
        for (int o = 16; o; o >>= 1) mx = fmaxf(mx, __shfl_xor_sync(0xffffffffu, mx, o));
        float e0 = __expf(v0 - mx), e1 = __expf(v1 - mx);
        float e2 = __expf(v2 - mx), e3 = __expf(v3 - mx);
        float sum = e0 + e1 + e2 + e3;
#pragma unroll
        for (int o = 16; o; o >>= 1) sum += __shfl_xor_sync(0xffffffffu, sum, o);
        float inv = 1.0f / sum;
        se[warp][lane] = e0 * inv;        se[warp][lane + 32] = e1 * inv;
        se[warp][lane + 64] = e2 * inv;   se[warp][lane + 96] = e3 * inv;
    }
    __syncthreads();

    // ---- context -> g_X_h[:, :256]
    {
        const int r = tid >> 6;
        const int c0 = tid & 63, c1 = c0 + 64;   // half2 columns
        const __half2* bH = (const __half2*)(g_batchH_h + (size_t)(b0 + r) * TLEN * ISZ);
        float2 a0 = make_float2(0.f, 0.f), a1 = make_float2(0.f, 0.f);
#pragma unroll 4
        for (int t = 0; t < TLEN; t++) {
            float al = se[r][t];
            float2 x0 = __half22float2(bH[t * 128 + c0]);
            float2 x1 = __half22float2(bH[t * 128 + c1]);
            a0.x = fmaf(al, x0.x, a0.x); a0.y = fmaf(al, x0.y, a0.y);
            a1.x = fmaf(al, x1.x, a1.x); a1.y = fmaf(al, x1.y, a1.y);
        }
        __half2* X2 = (__half2*)(g_X_h + (size_t)(b0 + r) * XDIM);
        X2[c0] = __floats2half2_rn(a0.x, a0.y);
        X2[c1] = __floats2half2_rn(a1.x, a1.y);
    }
}

// ------------------------- final LSTM (hs[25]) -------------------------------
__global__ __launch_bounds__(256) void lstm_final() {
    int row = blockIdx.x, j = threadIdx.x;
    const float* g = g_gates + (size_t)row * GDIM;
    float ig = fast_sigmoid(g[j]);
    float fg = fast_sigmoid(g[j + 256]);
    float gg = tanh_fast(g[j + 512]);
    float og = fast_sigmoid(g[j + 768]);
    float cn = fg * g_c[(size_t)row * HSZ + j] + ig * gg;
    float hn = og * tanh_fast(cn);
    g_hs_h[((size_t)row * NSTEP + (NSTEP - 1)) * HSZ + j] = __float2half_rn(hn);
}

// ------------------------- launch -------------------------------------------
extern "C" void kernel_launch(void* const* d_in, const int* in_sizes, int n_in,
                              void* d_out, int out_size) {
    const float* batch_H = (const float*)d_in[0];
    const int*   text    = (const int*)d_in[1];
    const float* W_i2h   = (const float*)d_in[3];
    const float* W_h2h   = (const float*)d_in[4];
    const float* b_h2h   = (const float*)d_in[5];
    const float* W_score = (const float*)d_in[6];
    const float* W_ih    = (const float*)d_in[7];
    const float* W_hh    = (const float*)d_in[8];
    const float* b_ih    = (const float*)d_in[9];
    const float* b_hh    = (const float*)d_in[10];
    const float* W_gen   = (const float*)d_in[11];
    const float* b_gen   = (const float*)d_in[12];
    float* out = (float*)d_out;

    __half *projH_h, *Wi2h_h, *Wcat_h, *Wgen_h, *X_h, *hs_h;
    float *gates, *bias2;
    cudaGetSymbolAddress((void**)&projH_h, g_projH_h);
    cudaGetSymbolAddress((void**)&Wi2h_h,  g_Wi2h_h);
    cudaGetSymbolAddress((void**)&Wcat_h,  g_Wcat_h);
    cudaGetSymbolAddress((void**)&Wgen_h,  g_Wgen_h);
    cudaGetSymbolAddress((void**)&X_h,     g_X_h);
    cudaGetSymbolAddress((void**)&hs_h,    g_hs_h);
    cudaGetSymbolAddress((void**)&gates,   g_gates);
    cudaGetSymbolAddress((void**)&bias2,   g_bias2);

    init_kernel<<<2048, 256>>>(W_ih, W_hh, b_ih, b_hh, W_i2h, W_h2h, W_gen);

    // proj_H = batch_H @ W_i2h^T -> fp16; also dumps batch_H as fp16
    hgemm<0, true, false, true><<<dim3(4, 1024), 256>>>(
        batch_H, Wi2h_h, projH_h, BSZ * TLEN, HSZ, ISZ, ISZ, ISZ, HSZ,
        nullptr, nullptr, nullptr, 0, 0);

    for (int s = 0; s < NSTEP; s++) {
        step_fused<<<BSZ / RPB, 256>>>(s, b_h2h, W_score);
        hgemm<2, false, true, false><<<dim3(16, 8), 256>>>(
            X_h, Wcat_h, gates, BSZ, GDIM, XDIM, XDIM, XDIM, GDIM,
            bias2, W_ih, text + s, NSTEP, WIH_LD);
    }

    lstm_final<<<BSZ, 256>>>();

    // logits = hs @ W_gen^T + b_gen, blank masked
    hgemm<3, false, true, false><<<dim3(2, (BSZ * NSTEP) / 64), 256>>>(
        hs_h, Wgen_h, out, BSZ * NSTEP, NCLS, HSZ, HSZ, HSZ, NCLS,
        b_gen, nullptr, nullptr, 0, 0);
}

// round 4
// speedup vs baseline: 2.8768x; 1.1456x over previous
#include <cuda_runtime.h>
#include <cuda_fp16.h>
#include <cstdint>

#define BSZ   512
#define TLEN  128
#define ISZ   256
#define HSZ   256
#define NCLS  100
#define NSTEP 26
#define XDIM  512
#define GDIM  1024
#define WIH_LD 356
#define BLANK_ID 3
#define RPB   4
#define NBLK  128
#define BSTR  520          // smem tile row stride (halves): conflict-free
#define SMEM_BYTES (2 * 2 * 64 * BSTR + 6912 * 4)   // 133120 + 27648 = 160768

// ------------------------- device scratch -----------------------------------
__device__ __half g_projH_h[BSZ * TLEN * HSZ];
__device__ __half g_batchH_h[BSZ * TLEN * ISZ];
__device__ __half g_X_h[BSZ * XDIM];
__device__ float  g_gates[BSZ * GDIM];
__device__ float  g_c[BSZ * HSZ];
__device__ __half g_hs_h[BSZ * NSTEP * HSZ];
__device__ __half g_Wcat_h[GDIM * XDIM];
__device__ __half g_Wh2h_h[HSZ * HSZ];
__device__ __half g_Wi2h_h[HSZ * ISZ];
__device__ __half g_Wgen_h[NCLS * HSZ];
__device__ float  g_bias2[GDIM];
// grid barrier state (replay-safe: count self-resets, epoch monotonic)
__device__ unsigned g_count;
__device__ volatile unsigned g_epoch;

// ------------------------- fast math ----------------------------------------
__device__ __forceinline__ float tanh_fast(float x) {
    float y;
    asm("tanh.approx.f32 %0, %1;" : "=f"(y) : "f"(x));
    return y;
}
__device__ __forceinline__ float fast_sigmoid(float x) {
    return 0.5f * (1.0f + tanh_fast(0.5f * x));
}

// ------------------------- grid barrier --------------------------------------
__device__ __forceinline__ void grid_sync() {
    __syncthreads();
    if (threadIdx.x == 0) {
        unsigned my = g_epoch;
        __threadfence();
        unsigned old = atomicAdd(&g_count, 1u);
        if (old == NBLK - 1) {
            g_count = 0;
            __threadfence();
            g_epoch = my + 1;
        } else {
            while (g_epoch == my) { __nanosleep(64); }
            __threadfence();
        }
    }
    __syncthreads();
}

// ------------------------- init ----------------------------------------------
__global__ void init_kernel(const float* __restrict__ W_ih,
                            const float* __restrict__ W_hh,
                            const float* __restrict__ b_ih,
                            const float* __restrict__ b_hh,
                            const float* __restrict__ W_i2h,
                            const float* __restrict__ W_h2h,
                            const float* __restrict__ W_gen) {
    int idx = blockIdx.x * 256 + threadIdx.x;
    if (idx < GDIM * XDIM) {
        int j = idx >> 9, k = idx & 511;
        float v = (k < 256) ? W_ih[j * WIH_LD + k] : W_hh[j * 256 + (k - 256)];
        g_Wcat_h[idx] = __float2half_rn(v);
    }
    if (idx < HSZ * HSZ) {
        g_Wh2h_h[idx] = __float2half_rn(W_h2h[idx]);
        g_Wi2h_h[idx] = __float2half_rn(W_i2h[idx]);
    }
    if (idx < NCLS * HSZ) g_Wgen_h[idx] = __float2half_rn(W_gen[idx]);
    if (idx < GDIM) g_bias2[idx] = b_ih[idx] + b_hh[idx];
    if (idx < BSZ * HSZ) g_c[idx] = 0.0f;
}

// ------------------------- fp16 MMA GEMM (proj_H / logits) ------------------
// MODE 0: plain  3: +bias[n], col BLANK_ID := -10000
template <int MODE, bool OUT_HALF, bool A_HALF, bool DUMP_A>
__global__ __launch_bounds__(256) void hgemm(
    const void* __restrict__ Aptr, const __half* __restrict__ Bw,
    void* __restrict__ Cm,
    int M, int N, int K, int lda, int ldb, int ldc,
    const float* __restrict__ bias) {

    __shared__ __half As[64 * 40];
    __shared__ __half Bs[64 * 40];

    const int m0 = blockIdx.y * 64, n0 = blockIdx.x * 64;
    const int tid = threadIdx.x, lane = tid & 31, warp = tid >> 5;
    const int wm = (warp >> 1) * 16, wn = (warp & 1) * 32;
    const int gID = lane >> 2, tig = lane & 3;
    const int lr = tid >> 2, lc = (tid & 3) * 8;

    float acc[4][4];
#pragma unroll
    for (int i = 0; i < 4; i++)
#pragma unroll
        for (int j = 0; j < 4; j++) acc[i][j] = 0.0f;

    auto loadA = [&](int k0) -> uint4 {
        if (A_HALF) {
            const __half* A = (const __half*)Aptr;
            return *(const uint4*)(A + (size_t)(m0 + lr) * lda + k0 + lc);
        } else {
            const float* A = (const float*)Aptr;
            const float* p = A + (size_t)(m0 + lr) * lda + k0 + lc;
            float4 f0 = *(const float4*)p;
            float4 f1 = *(const float4*)(p + 4);
            uint4 r;
            __half2 h;
            h = __floats2half2_rn(f0.x, f0.y); r.x = *(uint32_t*)&h;
            h = __floats2half2_rn(f0.z, f0.w); r.y = *(uint32_t*)&h;
            h = __floats2half2_rn(f1.x, f1.y); r.z = *(uint32_t*)&h;
            h = __floats2half2_rn(f1.z, f1.w); r.w = *(uint32_t*)&h;
            return r;
        }
    };
    auto loadB = [&](int k0) -> uint4 {
        if (n0 + lr < N)
            return *(const uint4*)(Bw + (size_t)(n0 + lr) * ldb + k0 + lc);
        return make_uint4(0u, 0u, 0u, 0u);
    };

    uint4 aR = loadA(0), bR = loadB(0);
    const int iters = K >> 5;

    for (int it = 0; it < iters; it++) {
        __syncthreads();
        *(uint4*)&As[lr * 40 + lc] = aR;
        *(uint4*)&Bs[lr * 40 + lc] = bR;
        if (DUMP_A && blockIdx.x == 0) {
            *(uint4*)(g_batchH_h + (size_t)(m0 + lr) * ISZ + it * 32 + lc) = aR;
        }
        __syncthreads();
        if (it + 1 < iters) {
            aR = loadA((it + 1) << 5);
            bR = loadB((it + 1) << 5);
        }
#pragma unroll
        for (int kk = 0; kk < 32; kk += 16) {
            uint32_t a0 = *(uint32_t*)&As[(wm + gID) * 40 + kk + tig * 2];
            uint32_t a1 = *(uint32_t*)&As[(wm + gID + 8) * 40 + kk + tig * 2];
            uint32_t a2 = *(uint32_t*)&As[(wm + gID) * 40 + kk + 8 + tig * 2];
            uint32_t a3 = *(uint32_t*)&As[(wm + gID + 8) * 40 + kk + 8 + tig * 2];
#pragma unroll
            for (int nt = 0; nt < 4; nt++) {
                uint32_t b0 = *(uint32_t*)&Bs[(wn + nt * 8 + gID) * 40 + kk + tig * 2];
                uint32_t b1 = *(uint32_t*)&Bs[(wn + nt * 8 + gID) * 40 + kk + 8 + tig * 2];
                asm volatile(
                    "mma.sync.aligned.m16n8k16.row.col.f32.f16.f16.f32 "
                    "{%0,%1,%2,%3}, {%4,%5,%6,%7}, {%8,%9}, {%0,%1,%2,%3};"
                    : "+f"(acc[nt][0]), "+f"(acc[nt][1]),
                      "+f"(acc[nt][2]), "+f"(acc[nt][3])
                    : "r"(a0), "r"(a1), "r"(a2), "r"(a3), "r"(b0), "r"(b1));
            }
        }
    }

    const int r0 = m0 + wm + gID, r1 = r0 + 8;
#pragma unroll
    for (int nt = 0; nt < 4; nt++) {
        int cbase = n0 + wn + nt * 8 + 2 * tig;
#pragma unroll
        for (int hr = 0; hr < 2; hr++) {
            int r = hr ? r1 : r0;
#pragma unroll
            for (int jj = 0; jj < 2; jj++) {
                int c = cbase + jj;
                if (c >= N) continue;
                float v = acc[nt][hr * 2 + jj];
                if (MODE == 3) {
                    v += bias[c];
                    if (c == BLANK_ID) v = -10000.0f;
                }
                if (OUT_HALF)
                    ((__half*)Cm)[(size_t)r * ldc + c] = __float2half_rn(v);
                else
                    ((float*)Cm)[(size_t)r * ldc + c] = v;
            }
        }
    }
}

// ------------------------- persistent 26-step kernel -------------------------
__global__ __launch_bounds__(256, 1) void persistent_steps(
    const int* __restrict__ text, const float* __restrict__ b_h2h,
    const float* __restrict__ wscore, const float* __restrict__ W_ih) {

    extern __shared__ char dyn[];
    __half* Bs = (__half*)dyn;                    // 64 x BSTR
    __half* As = Bs + 64 * BSTR;                  // 64 x BSTR
    float* fb = (float*)(dyn + 4 * 64 * BSTR);
    float (*sh_h)[HSZ] = (float(*)[HSZ])fb;       // [4][256]
    float (*sp)[HSZ]   = (float(*)[HSZ])(fb + 1024);
    float* sw          = fb + 2048;               // [256]
    float (*se)[TLEN]  = (float(*)[TLEN])(fb + 2304);  // [4][128]
    float* red         = fb + 2816;               // [4][4][64][4]

    const int tid = threadIdx.x, lane = tid & 31, warp = tid >> 5;
    const int bid = blockIdx.x;
    const int b0 = bid * RPB;                     // attention rows
    const int mt = bid >> 4, nt4 = bid & 15;      // gates tile
    const int m0 = mt * 64, n0 = nt4 * 64;
    const int wm = (warp >> 1) * 16, wn = (warp & 1) * 32;
    const int gID = lane >> 2, tig = lane & 3;

    sw[tid] = wscore[tid];

    // preload Wcat B-slab (64 rows x 512 k) once
#pragma unroll
    for (int i = 0; i < 16; i++) {
        int linear = tid + (i << 8);
        int row = linear >> 5, c8 = (linear & 31) << 4;   // 32 rows? no:
        (void)row; (void)c8;
    }
    // (proper: 64 rows x 64 uint4 per row = 4096 uint4; 16 per thread)
#pragma unroll
    for (int i = 0; i < 16; i++) {
        int linear = tid + (i << 8);
        int row = linear >> 6, c8 = (linear & 63) << 3;
        *(uint4*)&Bs[row * BSTR + c8] =
            *(const uint4*)(g_Wcat_h + ((size_t)(n0 + row)) * XDIM + c8);
    }
    __syncthreads();

    float swl[8];
#pragma unroll
    for (int p = 0; p < 8; p++) swl[p] = sw[lane * 8 + p];

    for (int s = 0; s < NSTEP; s++) {
        // ==== phase A: LSTM(s-1) -> h; projh; scores; softmax; context ====
        {
            const int r = tid >> 6, jb = tid & 63;
            const int row = b0 + r;
            if (s > 0) {
                const float* g = g_gates + (size_t)row * GDIM;
                float* cp = g_c + (size_t)row * HSZ;
#pragma unroll
                for (int jj = 0; jj < 4; jj++) {
                    int j = jb + (jj << 6);
                    float ig = fast_sigmoid(g[j]);
                    float fg = fast_sigmoid(g[j + 256]);
                    float gg = tanh_fast(g[j + 512]);
                    float og = fast_sigmoid(g[j + 768]);
                    float cn = fg * cp[j] + ig * gg;
                    float hn = og * tanh_fast(cn);
                    cp[j] = cn;
                    sh_h[r][j] = hn;
                    __half hh = __float2half_rn(hn);
                    g_X_h[(size_t)row * XDIM + 256 + j] = hh;
                    g_hs_h[((size_t)row * NSTEP + (s - 1)) * HSZ + j] = hh;
                }
            } else {
#pragma unroll
                for (int jj = 0; jj < 4; jj++) {
                    int j = jb + (jj << 6);
                    sh_h[r][j] = 0.0f;
                    g_X_h[(size_t)row * XDIM + 256 + j] = __float2half_rn(0.0f);
                }
            }
        }
        __syncthreads();

        // projh: k-split
        {
            const int q = tid >> 6, jb = tid & 63;
            const int kbase = q << 6;
            float a[4][RPB];
#pragma unroll
            for (int jj = 0; jj < 4; jj++)
#pragma unroll
                for (int r = 0; r < RPB; r++) a[jj][r] = 0.0f;

            for (int kk = 0; kk < 64; kk += 8) {
                float4 hA[RPB], hB[RPB];
#pragma unroll
                for (int r = 0; r < RPB; r++) {
                    hA[r] = *(const float4*)&sh_h[r][kbase + kk];
                    hB[r] = *(const float4*)&sh_h[r][kbase + kk + 4];
                }
#pragma unroll
                for (int jj = 0; jj < 4; jj++) {
                    int j = jb + (jj << 6);
                    uint4 wv = *(const uint4*)(g_Wh2h_h + (size_t)j * HSZ + kbase + kk);
                    const __half2* wh = (const __half2*)&wv;
                    float2 w0 = __half22float2(wh[0]);
                    float2 w1 = __half22float2(wh[1]);
                    float2 w2 = __half22float2(wh[2]);
                    float2 w3 = __half22float2(wh[3]);
#pragma unroll
                    for (int r = 0; r < RPB; r++) {
                        float t0 = fmaf(w0.x, hA[r].x, w0.y * hA[r].y);
                        float t1 = fmaf(w1.x, hA[r].z, w1.y * hA[r].w);
                        float t2 = fmaf(w2.x, hB[r].x, w2.y * hB[r].y);
                        float t3 = fmaf(w3.x, hB[r].z, w3.y * hB[r].w);
                        a[jj][r] += (t0 + t1) + (t2 + t3);
                    }
                }
            }
#pragma unroll
            for (int r = 0; r < RPB; r++) {
                float4 v = make_float4(a[0][r], a[1][r], a[2][r], a[3][r]);
                *(float4*)&red[(((q * RPB + r) * 64) + jb) * 4] = v;
            }
        }
        __syncthreads();
        {
            const int r = tid >> 6, jb = tid & 63;
            float4 v0 = *(const float4*)&red[(((0 * RPB + r) * 64) + jb) * 4];
            float4 v1 = *(const float4*)&red[(((1 * RPB + r) * 64) + jb) * 4];
            float4 v2 = *(const float4*)&red[(((2 * RPB + r) * 64) + jb) * 4];
            float4 v3 = *(const float4*)&red[(((3 * RPB + r) * 64) + jb) * 4];
            sp[r][jb]       = v0.x + v1.x + v2.x + v3.x + b_h2h[jb];
            sp[r][jb + 64]  = v0.y + v1.y + v2.y + v3.y + b_h2h[jb + 64];
            sp[r][jb + 128] = v0.z + v1.z + v2.z + v3.z + b_h2h[jb + 128];
            sp[r][jb + 192] = v0.w + v1.w + v2.w + v3.w + b_h2h[jb + 192];
        }
        __syncthreads();

        // scores: 2 warps per row, 64 t each, 4-way unroll for MLP
        {
            const int r = warp >> 1;
            const int tb = (warp & 1) << 6;
            float spl[8];
#pragma unroll
            for (int p = 0; p < 8; p++) spl[p] = sp[r][lane * 8 + p];
            const __half* pH = g_projH_h + ((size_t)(b0 + r) * TLEN + tb) * HSZ + lane * 8;
            for (int t = 0; t < 64; t += 4) {
                uint4 v[4];
#pragma unroll
                for (int u = 0; u < 4; u++) v[u] = *(const uint4*)(pH + (t + u) * HSZ);
                float ac[4];
#pragma unroll
                for (int u = 0; u < 4; u++) {
                    const __half2* hv = (const __half2*)&v[u];
                    float acc = 0.0f;
#pragma unroll
                    for (int p = 0; p < 4; p++) {
                        float2 f = __half22float2(hv[p]);
                        acc = fmaf(swl[2 * p],     tanh_fast(f.x + spl[2 * p]),     acc);
                        acc = fmaf(swl[2 * p + 1], tanh_fast(f.y + spl[2 * p + 1]), acc);
                    }
                    ac[u] = acc;
                }
#pragma unroll
                for (int u = 0; u < 4; u++) {
#pragma unroll
                    for (int o = 16; o; o >>= 1)
                        ac[u] += __shfl_xor_sync(0xffffffffu, ac[u], o);
                    if (lane == 0) se[r][tb + t + u] = ac[u];
                }
            }
        }
        __syncthreads();

        // softmax (warps 0..3, one row each)
        if (warp < RPB) {
            float v0 = se[warp][lane], v1 = se[warp][lane + 32];
            float v2 = se[warp][lane + 64], v3 = se[warp][lane + 96];
            float mx = fmaxf(fmaxf(v0, v1), fmaxf(v2, v3));
#pragma unroll
            for (int o = 16; o; o >>= 1) mx = fmaxf(mx, __shfl_xor_sync(0xffffffffu, mx, o));
            float e0 = __expf(v0 - mx), e1 = __expf(v1 - mx);
            float e2 = __expf(v2 - mx), e3 = __expf(v3 - mx);
            float sum = e0 + e1 + e2 + e3;
#pragma unroll
            for (int o = 16; o; o >>= 1) sum += __shfl_xor_sync(0xffffffffu, sum, o);
            float inv = 1.0f / sum;
            se[warp][lane] = e0 * inv;      se[warp][lane + 32] = e1 * inv;
            se[warp][lane + 64] = e2 * inv; se[warp][lane + 96] = e3 * inv;
        }
        __syncthreads();

        // context -> g_X_h[:, :256]
        {
            const int r = tid >> 6, ci = tid & 63;
            const __half2* bH = (const __half2*)(g_batchH_h + (size_t)(b0 + r) * TLEN * ISZ);
            float2 a0 = make_float2(0.f, 0.f), a1 = make_float2(0.f, 0.f);
#pragma unroll 4
            for (int t = 0; t < TLEN; t++) {
                float al = se[r][t];
                float2 x0 = __half22float2(bH[t * 128 + ci]);
                float2 x1 = __half22float2(bH[t * 128 + ci + 64]);
                a0.x = fmaf(al, x0.x, a0.x); a0.y = fmaf(al, x0.y, a0.y);
                a1.x = fmaf(al, x1.x, a1.x); a1.y = fmaf(al, x1.y, a1.y);
            }
            __half2* X2 = (__half2*)(g_X_h + (size_t)(b0 + r) * XDIM);
            X2[ci] = __floats2half2_rn(a0.x, a0.y);
            X2[ci + 64] = __floats2half2_rn(a1.x, a1.y);
        }

        grid_sync();   // X ready everywhere

        // ==== phase B: gates tile = X[m0:m0+64] @ Wcat[n0:n0+64]^T ====
        {
#pragma unroll
            for (int i = 0; i < 16; i++) {
                int linear = tid + (i << 8);
                int row = linear >> 6, c8 = (linear & 63) << 3;
                *(uint4*)&As[row * BSTR + c8] =
                    *(const uint4*)(g_X_h + ((size_t)(m0 + row)) * XDIM + c8);
            }
            __syncthreads();

            float acc[4][4];
#pragma unroll
            for (int i = 0; i < 4; i++)
#pragma unroll
                for (int j = 0; j < 4; j++) acc[i][j] = 0.0f;

#pragma unroll 4
            for (int kk = 0; kk < 512; kk += 16) {
                uint32_t a0 = *(uint32_t*)&As[(wm + gID) * BSTR + kk + tig * 2];
                uint32_t a1 = *(uint32_t*)&As[(wm + gID + 8) * BSTR + kk + tig * 2];
                uint32_t a2 = *(uint32_t*)&As[(wm + gID) * BSTR + kk + 8 + tig * 2];
                uint32_t a3 = *(uint32_t*)&As[(wm + gID + 8) * BSTR + kk + 8 + tig * 2];
#pragma unroll
                for (int nt = 0; nt < 4; nt++) {
                    uint32_t bb0 = *(uint32_t*)&Bs[(wn + nt * 8 + gID) * BSTR + kk + tig * 2];
                    uint32_t bb1 = *(uint32_t*)&Bs[(wn + nt * 8 + gID) * BSTR + kk + 8 + tig * 2];
                    asm volatile(
                        "mma.sync.aligned.m16n8k16.row.col.f32.f16.f16.f32 "
                        "{%0,%1,%2,%3}, {%4,%5,%6,%7}, {%8,%9}, {%0,%1,%2,%3};"
                        : "+f"(acc[nt][0]), "+f"(acc[nt][1]),
                          "+f"(acc[nt][2]), "+f"(acc[nt][3])
                        : "r"(a0), "r"(a1), "r"(a2), "r"(a3), "r"(bb0), "r"(bb1));
                }
            }

            const int r0 = m0 + wm + gID, r1 = r0 + 8;
            int tgt0 = text[r0 * NSTEP + s];
            int tgt1 = text[r1 * NSTEP + s];
#pragma unroll
            for (int nt = 0; nt < 4; nt++) {
                int cbase = n0 + wn + nt * 8 + 2 * tig;
#pragma unroll
                for (int hr = 0; hr < 2; hr++) {
                    int r = hr ? r1 : r0;
                    int tgt = hr ? tgt1 : tgt0;
#pragma unroll
                    for (int jj = 0; jj < 2; jj++) {
                        int c = cbase + jj;
                        float v = acc[nt][hr * 2 + jj] + g_bias2[c]
                                + W_ih[(size_t)c * WIH_LD + 256 + tgt];
                        g_gates[(size_t)r * GDIM + c] = v;
                    }
                }
            }
        }

        grid_sync();   // gates ready everywhere
    }

    // final LSTM -> hs[25]
    {
        const int r = tid >> 6, jb = tid & 63;
        const int row = b0 + r;
        const float* g = g_gates + (size_t)row * GDIM;
        const float* cp = g_c + (size_t)row * HSZ;
#pragma unroll
        for (int jj = 0; jj < 4; jj++) {
            int j = jb + (jj << 6);
            float ig = fast_sigmoid(g[j]);
            float fg = fast_sigmoid(g[j + 256]);
            float gg = tanh_fast(g[j + 512]);
            float og = fast_sigmoid(g[j + 768]);
            float cn = fg * cp[j] + ig * gg;
            float hn = og * tanh_fast(cn);
            g_hs_h[((size_t)row * NSTEP + (NSTEP - 1)) * HSZ + j] = __float2half_rn(hn);
        }
    }
}

// ------------------------- launch -------------------------------------------
extern "C" void kernel_launch(void* const* d_in, const int* in_sizes, int n_in,
                              void* d_out, int out_size) {
    const float* batch_H = (const float*)d_in[0];
    const int*   text    = (const int*)d_in[1];
    const float* W_i2h   = (const float*)d_in[3];
    const float* W_h2h   = (const float*)d_in[4];
    const float* b_h2h   = (const float*)d_in[5];
    const float* W_score = (const float*)d_in[6];
    const float* W_ih    = (const float*)d_in[7];
    const float* W_hh    = (const float*)d_in[8];
    const float* b_ih    = (const float*)d_in[9];
    const float* b_hh    = (const float*)d_in[10];
    const float* W_gen   = (const float*)d_in[11];
    const float* b_gen   = (const float*)d_in[12];
    float* out = (float*)d_out;

    __half *projH_h, *Wi2h_h, *Wgen_h, *hs_h;
    cudaGetSymbolAddress((void**)&projH_h, g_projH_h);
    cudaGetSymbolAddress((void**)&Wi2h_h,  g_Wi2h_h);
    cudaGetSymbolAddress((void**)&Wgen_h,  g_Wgen_h);
    cudaGetSymbolAddress((void**)&hs_h,    g_hs_h);

    static bool attr_set = false;
    if (!attr_set) {
        cudaFuncSetAttribute(persistent_steps,
                             cudaFuncAttributeMaxDynamicSharedMemorySize,
                             SMEM_BYTES);
        attr_set = true;
    }

    init_kernel<<<2048, 256>>>(W_ih, W_hh, b_ih, b_hh, W_i2h, W_h2h, W_gen);

    // proj_H = batch_H @ W_i2h^T -> fp16 (+ batch_H fp16 dump)
    hgemm<0, true, false, true><<<dim3(4, 1024), 256>>>(
        batch_H, Wi2h_h, projH_h, BSZ * TLEN, HSZ, ISZ, ISZ, ISZ, HSZ, nullptr);

    // entire 26-step recurrence in one persistent kernel
    persistent_steps<<<NBLK, 256, SMEM_BYTES>>>(text, b_h2h, W_score, W_ih);

    // logits = hs @ W_gen^T + b_gen, blank masked
    hgemm<3, false, true, false><<<dim3(2, (BSZ * NSTEP) / 64), 256>>>(
        hs_h, Wgen_h, out, BSZ * NSTEP, NCLS, HSZ, HSZ, HSZ, NCLS, b_gen);
}

// round 5
// speedup vs baseline: 3.2579x; 1.1325x over previous
#include <cuda_runtime.h>
#include <cuda_fp16.h>
#include <cstdint>

#define BSZ   512
#define TLEN  128
#define ISZ   256
#define HSZ   256
#define NCLS  100
#define NSTEP 26
#define XDIM  512
#define GDIM  1024
#define WIH_LD 356
#define BLANK_ID 3
#define RPB   4
#define NBLK  128
#define BSTR  520
// smem: Bs(64x520 h) + As(64x520 h) + tail
#define TAIL_BYTES (2048 + 2048 + 512 + 1024 + 2048 + 2048)   // sh, sp_h, sw_h, sb, se, seh
#define SMEM_BYTES (4 * 64 * BSTR + TAIL_BYTES)

// ------------------------- device scratch -----------------------------------
__device__ __half g_projH_h[BSZ * TLEN * HSZ];
__device__ __half g_batchH_h[BSZ * TLEN * ISZ];
__device__ __half g_X_h[BSZ * XDIM];
__device__ float  g_gates[BSZ * GDIM];
__device__ float  g_c[BSZ * HSZ];
__device__ __half g_hs_h[BSZ * NSTEP * HSZ];
__device__ __half g_Wcat_h[GDIM * XDIM];
__device__ __half g_Wh2hT_h[HSZ * HSZ];     // transposed [k][j]
__device__ __half g_Wi2h_h[HSZ * ISZ];
__device__ __half g_Wgen_h[NCLS * HSZ];
__device__ float  g_Wemb[NCLS * GDIM];      // W_ih[:,256+cls] + b_ih + b_hh
__device__ unsigned g_count;
__device__ volatile unsigned g_epoch;

// ------------------------- fast math ----------------------------------------
__device__ __forceinline__ float tanh_fast(float x) {
    float y;
    asm("tanh.approx.f32 %0, %1;" : "=f"(y) : "f"(x));
    return y;
}
__device__ __forceinline__ float fast_sigmoid(float x) {
    return 0.5f * (1.0f + tanh_fast(0.5f * x));
}
__device__ __forceinline__ __half2 tanh2(__half2 x) {
    uint32_t xi = *(uint32_t*)&x, yo;
    asm("tanh.approx.f16x2 %0, %1;" : "=r"(yo) : "r"(xi));
    return *(__half2*)&yo;
}

// ------------------------- grid barrier --------------------------------------
__device__ __forceinline__ void grid_sync() {
    __syncthreads();
    if (threadIdx.x == 0) {
        unsigned my = g_epoch;
        __threadfence();
        unsigned old = atomicAdd(&g_count, 1u);
        if (old == NBLK - 1) {
            g_count = 0;
            __threadfence();
            g_epoch = my + 1;
        } else {
            while (g_epoch == my) { __nanosleep(32); }
            __threadfence();
        }
    }
    __syncthreads();
}

// ------------------------- init ----------------------------------------------
__global__ void init_kernel(const float* __restrict__ W_ih,
                            const float* __restrict__ W_hh,
                            const float* __restrict__ b_ih,
                            const float* __restrict__ b_hh,
                            const float* __restrict__ W_i2h,
                            const float* __restrict__ W_h2h,
                            const float* __restrict__ W_gen) {
    int idx = blockIdx.x * 256 + threadIdx.x;
    if (idx < GDIM * XDIM) {
        int j = idx >> 9, k = idx & 511;
        float v = (k < 256) ? W_ih[j * WIH_LD + k] : W_hh[j * 256 + (k - 256)];
        g_Wcat_h[idx] = __float2half_rn(v);
    }
    if (idx < HSZ * HSZ) {
        int j = idx >> 8, k = idx & 255;
        g_Wh2hT_h[k * HSZ + j] = __float2half_rn(W_h2h[idx]);   // transpose
        g_Wi2h_h[idx] = __float2half_rn(W_i2h[idx]);
    }
    if (idx < NCLS * HSZ) g_Wgen_h[idx] = __float2half_rn(W_gen[idx]);
    if (idx < NCLS * GDIM) {
        int cls = idx >> 10, c = idx & 1023;
        g_Wemb[idx] = W_ih[(size_t)c * WIH_LD + 256 + cls] + b_ih[c] + b_hh[c];
    }
    if (idx < BSZ * HSZ) g_c[idx] = 0.0f;
}

// ------------------------- fp16 MMA GEMM (proj_H / logits) ------------------
template <int MODE, bool OUT_HALF, bool A_HALF, bool DUMP_A>
__global__ __launch_bounds__(256) void hgemm(
    const void* __restrict__ Aptr, const __half* __restrict__ Bw,
    void* __restrict__ Cm,
    int M, int N, int K, int lda, int ldb, int ldc,
    const float* __restrict__ bias) {

    __shared__ __half As[64 * 40];
    __shared__ __half Bs[64 * 40];

    const int m0 = blockIdx.y * 64, n0 = blockIdx.x * 64;
    const int tid = threadIdx.x, lane = tid & 31, warp = tid >> 5;
    const int wm = (warp >> 1) * 16, wn = (warp & 1) * 32;
    const int gID = lane >> 2, tig = lane & 3;
    const int lr = tid >> 2, lc = (tid & 3) * 8;

    float acc[4][4];
#pragma unroll
    for (int i = 0; i < 4; i++)
#pragma unroll
        for (int j = 0; j < 4; j++) acc[i][j] = 0.0f;

    auto loadA = [&](int k0) -> uint4 {
        if (A_HALF) {
            const __half* A = (const __half*)Aptr;
            return *(const uint4*)(A + (size_t)(m0 + lr) * lda + k0 + lc);
        } else {
            const float* A = (const float*)Aptr;
            const float* p = A + (size_t)(m0 + lr) * lda + k0 + lc;
            float4 f0 = *(const float4*)p;
            float4 f1 = *(const float4*)(p + 4);
            uint4 r;
            __half2 h;
            h = __floats2half2_rn(f0.x, f0.y); r.x = *(uint32_t*)&h;
            h = __floats2half2_rn(f0.z, f0.w); r.y = *(uint32_t*)&h;
            h = __floats2half2_rn(f1.x, f1.y); r.z = *(uint32_t*)&h;
            h = __floats2half2_rn(f1.z, f1.w); r.w = *(uint32_t*)&h;
            return r;
        }
    };
    auto loadB = [&](int k0) -> uint4 {
        if (n0 + lr < N)
            return *(const uint4*)(Bw + (size_t)(n0 + lr) * ldb + k0 + lc);
        return make_uint4(0u, 0u, 0u, 0u);
    };

    uint4 aR = loadA(0), bR = loadB(0);
    const int iters = K >> 5;

    for (int it = 0; it < iters; it++) {
        __syncthreads();
        *(uint4*)&As[lr * 40 + lc] = aR;
        *(uint4*)&Bs[lr * 40 + lc] = bR;
        if (DUMP_A && blockIdx.x == 0) {
            *(uint4*)(g_batchH_h + (size_t)(m0 + lr) * ISZ + it * 32 + lc) = aR;
        }
        __syncthreads();
        if (it + 1 < iters) {
            aR = loadA((it + 1) << 5);
            bR = loadB((it + 1) << 5);
        }
#pragma unroll
        for (int kk = 0; kk < 32; kk += 16) {
            uint32_t a0 = *(uint32_t*)&As[(wm + gID) * 40 + kk + tig * 2];
            uint32_t a1 = *(uint32_t*)&As[(wm + gID + 8) * 40 + kk + tig * 2];
            uint32_t a2 = *(uint32_t*)&As[(wm + gID) * 40 + kk + 8 + tig * 2];
            uint32_t a3 = *(uint32_t*)&As[(wm + gID + 8) * 40 + kk + 8 + tig * 2];
#pragma unroll
            for (int nt = 0; nt < 4; nt++) {
                uint32_t b0 = *(uint32_t*)&Bs[(wn + nt * 8 + gID) * 40 + kk + tig * 2];
                uint32_t b1 = *(uint32_t*)&Bs[(wn + nt * 8 + gID) * 40 + kk + 8 + tig * 2];
                asm volatile(
                    "mma.sync.aligned.m16n8k16.row.col.f32.f16.f16.f32 "
                    "{%0,%1,%2,%3}, {%4,%5,%6,%7}, {%8,%9}, {%0,%1,%2,%3};"
                    : "+f"(acc[nt][0]), "+f"(acc[nt][1]),
                      "+f"(acc[nt][2]), "+f"(acc[nt][3])
                    : "r"(a0), "r"(a1), "r"(a2), "r"(a3), "r"(b0), "r"(b1));
            }
        }
    }

    const int r0 = m0 + wm + gID, r1 = r0 + 8;
#pragma unroll
    for (int nt = 0; nt < 4; nt++) {
        int cbase = n0 + wn + nt * 8 + 2 * tig;
#pragma unroll
        for (int hr = 0; hr < 2; hr++) {
            int r = hr ? r1 : r0;
#pragma unroll
            for (int jj = 0; jj < 2; jj++) {
                int c = cbase + jj;
                if (c >= N) continue;
                float v = acc[nt][hr * 2 + jj];
                if (MODE == 3) {
                    v += bias[c];
                    if (c == BLANK_ID) v = -10000.0f;
                }
                if (OUT_HALF)
                    ((__half*)Cm)[(size_t)r * ldc + c] = __float2half_rn(v);
                else
                    ((float*)Cm)[(size_t)r * ldc + c] = v;
            }
        }
    }
}

// ------------------------- persistent 26-step kernel -------------------------
__global__ __launch_bounds__(256, 1) void persistent_steps(
    const int* __restrict__ text, const float* __restrict__ b_h2h,
    const float* __restrict__ wscore) {

    extern __shared__ char dyn[];
    __half* Bs = (__half*)dyn;                         // [64][BSTR]
    __half* As = Bs + 64 * BSTR;                       // [64][BSTR] (phase B)
    float*  red = (float*)As;                          // [8][4][256] overlay (phase A)
    char* tail = dyn + 4 * 64 * BSTR;
    __half*  sh   = (__half*)tail;                     // [4][256] h fp16
    __half*  sp_h = sh + 1024;                         // [4][256] projh fp16
    __half*  sw_h = sp_h + 1024;                       // [256] wscore fp16
    float*   sb   = (float*)(sw_h + 256);              // [256] b_h2h
    float*   se   = sb + 256;                          // [4][128] scores fp32
    __half2* seh  = (__half2*)(se + 512);              // [4][128] alpha dup

    const int tid = threadIdx.x, lane = tid & 31, warp = tid >> 5;
    const int bid = blockIdx.x;
    const int b0 = bid * RPB;
    const int m0 = (bid >> 4) * 64, n0 = (bid & 15) * 64;
    const int wm = (warp >> 1) * 16, wn = (warp & 1) * 32;
    const int gID = lane >> 2, tig = lane & 3;

    sw_h[tid] = __float2half_rn(wscore[tid]);
    sb[tid] = b_h2h[tid];

    // preload Wcat B-slab once: 64 rows x 512 halves
#pragma unroll
    for (int i = 0; i < 16; i++) {
        int linear = tid + (i << 8);
        int row = linear >> 6, c8 = (linear & 63) << 3;
        *(uint4*)&Bs[row * BSTR + c8] =
            *(const uint4*)(g_Wcat_h + ((size_t)(n0 + row)) * XDIM + c8);
    }
    __syncthreads();

    // per-lane wscore half2 slice (h = lane*8 .. +8)
    __half2 swl2[4];
    {
        uint4 v = *(const uint4*)(sw_h + lane * 8);
        swl2[0] = *(__half2*)&v.x; swl2[1] = *(__half2*)&v.y;
        swl2[2] = *(__half2*)&v.z; swl2[3] = *(__half2*)&v.w;
    }

    for (int s = 0; s < NSTEP; s++) {
        // ==== LSTM(s-1) -> h (fp16 in smem + X + hs) ====
        {
            const int r = tid >> 6, jb = tid & 63;
            const int row = b0 + r;
            if (s > 0) {
                const float* g = g_gates + (size_t)row * GDIM;
                float* cp = g_c + (size_t)row * HSZ;
#pragma unroll
                for (int jj = 0; jj < 4; jj++) {
                    int j = jb + (jj << 6);
                    float ig = fast_sigmoid(g[j]);
                    float fg = fast_sigmoid(g[j + 256]);
                    float gg = tanh_fast(g[j + 512]);
                    float og = fast_sigmoid(g[j + 768]);
                    float cn = fg * cp[j] + ig * gg;
                    float hn = og * tanh_fast(cn);
                    cp[j] = cn;
                    __half hh = __float2half_rn(hn);
                    sh[r * HSZ + j] = hh;
                    g_X_h[(size_t)row * XDIM + 256 + j] = hh;
                    g_hs_h[((size_t)row * NSTEP + (s - 1)) * HSZ + j] = hh;
                }
            } else {
                __half z = __float2half_rn(0.0f);
#pragma unroll
                for (int jj = 0; jj < 4; jj++) {
                    int j = jb + (jj << 6);
                    sh[r * HSZ + j] = z;
                    g_X_h[(size_t)row * XDIM + 256 + j] = z;
                }
            }
        }
        __syncthreads();

        // ==== projh partials: warp w covers k in [w*32, w*32+32) ====
        {
            const int kb = warp << 5;
            __half2 acc2[RPB][4];
#pragma unroll
            for (int r = 0; r < RPB; r++)
#pragma unroll
                for (int p = 0; p < 4; p++)
                    acc2[r][p] = __floats2half2_rn(0.f, 0.f);

            const __half* WT = g_Wh2hT_h + (size_t)kb * HSZ + lane * 8;
#pragma unroll 4
            for (int k = 0; k < 32; k++) {
                uint4 wv = *(const uint4*)(WT + k * HSZ);
                __half2 wh[4];
                wh[0] = *(__half2*)&wv.x; wh[1] = *(__half2*)&wv.y;
                wh[2] = *(__half2*)&wv.z; wh[3] = *(__half2*)&wv.w;
#pragma unroll
                for (int r = 0; r < RPB; r++) {
                    __half2 hk2 = __half2half2(sh[r * HSZ + kb + k]);
#pragma unroll
                    for (int p = 0; p < 4; p++)
                        acc2[r][p] = __hfma2(wh[p], hk2, acc2[r][p]);
                }
            }
            // store fp32 partials: red[warp][r][j], j = lane*8 + 2p
#pragma unroll
            for (int r = 0; r < RPB; r++) {
#pragma unroll
                for (int p = 0; p < 4; p++) {
                    float2 f = __half22float2(acc2[r][p]);
                    *(float2*)&red[((warp * RPB + r) * HSZ) + lane * 8 + 2 * p] = f;
                }
            }
        }
        __syncthreads();

        // ==== reduce partials -> sp_h (fp16) ====
        {
            const int r = tid >> 6, jb = tid & 63;   // j4 = jb*4
            float4 sum = make_float4(0.f, 0.f, 0.f, 0.f);
#pragma unroll
            for (int w = 0; w < 8; w++) {
                float4 v = *(const float4*)&red[((w * RPB + r) * HSZ) + jb * 4];
                sum.x += v.x; sum.y += v.y; sum.z += v.z; sum.w += v.w;
            }
            float4 bv = *(const float4*)&sb[jb * 4];
            __half2 h0 = __floats2half2_rn(sum.x + bv.x, sum.y + bv.y);
            __half2 h1 = __floats2half2_rn(sum.z + bv.z, sum.w + bv.w);
            uint2 pk;
            pk.x = *(uint32_t*)&h0; pk.y = *(uint32_t*)&h1;
            *(uint2*)&sp_h[r * HSZ + jb * 4] = pk;
        }
        __syncthreads();

        // ==== scores: 2 warps per row, f16x2 tanh ====
        {
            const int r = warp >> 1;
            const int tb = (warp & 1) << 6;
            __half2 spl2[4];
            {
                uint4 v = *(const uint4*)(sp_h + r * HSZ + lane * 8);
                spl2[0] = *(__half2*)&v.x; spl2[1] = *(__half2*)&v.y;
                spl2[2] = *(__half2*)&v.z; spl2[3] = *(__half2*)&v.w;
            }
            const __half* pH = g_projH_h + ((size_t)(b0 + r) * TLEN + tb) * HSZ + lane * 8;
            for (int t = 0; t < 64; t += 4) {
                uint4 v[4];
#pragma unroll
                for (int u = 0; u < 4; u++) v[u] = *(const uint4*)(pH + (t + u) * HSZ);
                float ac[4];
#pragma unroll
                for (int u = 0; u < 4; u++) {
                    __half2 hv[4];
                    hv[0] = *(__half2*)&v[u].x; hv[1] = *(__half2*)&v[u].y;
                    hv[2] = *(__half2*)&v[u].z; hv[3] = *(__half2*)&v[u].w;
                    __half2 prod = __floats2half2_rn(0.f, 0.f);
#pragma unroll
                    for (int p = 0; p < 4; p++) {
                        __half2 th = tanh2(__hadd2(hv[p], spl2[p]));
                        prod = __hfma2(swl2[p], th, prod);
                    }
                    float2 f = __half22float2(prod);
                    ac[u] = f.x + f.y;
                }
#pragma unroll
                for (int u = 0; u < 4; u++) {
#pragma unroll
                    for (int o = 16; o; o >>= 1)
                        ac[u] += __shfl_xor_sync(0xffffffffu, ac[u], o);
                    if (lane == 0) se[r * TLEN + tb + t + u] = ac[u];
                }
            }
        }
        __syncthreads();

        // ==== softmax -> seh (half2 dup alpha) ====
        if (warp < RPB) {
            const float* sr = se + warp * TLEN;
            float v0 = sr[lane], v1 = sr[lane + 32];
            float v2 = sr[lane + 64], v3 = sr[lane + 96];
            float mx = fmaxf(fmaxf(v0, v1), fmaxf(v2, v3));
#pragma unroll
            for (int o = 16; o; o >>= 1) mx = fmaxf(mx, __shfl_xor_sync(0xffffffffu, mx, o));
            float e0 = __expf(v0 - mx), e1 = __expf(v1 - mx);
            float e2 = __expf(v2 - mx), e3 = __expf(v3 - mx);
            float sum = e0 + e1 + e2 + e3;
#pragma unroll
            for (int o = 16; o; o >>= 1) sum += __shfl_xor_sync(0xffffffffu, sum, o);
            float inv = 1.0f / sum;
            __half2* dr = seh + warp * TLEN;
            dr[lane]      = __float2half2_rn(e0 * inv);
            dr[lane + 32] = __float2half2_rn(e1 * inv);
            dr[lane + 64] = __float2half2_rn(e2 * inv);
            dr[lane + 96] = __float2half2_rn(e3 * inv);
        }
        __syncthreads();

        // ==== context (half2 accumulate) -> g_X_h[:, :256] ====
        {
            const int r = tid >> 6, ci = tid & 63;
            const __half2* bH = (const __half2*)(g_batchH_h + (size_t)(b0 + r) * TLEN * ISZ);
            const __half2* al = seh + r * TLEN;
            __half2 a0 = __floats2half2_rn(0.f, 0.f);
            __half2 a1 = a0;
#pragma unroll 4
            for (int t = 0; t < TLEN; t++) {
                __half2 av = al[t];
                a0 = __hfma2(av, bH[t * 128 + ci], a0);
                a1 = __hfma2(av, bH[t * 128 + ci + 64], a1);
            }
            __half2* X2 = (__half2*)(g_X_h + (size_t)(b0 + r) * XDIM);
            X2[ci] = a0;
            X2[ci + 64] = a1;
        }

        grid_sync();   // X ready everywhere

        // ==== gates tile = X[m0:+64] @ Wcat[n0:+64]^T ====
        {
#pragma unroll
            for (int i = 0; i < 16; i++) {
                int linear = tid + (i << 8);
                int row = linear >> 6, c8 = (linear & 63) << 3;
                *(uint4*)&As[row * BSTR + c8] =
                    *(const uint4*)(g_X_h + ((size_t)(m0 + row)) * XDIM + c8);
            }
            __syncthreads();

            float acc[4][4];
#pragma unroll
            for (int i = 0; i < 4; i++)
#pragma unroll
                for (int j = 0; j < 4; j++) acc[i][j] = 0.0f;

#pragma unroll 4
            for (int kk = 0; kk < 512; kk += 16) {
                uint32_t a0 = *(uint32_t*)&As[(wm + gID) * BSTR + kk + tig * 2];
                uint32_t a1 = *(uint32_t*)&As[(wm + gID + 8) * BSTR + kk + tig * 2];
                uint32_t a2 = *(uint32_t*)&As[(wm + gID) * BSTR + kk + 8 + tig * 2];
                uint32_t a3 = *(uint32_t*)&As[(wm + gID + 8) * BSTR + kk + 8 + tig * 2];
#pragma unroll
                for (int nt = 0; nt < 4; nt++) {
                    uint32_t bb0 = *(uint32_t*)&Bs[(wn + nt * 8 + gID) * BSTR + kk + tig * 2];
                    uint32_t bb1 = *(uint32_t*)&Bs[(wn + nt * 8 + gID) * BSTR + kk + 8 + tig * 2];
                    asm volatile(
                        "mma.sync.aligned.m16n8k16.row.col.f32.f16.f16.f32 "
                        "{%0,%1,%2,%3}, {%4,%5,%6,%7}, {%8,%9}, {%0,%1,%2,%3};"
                        : "+f"(acc[nt][0]), "+f"(acc[nt][1]),
                          "+f"(acc[nt][2]), "+f"(acc[nt][3])
                        : "r"(a0), "r"(a1), "r"(a2), "r"(a3), "r"(bb0), "r"(bb1));
                }
            }

            const int r0 = m0 + wm + gID, r1 = r0 + 8;
            int tgt0 = text[r0 * NSTEP + s];
            int tgt1 = text[r1 * NSTEP + s];
            const float* e0 = g_Wemb + (size_t)tgt0 * GDIM;
            const float* e1 = g_Wemb + (size_t)tgt1 * GDIM;
#pragma unroll
            for (int nt = 0; nt < 4; nt++) {
                int cbase = n0 + wn + nt * 8 + 2 * tig;
                float2 w0 = *(const float2*)(e0 + cbase);
                float2 w1 = *(const float2*)(e1 + cbase);
                float2 o0 = make_float2(acc[nt][0] + w0.x, acc[nt][1] + w0.y);
                float2 o1 = make_float2(acc[nt][2] + w1.x, acc[nt][3] + w1.y);
                *(float2*)&g_gates[(size_t)r0 * GDIM + cbase] = o0;
                *(float2*)&g_gates[(size_t)r1 * GDIM + cbase] = o1;
            }
        }

        grid_sync();   // gates ready everywhere
    }

    // final LSTM -> hs[25]
    {
        const int r = tid >> 6, jb = tid & 63;
        const int row = b0 + r;
        const float* g = g_gates + (size_t)row * GDIM;
        const float* cp = g_c + (size_t)row * HSZ;
#pragma unroll
        for (int jj = 0; jj < 4; jj++) {
            int j = jb + (jj << 6);
            float ig = fast_sigmoid(g[j]);
            float fg = fast_sigmoid(g[j + 256]);
            float gg = tanh_fast(g[j + 512]);
            float og = fast_sigmoid(g[j + 768]);
            float cn = fg * cp[j] + ig * gg;
            float hn = og * tanh_fast(cn);
            g_hs_h[((size_t)row * NSTEP + (NSTEP - 1)) * HSZ + j] = __float2half_rn(hn);
        }
    }
}

// ------------------------- launch -------------------------------------------
extern "C" void kernel_launch(void* const* d_in, const int* in_sizes, int n_in,
                              void* d_out, int out_size) {
    const float* batch_H = (const float*)d_in[0];
    const int*   text    = (const int*)d_in[1];
    const float* W_i2h   = (const float*)d_in[3];
    const float* W_h2h   = (const float*)d_in[4];
    const float* b_h2h   = (const float*)d_in[5];
    const float* W_score = (const float*)d_in[6];
    const float* W_ih    = (const float*)d_in[7];
    const float* W_hh    = (const float*)d_in[8];
    const float* b_ih    = (const float*)d_in[9];
    const float* b_hh    = (const float*)d_in[10];
    const float* W_gen   = (const float*)d_in[11];
    const float* b_gen   = (const float*)d_in[12];
    float* out = (float*)d_out;

    __half *projH_h, *Wi2h_h, *Wgen_h, *hs_h;
    cudaGetSymbolAddress((void**)&projH_h, g_projH_h);
    cudaGetSymbolAddress((void**)&Wi2h_h,  g_Wi2h_h);
    cudaGetSymbolAddress((void**)&Wgen_h,  g_Wgen_h);
    cudaGetSymbolAddress((void**)&hs_h,    g_hs_h);

    static bool attr_set = false;
    if (!attr_set) {
        cudaFuncSetAttribute(persistent_steps,
                             cudaFuncAttributeMaxDynamicSharedMemorySize,
                             SMEM_BYTES);
        attr_set = true;
    }

    init_kernel<<<2048, 256>>>(W_ih, W_hh, b_ih, b_hh, W_i2h, W_h2h, W_gen);

    hgemm<0, true, false, true><<<dim3(4, 1024), 256>>>(
        batch_H, Wi2h_h, projH_h, BSZ * TLEN, HSZ, ISZ, ISZ, ISZ, HSZ, nullptr);

    persistent_steps<<<NBLK, 256, SMEM_BYTES>>>(text, b_h2h, W_score);

    hgemm<3, false, true, false><<<dim3(2, (BSZ * NSTEP) / 64), 256>>>(
        hs_h, Wgen_h, out, BSZ * NSTEP, NCLS, HSZ, HSZ, HSZ, NCLS, b_gen);
}

// round 6
// speedup vs baseline: 3.2972x; 1.0121x over previous
#include <cuda_runtime.h>
#include <cuda_fp16.h>
#include <cstdint>

#define BSZ   512
#define TLEN  128
#define ISZ   256
#define HSZ   256
#define NCLS  100
#define NSTEP 26
#define XDIM  512
#define GDIM  1024
#define WIH_LD 356
#define BLANK_ID 3
#define RPB   4
#define NBLK  128
#define GRPBLK 32          // blocks per batch group
#define BSTR  520
#define TAIL_BYTES (2048 + 2048 + 512 + 1024 + 2048 + 2048)
#define SMEM_BYTES (4 * 64 * BSTR + TAIL_BYTES)

// ------------------------- device scratch -----------------------------------
__device__ __half g_projH_h[BSZ * TLEN * HSZ];
__device__ __half g_batchH_h[BSZ * TLEN * ISZ];
__device__ __half g_X_h[BSZ * XDIM];
__device__ float  g_gates[BSZ * GDIM];
__device__ float  g_c[BSZ * HSZ];
__device__ __half g_hs_h[BSZ * NSTEP * HSZ];
__device__ __half g_Wcat_h[GDIM * XDIM];
__device__ __half g_Wh2hT_h[HSZ * HSZ];
__device__ __half g_Wi2h_h[HSZ * ISZ];
__device__ __half g_Wgen_h[NCLS * HSZ];
__device__ float  g_Wemb[NCLS * GDIM];
// per-group barrier state (stride 32 uints = 128B; epoch monotonic -> replay-safe)
__device__ unsigned g_count[4 * 32];
__device__ volatile unsigned g_epoch[4 * 32];

// ------------------------- fast math ----------------------------------------
__device__ __forceinline__ float tanh_fast(float x) {
    float y;
    asm("tanh.approx.f32 %0, %1;" : "=f"(y) : "f"(x));
    return y;
}
__device__ __forceinline__ float fast_sigmoid(float x) {
    return 0.5f * (1.0f + tanh_fast(0.5f * x));
}
__device__ __forceinline__ __half2 tanh2(__half2 x) {
    uint32_t xi = *(uint32_t*)&x, yo;
    asm("tanh.approx.f16x2 %0, %1;" : "=r"(yo) : "r"(xi));
    return *(__half2*)&yo;
}

// ------------------------- group barrier (32 blocks) -------------------------
__device__ __forceinline__ void group_sync(int g) {
    __syncthreads();
    if (threadIdx.x == 0) {
        const int slot = g * 32;
        unsigned my = g_epoch[slot];
        __threadfence();
        unsigned old = atomicAdd(&g_count[slot], 1u);
        if (old == GRPBLK - 1) {
            g_count[slot] = 0;
            __threadfence();
            g_epoch[slot] = my + 1;
        } else {
            while (g_epoch[slot] == my) { __nanosleep(32); }
            __threadfence();
        }
    }
    __syncthreads();
}

// ------------------------- init ----------------------------------------------
__global__ void init_kernel(const float* __restrict__ W_ih,
                            const float* __restrict__ W_hh,
                            const float* __restrict__ b_ih,
                            const float* __restrict__ b_hh,
                            const float* __restrict__ W_i2h,
                            const float* __restrict__ W_h2h,
                            const float* __restrict__ W_gen) {
    int idx = blockIdx.x * 256 + threadIdx.x;
    if (idx < GDIM * XDIM) {
        int j = idx >> 9, k = idx & 511;
        float v = (k < 256) ? W_ih[j * WIH_LD + k] : W_hh[j * 256 + (k - 256)];
        g_Wcat_h[idx] = __float2half_rn(v);
    }
    if (idx < HSZ * HSZ) {
        int j = idx >> 8, k = idx & 255;
        g_Wh2hT_h[k * HSZ + j] = __float2half_rn(W_h2h[idx]);
        g_Wi2h_h[idx] = __float2half_rn(W_i2h[idx]);
    }
    if (idx < NCLS * HSZ) g_Wgen_h[idx] = __float2half_rn(W_gen[idx]);
    if (idx < NCLS * GDIM) {
        int cls = idx >> 10, c = idx & 1023;
        g_Wemb[idx] = W_ih[(size_t)c * WIH_LD + 256 + cls] + b_ih[c] + b_hh[c];
    }
    if (idx < BSZ * HSZ) g_c[idx] = 0.0f;
}

// ------------------------- fp16 MMA GEMM, tile 128x64  C = A*B^T ------------
// 256 threads, 8 warps (4M x 2N), warp tile 32x32 (2 m-frags), mma m16n8k16.
// MODE 0: plain  3: +bias[n], col BLANK_ID := -10000
template <int MODE, bool OUT_HALF, bool A_HALF, bool DUMP_A>
__global__ __launch_bounds__(256) void hgemm2(
    const void* __restrict__ Aptr, const __half* __restrict__ Bw,
    void* __restrict__ Cm,
    int M, int N, int K, int lda, int ldb, int ldc,
    const float* __restrict__ bias) {

    __shared__ __half As[128 * 40];
    __shared__ __half Bs[64 * 40];

    const int m0 = blockIdx.y * 128, n0 = blockIdx.x * 64;
    const int tid = threadIdx.x, lane = tid & 31, warp = tid >> 5;
    const int wm = (warp >> 1) * 32, wn = (warp & 1) * 32;
    const int gID = lane >> 2, tig = lane & 3;
    const int ar = tid >> 1, aseg = (tid & 1) << 4;   // A: 2 thr/row, 16 halves each
    const int br = tid >> 2, bseg = (tid & 3) << 3;   // B: 4 thr/row, 8 halves each

    float acc[2][4][4];
#pragma unroll
    for (int mf = 0; mf < 2; mf++)
#pragma unroll
        for (int i = 0; i < 4; i++)
#pragma unroll
            for (int j = 0; j < 4; j++) acc[mf][i][j] = 0.0f;

    auto loadA = [&](int k0, uint4& o0, uint4& o1) {
        if (A_HALF) {
            const __half* A = (const __half*)Aptr;
            const __half* p = A + (size_t)(m0 + ar) * lda + k0 + aseg;
            o0 = *(const uint4*)p;
            o1 = *(const uint4*)(p + 8);
        } else {
            const float* A = (const float*)Aptr;
            const float* p = A + (size_t)(m0 + ar) * lda + k0 + aseg;
            float4 f0 = *(const float4*)p;
            float4 f1 = *(const float4*)(p + 4);
            float4 f2 = *(const float4*)(p + 8);
            float4 f3 = *(const float4*)(p + 12);
            __half2 h;
            h = __floats2half2_rn(f0.x, f0.y); o0.x = *(uint32_t*)&h;
            h = __floats2half2_rn(f0.z, f0.w); o0.y = *(uint32_t*)&h;
            h = __floats2half2_rn(f1.x, f1.y); o0.z = *(uint32_t*)&h;
            h = __floats2half2_rn(f1.z, f1.w); o0.w = *(uint32_t*)&h;
            h = __floats2half2_rn(f2.x, f2.y); o1.x = *(uint32_t*)&h;
            h = __floats2half2_rn(f2.z, f2.w); o1.y = *(uint32_t*)&h;
            h = __floats2half2_rn(f3.x, f3.y); o1.z = *(uint32_t*)&h;
            h = __floats2half2_rn(f3.z, f3.w); o1.w = *(uint32_t*)&h;
        }
    };
    auto loadB = [&](int k0) -> uint4 {
        if (n0 + br < N)
            return *(const uint4*)(Bw + (size_t)(n0 + br) * ldb + k0 + bseg);
        return make_uint4(0u, 0u, 0u, 0u);
    };

    uint4 a0R, a1R, bR;
    loadA(0, a0R, a1R);
    bR = loadB(0);
    const int iters = K >> 5;

    for (int it = 0; it < iters; it++) {
        __syncthreads();
        *(uint4*)&As[ar * 40 + aseg] = a0R;
        *(uint4*)&As[ar * 40 + aseg + 8] = a1R;
        if (br < 64) *(uint4*)&Bs[br * 40 + bseg] = bR;
        if (DUMP_A && blockIdx.x == 0) {
            __half* d = g_batchH_h + (size_t)(m0 + ar) * ISZ + it * 32 + aseg;
            *(uint4*)d = a0R;
            *(uint4*)(d + 8) = a1R;
        }
        __syncthreads();
        if (it + 1 < iters) {
            loadA((it + 1) << 5, a0R, a1R);
            bR = loadB((it + 1) << 5);
        }
#pragma unroll
        for (int kk = 0; kk < 32; kk += 16) {
            uint32_t af[2][4];
#pragma unroll
            for (int mf = 0; mf < 2; mf++) {
                int rb = wm + mf * 16 + gID;
                af[mf][0] = *(uint32_t*)&As[rb * 40 + kk + tig * 2];
                af[mf][1] = *(uint32_t*)&As[(rb + 8) * 40 + kk + tig * 2];
                af[mf][2] = *(uint32_t*)&As[rb * 40 + kk + 8 + tig * 2];
                af[mf][3] = *(uint32_t*)&As[(rb + 8) * 40 + kk + 8 + tig * 2];
            }
#pragma unroll
            for (int nt = 0; nt < 4; nt++) {
                uint32_t b0 = *(uint32_t*)&Bs[(wn + nt * 8 + gID) * 40 + kk + tig * 2];
                uint32_t b1 = *(uint32_t*)&Bs[(wn + nt * 8 + gID) * 40 + kk + 8 + tig * 2];
#pragma unroll
                for (int mf = 0; mf < 2; mf++) {
                    asm volatile(
                        "mma.sync.aligned.m16n8k16.row.col.f32.f16.f16.f32 "
                        "{%0,%1,%2,%3}, {%4,%5,%6,%7}, {%8,%9}, {%0,%1,%2,%3};"
                        : "+f"(acc[mf][nt][0]), "+f"(acc[mf][nt][1]),
                          "+f"(acc[mf][nt][2]), "+f"(acc[mf][nt][3])
                        : "r"(af[mf][0]), "r"(af[mf][1]), "r"(af[mf][2]),
                          "r"(af[mf][3]), "r"(b0), "r"(b1));
                }
            }
        }
    }

#pragma unroll
    for (int mf = 0; mf < 2; mf++) {
        const int r0 = m0 + wm + mf * 16 + gID, r1 = r0 + 8;
#pragma unroll
        for (int nt = 0; nt < 4; nt++) {
            int cbase = n0 + wn + nt * 8 + 2 * tig;
#pragma unroll
            for (int hr = 0; hr < 2; hr++) {
                int r = hr ? r1 : r0;
                if (r >= M) continue;
#pragma unroll
                for (int jj = 0; jj < 2; jj++) {
                    int c = cbase + jj;
                    if (c >= N) continue;
                    float v = acc[mf][nt][hr * 2 + jj];
                    if (MODE == 3) {
                        v += bias[c];
                        if (c == BLANK_ID) v = -10000.0f;
                    }
                    if (OUT_HALF)
                        ((__half*)Cm)[(size_t)r * ldc + c] = __float2half_rn(v);
                    else
                        ((float*)Cm)[(size_t)r * ldc + c] = v;
                }
            }
        }
    }
}

// ------------------------- persistent 26-step kernel -------------------------
__global__ __launch_bounds__(256, 1) void persistent_steps(
    const int* __restrict__ text, const float* __restrict__ b_h2h,
    const float* __restrict__ wscore) {

    extern __shared__ char dyn[];
    __half* Bs = (__half*)dyn;                         // [64][BSTR]
    __half* As = Bs + 64 * BSTR;                       // [64][BSTR] (phase B)
    float*  red = (float*)As;                          // [8][4][256] overlay (phase A)
    char* tail = dyn + 4 * 64 * BSTR;
    __half*  sh   = (__half*)tail;                     // [4][256]
    __half*  sp_h = sh + 1024;                         // [4][256]
    __half*  sw_h = sp_h + 1024;                       // [256]
    float*   sb   = (float*)(sw_h + 256);              // [256]
    float*   se   = sb + 256;                          // [4][128]
    __half2* seh  = (__half2*)(se + 512);              // [4][128]

    const int tid = threadIdx.x, lane = tid & 31, warp = tid >> 5;
    const int bid = blockIdx.x;
    const int grp = bid >> 5;            // batch group (4 groups x 32 blocks)
    const int lid = bid & 31;
    const int b0 = bid * RPB;            // attention rows (within group's 128)
    const int m0 = grp * 128 + (lid >> 4) * 64;   // gates m-tile (within group)
    const int n0 = (lid & 15) * 64;
    const int wm = (warp >> 1) * 16, wn = (warp & 1) * 32;
    const int gID = lane >> 2, tig = lane & 3;

    sw_h[tid] = __float2half_rn(wscore[tid]);
    sb[tid] = b_h2h[tid];

    // preload Wcat B-slab once
#pragma unroll
    for (int i = 0; i < 16; i++) {
        int linear = tid + (i << 8);
        int row = linear >> 6, c8 = (linear & 63) << 3;
        *(uint4*)&Bs[row * BSTR + c8] =
            *(const uint4*)(g_Wcat_h + ((size_t)(n0 + row)) * XDIM + c8);
    }
    __syncthreads();

    __half2 swl2[4];
    {
        uint4 v = *(const uint4*)(sw_h + lane * 8);
        swl2[0] = *(__half2*)&v.x; swl2[1] = *(__half2*)&v.y;
        swl2[2] = *(__half2*)&v.z; swl2[3] = *(__half2*)&v.w;
    }

    for (int s = 0; s < NSTEP; s++) {
        // ==== LSTM(s-1) -> h ====
        {
            const int r = tid >> 6, jb = tid & 63;
            const int row = b0 + r;
            if (s > 0) {
                const float* g = g_gates + (size_t)row * GDIM;
                float* cp = g_c + (size_t)row * HSZ;
#pragma unroll
                for (int jj = 0; jj < 4; jj++) {
                    int j = jb + (jj << 6);
                    float ig = fast_sigmoid(g[j]);
                    float fg = fast_sigmoid(g[j + 256]);
                    float gg = tanh_fast(g[j + 512]);
                    float og = fast_sigmoid(g[j + 768]);
                    float cn = fg * cp[j] + ig * gg;
                    float hn = og * tanh_fast(cn);
                    cp[j] = cn;
                    __half hh = __float2half_rn(hn);
                    sh[r * HSZ + j] = hh;
                    g_X_h[(size_t)row * XDIM + 256 + j] = hh;
                    g_hs_h[((size_t)row * NSTEP + (s - 1)) * HSZ + j] = hh;
                }
            } else {
                __half z = __float2half_rn(0.0f);
#pragma unroll
                for (int jj = 0; jj < 4; jj++) {
                    int j = jb + (jj << 6);
                    sh[r * HSZ + j] = z;
                    g_X_h[(size_t)row * XDIM + 256 + j] = z;
                }
            }
        }
        __syncthreads();

        // ==== projh partials: warp w covers k in [w*32, +32) ====
        {
            const int kb = warp << 5;
            __half2 acc2[RPB][4];
#pragma unroll
            for (int r = 0; r < RPB; r++)
#pragma unroll
                for (int p = 0; p < 4; p++)
                    acc2[r][p] = __floats2half2_rn(0.f, 0.f);

            const __half* WT = g_Wh2hT_h + (size_t)kb * HSZ + lane * 8;
#pragma unroll 4
            for (int k = 0; k < 32; k++) {
                uint4 wv = *(const uint4*)(WT + k * HSZ);
                __half2 wh[4];
                wh[0] = *(__half2*)&wv.x; wh[1] = *(__half2*)&wv.y;
                wh[2] = *(__half2*)&wv.z; wh[3] = *(__half2*)&wv.w;
#pragma unroll
                for (int r = 0; r < RPB; r++) {
                    __half2 hk2 = __half2half2(sh[r * HSZ + kb + k]);
#pragma unroll
                    for (int p = 0; p < 4; p++)
                        acc2[r][p] = __hfma2(wh[p], hk2, acc2[r][p]);
                }
            }
#pragma unroll
            for (int r = 0; r < RPB; r++) {
#pragma unroll
                for (int p = 0; p < 4; p++) {
                    float2 f = __half22float2(acc2[r][p]);
                    *(float2*)&red[((warp * RPB + r) * HSZ) + lane * 8 + 2 * p] = f;
                }
            }
        }
        __syncthreads();

        // ==== reduce -> sp_h ====
        {
            const int r = tid >> 6, jb = tid & 63;
            float4 sum = make_float4(0.f, 0.f, 0.f, 0.f);
#pragma unroll
            for (int w = 0; w < 8; w++) {
                float4 v = *(const float4*)&red[((w * RPB + r) * HSZ) + jb * 4];
                sum.x += v.x; sum.y += v.y; sum.z += v.z; sum.w += v.w;
            }
            float4 bv = *(const float4*)&sb[jb * 4];
            __half2 h0 = __floats2half2_rn(sum.x + bv.x, sum.y + bv.y);
            __half2 h1 = __floats2half2_rn(sum.z + bv.z, sum.w + bv.w);
            uint2 pk;
            pk.x = *(uint32_t*)&h0; pk.y = *(uint32_t*)&h1;
            *(uint2*)&sp_h[r * HSZ + jb * 4] = pk;
        }
        __syncthreads();

        // ==== scores ====
        {
            const int r = warp >> 1;
            const int tb = (warp & 1) << 6;
            __half2 spl2[4];
            {
                uint4 v = *(const uint4*)(sp_h + r * HSZ + lane * 8);
                spl2[0] = *(__half2*)&v.x; spl2[1] = *(__half2*)&v.y;
                spl2[2] = *(__half2*)&v.z; spl2[3] = *(__half2*)&v.w;
            }
            const __half* pH = g_projH_h + ((size_t)(b0 + r) * TLEN + tb) * HSZ + lane * 8;
            for (int t = 0; t < 64; t += 4) {
                uint4 v[4];
#pragma unroll
                for (int u = 0; u < 4; u++) v[u] = *(const uint4*)(pH + (t + u) * HSZ);
                float ac[4];
#pragma unroll
                for (int u = 0; u < 4; u++) {
                    __half2 hv[4];
                    hv[0] = *(__half2*)&v[u].x; hv[1] = *(__half2*)&v[u].y;
                    hv[2] = *(__half2*)&v[u].z; hv[3] = *(__half2*)&v[u].w;
                    __half2 prod = __floats2half2_rn(0.f, 0.f);
#pragma unroll
                    for (int p = 0; p < 4; p++) {
                        __half2 th = tanh2(__hadd2(hv[p], spl2[p]));
                        prod = __hfma2(swl2[p], th, prod);
                    }
                    float2 f = __half22float2(prod);
                    ac[u] = f.x + f.y;
                }
#pragma unroll
                for (int u = 0; u < 4; u++) {
#pragma unroll
                    for (int o = 16; o; o >>= 1)
                        ac[u] += __shfl_xor_sync(0xffffffffu, ac[u], o);
                    if (lane == 0) se[r * TLEN + tb + t + u] = ac[u];
                }
            }
        }
        __syncthreads();

        // ==== softmax -> seh ====
        if (warp < RPB) {
            const float* sr = se + warp * TLEN;
            float v0 = sr[lane], v1 = sr[lane + 32];
            float v2 = sr[lane + 64], v3 = sr[lane + 96];
            float mx = fmaxf(fmaxf(v0, v1), fmaxf(v2, v3));
#pragma unroll
            for (int o = 16; o; o >>= 1) mx = fmaxf(mx, __shfl_xor_sync(0xffffffffu, mx, o));
            float e0 = __expf(v0 - mx), e1 = __expf(v1 - mx);
            float e2 = __expf(v2 - mx), e3 = __expf(v3 - mx);
            float sum = e0 + e1 + e2 + e3;
#pragma unroll
            for (int o = 16; o; o >>= 1) sum += __shfl_xor_sync(0xffffffffu, sum, o);
            float inv = 1.0f / sum;
            __half2* dr = seh + warp * TLEN;
            dr[lane]      = __float2half2_rn(e0 * inv);
            dr[lane + 32] = __float2half2_rn(e1 * inv);
            dr[lane + 64] = __float2half2_rn(e2 * inv);
            dr[lane + 96] = __float2half2_rn(e3 * inv);
        }
        __syncthreads();

        // ==== context -> g_X_h[:, :256] ====
        {
            const int r = tid >> 6, ci = tid & 63;
            const __half2* bH = (const __half2*)(g_batchH_h + (size_t)(b0 + r) * TLEN * ISZ);
            const __half2* al = seh + r * TLEN;
            __half2 a0 = __floats2half2_rn(0.f, 0.f);
            __half2 a1 = a0;
#pragma unroll 4
            for (int t = 0; t < TLEN; t++) {
                __half2 av = al[t];
                a0 = __hfma2(av, bH[t * 128 + ci], a0);
                a1 = __hfma2(av, bH[t * 128 + ci + 64], a1);
            }
            __half2* X2 = (__half2*)(g_X_h + (size_t)(b0 + r) * XDIM);
            X2[ci] = a0;
            X2[ci + 64] = a1;
        }

        group_sync(grp);   // X ready within group

        // ==== gates tile = X[m0:+64] @ Wcat[n0:+64]^T ====
        {
#pragma unroll
            for (int i = 0; i < 16; i++) {
                int linear = tid + (i << 8);
                int row = linear >> 6, c8 = (linear & 63) << 3;
                *(uint4*)&As[row * BSTR + c8] =
                    *(const uint4*)(g_X_h + ((size_t)(m0 + row)) * XDIM + c8);
            }
            __syncthreads();

            float acc[4][4];
#pragma unroll
            for (int i = 0; i < 4; i++)
#pragma unroll
                for (int j = 0; j < 4; j++) acc[i][j] = 0.0f;

#pragma unroll 4
            for (int kk = 0; kk < 512; kk += 16) {
                uint32_t a0 = *(uint32_t*)&As[(wm + gID) * BSTR + kk + tig * 2];
                uint32_t a1 = *(uint32_t*)&As[(wm + gID + 8) * BSTR + kk + tig * 2];
                uint32_t a2 = *(uint32_t*)&As[(wm + gID) * BSTR + kk + 8 + tig * 2];
                uint32_t a3 = *(uint32_t*)&As[(wm + gID + 8) * BSTR + kk + 8 + tig * 2];
#pragma unroll
                for (int nt = 0; nt < 4; nt++) {
                    uint32_t bb0 = *(uint32_t*)&Bs[(wn + nt * 8 + gID) * BSTR + kk + tig * 2];
                    uint32_t bb1 = *(uint32_t*)&Bs[(wn + nt * 8 + gID) * BSTR + kk + 8 + tig * 2];
                    asm volatile(
                        "mma.sync.aligned.m16n8k16.row.col.f32.f16.f16.f32 "
                        "{%0,%1,%2,%3}, {%4,%5,%6,%7}, {%8,%9}, {%0,%1,%2,%3};"
                        : "+f"(acc[nt][0]), "+f"(acc[nt][1]),
                          "+f"(acc[nt][2]), "+f"(acc[nt][3])
                        : "r"(a0), "r"(a1), "r"(a2), "r"(a3), "r"(bb0), "r"(bb1));
                }
            }

            const int r0 = m0 + wm + gID, r1 = r0 + 8;
            int tgt0 = text[r0 * NSTEP + s];
            int tgt1 = text[r1 * NSTEP + s];
            const float* e0 = g_Wemb + (size_t)tgt0 * GDIM;
            const float* e1 = g_Wemb + (size_t)tgt1 * GDIM;
#pragma unroll
            for (int nt = 0; nt < 4; nt++) {
                int cbase = n0 + wn + nt * 8 + 2 * tig;
                float2 w0 = *(const float2*)(e0 + cbase);
                float2 w1 = *(const float2*)(e1 + cbase);
                float2 o0 = make_float2(acc[nt][0] + w0.x, acc[nt][1] + w0.y);
                float2 o1 = make_float2(acc[nt][2] + w1.x, acc[nt][3] + w1.y);
                *(float2*)&g_gates[(size_t)r0 * GDIM + cbase] = o0;
                *(float2*)&g_gates[(size_t)r1 * GDIM + cbase] = o1;
            }
        }

        group_sync(grp);   // gates ready within group
    }

    // final LSTM -> hs[25]
    {
        const int r = tid >> 6, jb = tid & 63;
        const int row = b0 + r;
        const float* g = g_gates + (size_t)row * GDIM;
        const float* cp = g_c + (size_t)row * HSZ;
#pragma unroll
        for (int jj = 0; jj < 4; jj++) {
            int j = jb + (jj << 6);
            float ig = fast_sigmoid(g[j]);
            float fg = fast_sigmoid(g[j + 256]);
            float gg = tanh_fast(g[j + 512]);
            float og = fast_sigmoid(g[j + 768]);
            float cn = fg * cp[j] + ig * gg;
            float hn = og * tanh_fast(cn);
            g_hs_h[((size_t)row * NSTEP + (NSTEP - 1)) * HSZ + j] = __float2half_rn(hn);
        }
    }
}

// ------------------------- launch -------------------------------------------
extern "C" void kernel_launch(void* const* d_in, const int* in_sizes, int n_in,
                              void* d_out, int out_size) {
    const float* batch_H = (const float*)d_in[0];
    const int*   text    = (const int*)d_in[1];
    const float* W_i2h   = (const float*)d_in[3];
    const float* W_h2h   = (const float*)d_in[4];
    const float* b_h2h   = (const float*)d_in[5];
    const float* W_score = (const float*)d_in[6];
    const float* W_ih    = (const float*)d_in[7];
    const float* W_hh    = (const float*)d_in[8];
    const float* b_ih    = (const float*)d_in[9];
    const float* b_hh    = (const float*)d_in[10];
    const float* W_gen   = (const float*)d_in[11];
    const float* b_gen   = (const float*)d_in[12];
    float* out = (float*)d_out;

    __half *projH_h, *Wi2h_h, *Wgen_h, *hs_h;
    cudaGetSymbolAddress((void**)&projH_h, g_projH_h);
    cudaGetSymbolAddress((void**)&Wi2h_h,  g_Wi2h_h);
    cudaGetSymbolAddress((void**)&Wgen_h,  g_Wgen_h);
    cudaGetSymbolAddress((void**)&hs_h,    g_hs_h);

    static bool attr_set = false;
    if (!attr_set) {
        cudaFuncSetAttribute(persistent_steps,
                             cudaFuncAttributeMaxDynamicSharedMemorySize,
                             SMEM_BYTES);
        attr_set = true;
    }

    init_kernel<<<2048, 256>>>(W_ih, W_hh, b_ih, b_hh, W_i2h, W_h2h, W_gen);

    // proj_H = batch_H @ W_i2h^T -> fp16 (+ batch_H fp16 dump), 128x64 tiles
    hgemm2<0, true, false, true><<<dim3(4, 512), 256>>>(
        batch_H, Wi2h_h, projH_h, BSZ * TLEN, HSZ, ISZ, ISZ, ISZ, HSZ, nullptr);

    persistent_steps<<<NBLK, 256, SMEM_BYTES>>>(text, b_h2h, W_score);

    // logits = hs @ W_gen^T + b_gen, blank masked; M=13312 = 104*128
    hgemm2<3, false, true, false><<<dim3(2, 104), 256>>>(
        hs_h, Wgen_h, out, BSZ * NSTEP, NCLS, HSZ, HSZ, HSZ, NCLS, b_gen);
}

// round 7
// speedup vs baseline: 4.0730x; 1.2353x over previous
#include <cuda_runtime.h>
#include <cuda_fp16.h>
#include <cstdint>

#define BSZ   512
#define TLEN  128
#define ISZ   256
#define HSZ   256
#define NCLS  100
#define NSTEP 26
#define XDIM  512
#define GDIM  1024
#define WIH_LD 356
#define BLANK_ID 3
#define RPB   4
#define NBLK  128
#define GRPBLK 32
#define NTHR  512
#define BSTR  520
#define TAIL_BYTES (2048 + 2048 + 512 + 1024 + 2048 + 2048)
#define SMEM_BYTES (4 * 64 * BSTR + TAIL_BYTES)

// ------------------------- device scratch -----------------------------------
__device__ __half g_projH_h[BSZ * TLEN * HSZ];
__device__ __half g_batchH_h[BSZ * TLEN * ISZ];
__device__ __half g_X_h[BSZ * XDIM];
__device__ float  g_gates[BSZ * GDIM];
__device__ float  g_c[BSZ * HSZ];
__device__ __half g_hs_h[BSZ * NSTEP * HSZ];
__device__ __half g_Wcat_h[GDIM * XDIM];
__device__ __half g_Wh2hT_h[HSZ * HSZ];
__device__ __half g_Wi2h_h[HSZ * ISZ];
__device__ __half g_Wgen_h[NCLS * HSZ];
__device__ float  g_Wemb[NCLS * GDIM];
__device__ unsigned g_count[4 * 32];
__device__ volatile unsigned g_epoch[4 * 32];

// ------------------------- fast math ----------------------------------------
__device__ __forceinline__ float tanh_fast(float x) {
    float y;
    asm("tanh.approx.f32 %0, %1;" : "=f"(y) : "f"(x));
    return y;
}
__device__ __forceinline__ float fast_sigmoid(float x) {
    return 0.5f * (1.0f + tanh_fast(0.5f * x));
}
__device__ __forceinline__ __half2 tanh2(__half2 x) {
    uint32_t xi = *(uint32_t*)&x, yo;
    asm("tanh.approx.f16x2 %0, %1;" : "=r"(yo) : "r"(xi));
    return *(__half2*)&yo;
}

// ------------------------- group barrier (32 blocks) -------------------------
__device__ __forceinline__ void group_sync(int g) {
    __syncthreads();
    if (threadIdx.x == 0) {
        const int slot = g * 32;
        unsigned my = g_epoch[slot];
        __threadfence();
        unsigned old = atomicAdd(&g_count[slot], 1u);
        if (old == GRPBLK - 1) {
            g_count[slot] = 0;
            __threadfence();
            g_epoch[slot] = my + 1;
        } else {
            while (g_epoch[slot] == my) { __nanosleep(16); }
            __threadfence();
        }
    }
    __syncthreads();
}

// ------------------------- init ----------------------------------------------
__global__ void init_kernel(const float* __restrict__ W_ih,
                            const float* __restrict__ W_hh,
                            const float* __restrict__ b_ih,
                            const float* __restrict__ b_hh,
                            const float* __restrict__ W_i2h,
                            const float* __restrict__ W_h2h,
                            const float* __restrict__ W_gen) {
    int idx = blockIdx.x * 256 + threadIdx.x;
    if (idx < GDIM * XDIM) {
        int j = idx >> 9, k = idx & 511;
        float v = (k < 256) ? W_ih[j * WIH_LD + k] : W_hh[j * 256 + (k - 256)];
        g_Wcat_h[idx] = __float2half_rn(v);
    }
    if (idx < HSZ * HSZ) {
        int j = idx >> 8, k = idx & 255;
        g_Wh2hT_h[k * HSZ + j] = __float2half_rn(W_h2h[idx]);
        g_Wi2h_h[idx] = __float2half_rn(W_i2h[idx]);
    }
    if (idx < NCLS * HSZ) g_Wgen_h[idx] = __float2half_rn(W_gen[idx]);
    if (idx < NCLS * GDIM) {
        int cls = idx >> 10, c = idx & 1023;
        g_Wemb[idx] = W_ih[(size_t)c * WIH_LD + 256 + cls] + b_ih[c] + b_hh[c];
    }
    if (idx < BSZ * HSZ) g_c[idx] = 0.0f;
}

// ------------------------- fp16 MMA GEMM, tile 128x64 (prolog/epilog) -------
template <int MODE, bool OUT_HALF, bool A_HALF, bool DUMP_A>
__global__ __launch_bounds__(256) void hgemm2(
    const void* __restrict__ Aptr, const __half* __restrict__ Bw,
    void* __restrict__ Cm,
    int M, int N, int K, int lda, int ldb, int ldc,
    const float* __restrict__ bias) {

    __shared__ __half As[128 * 40];
    __shared__ __half Bs[64 * 40];

    const int m0 = blockIdx.y * 128, n0 = blockIdx.x * 64;
    const int tid = threadIdx.x, lane = tid & 31, warp = tid >> 5;
    const int wm = (warp >> 1) * 32, wn = (warp & 1) * 32;
    const int gID = lane >> 2, tig = lane & 3;
    const int ar = tid >> 1, aseg = (tid & 1) << 4;
    const int br = tid >> 2, bseg = (tid & 3) << 3;

    float acc[2][4][4];
#pragma unroll
    for (int mf = 0; mf < 2; mf++)
#pragma unroll
        for (int i = 0; i < 4; i++)
#pragma unroll
            for (int j = 0; j < 4; j++) acc[mf][i][j] = 0.0f;

    auto loadA = [&](int k0, uint4& o0, uint4& o1) {
        if (A_HALF) {
            const __half* A = (const __half*)Aptr;
            const __half* p = A + (size_t)(m0 + ar) * lda + k0 + aseg;
            o0 = *(const uint4*)p;
            o1 = *(const uint4*)(p + 8);
        } else {
            const float* A = (const float*)Aptr;
            const float* p = A + (size_t)(m0 + ar) * lda + k0 + aseg;
            float4 f0 = *(const float4*)p;
            float4 f1 = *(const float4*)(p + 4);
            float4 f2 = *(const float4*)(p + 8);
            float4 f3 = *(const float4*)(p + 12);
            __half2 h;
            h = __floats2half2_rn(f0.x, f0.y); o0.x = *(uint32_t*)&h;
            h = __floats2half2_rn(f0.z, f0.w); o0.y = *(uint32_t*)&h;
            h = __floats2half2_rn(f1.x, f1.y); o0.z = *(uint32_t*)&h;
            h = __floats2half2_rn(f1.z, f1.w); o0.w = *(uint32_t*)&h;
            h = __floats2half2_rn(f2.x, f2.y); o1.x = *(uint32_t*)&h;
            h = __floats2half2_rn(f2.z, f2.w); o1.y = *(uint32_t*)&h;
            h = __floats2half2_rn(f3.x, f3.y); o1.z = *(uint32_t*)&h;
            h = __floats2half2_rn(f3.z, f3.w); o1.w = *(uint32_t*)&h;
        }
    };
    auto loadB = [&](int k0) -> uint4 {
        if (n0 + br < N)
            return *(const uint4*)(Bw + (size_t)(n0 + br) * ldb + k0 + bseg);
        return make_uint4(0u, 0u, 0u, 0u);
    };

    uint4 a0R, a1R, bR;
    loadA(0, a0R, a1R);
    bR = loadB(0);
    const int iters = K >> 5;

    for (int it = 0; it < iters; it++) {
        __syncthreads();
        *(uint4*)&As[ar * 40 + aseg] = a0R;
        *(uint4*)&As[ar * 40 + aseg + 8] = a1R;
        if (br < 64) *(uint4*)&Bs[br * 40 + bseg] = bR;
        if (DUMP_A && blockIdx.x == 0) {
            __half* d = g_batchH_h + (size_t)(m0 + ar) * ISZ + it * 32 + aseg;
            *(uint4*)d = a0R;
            *(uint4*)(d + 8) = a1R;
        }
        __syncthreads();
        if (it + 1 < iters) {
            loadA((it + 1) << 5, a0R, a1R);
            bR = loadB((it + 1) << 5);
        }
#pragma unroll
        for (int kk = 0; kk < 32; kk += 16) {
            uint32_t af[2][4];
#pragma unroll
            for (int mf = 0; mf < 2; mf++) {
                int rb = wm + mf * 16 + gID;
                af[mf][0] = *(uint32_t*)&As[rb * 40 + kk + tig * 2];
                af[mf][1] = *(uint32_t*)&As[(rb + 8) * 40 + kk + tig * 2];
                af[mf][2] = *(uint32_t*)&As[rb * 40 + kk + 8 + tig * 2];
                af[mf][3] = *(uint32_t*)&As[(rb + 8) * 40 + kk + 8 + tig * 2];
            }
#pragma unroll
            for (int nt = 0; nt < 4; nt++) {
                uint32_t b0 = *(uint32_t*)&Bs[(wn + nt * 8 + gID) * 40 + kk + tig * 2];
                uint32_t b1 = *(uint32_t*)&Bs[(wn + nt * 8 + gID) * 40 + kk + 8 + tig * 2];
#pragma unroll
                for (int mf = 0; mf < 2; mf++) {
                    asm volatile(
                        "mma.sync.aligned.m16n8k16.row.col.f32.f16.f16.f32 "
                        "{%0,%1,%2,%3}, {%4,%5,%6,%7}, {%8,%9}, {%0,%1,%2,%3};"
                        : "+f"(acc[mf][nt][0]), "+f"(acc[mf][nt][1]),
                          "+f"(acc[mf][nt][2]), "+f"(acc[mf][nt][3])
                        : "r"(af[mf][0]), "r"(af[mf][1]), "r"(af[mf][2]),
                          "r"(af[mf][3]), "r"(b0), "r"(b1));
                }
            }
        }
    }

#pragma unroll
    for (int mf = 0; mf < 2; mf++) {
        const int r0 = m0 + wm + mf * 16 + gID, r1 = r0 + 8;
#pragma unroll
        for (int nt = 0; nt < 4; nt++) {
            int cbase = n0 + wn + nt * 8 + 2 * tig;
#pragma unroll
            for (int hr = 0; hr < 2; hr++) {
                int r = hr ? r1 : r0;
                if (r >= M) continue;
#pragma unroll
                for (int jj = 0; jj < 2; jj++) {
                    int c = cbase + jj;
                    if (c >= N) continue;
                    float v = acc[mf][nt][hr * 2 + jj];
                    if (MODE == 3) {
                        v += bias[c];
                        if (c == BLANK_ID) v = -10000.0f;
                    }
                    if (OUT_HALF)
                        ((__half*)Cm)[(size_t)r * ldc + c] = __float2half_rn(v);
                    else
                        ((float*)Cm)[(size_t)r * ldc + c] = v;
                }
            }
        }
    }
}

// ------------------------- persistent 26-step kernel (512 thr) ---------------
__global__ __launch_bounds__(NTHR, 1) void persistent_steps(
    const int* __restrict__ text, const float* __restrict__ b_h2h,
    const float* __restrict__ wscore) {

    extern __shared__ char dyn[];
    __half* Bs = (__half*)dyn;                         // [64][BSTR]
    __half* As = Bs + 64 * BSTR;                       // [64][BSTR] (phase B)
    float*  red = (float*)As;                          // [16][4][256] overlay 64KB
    char* tail = dyn + 4 * 64 * BSTR;
    __half*  sh   = (__half*)tail;                     // [4][256]
    __half*  sp_h = sh + 1024;                         // [4][256]
    __half*  sw_h = sp_h + 1024;                       // [256]
    float*   sb   = (float*)(sw_h + 256);              // [256]
    float*   se   = sb + 256;                          // [4][128]
    __half2* seh  = (__half2*)(se + 512);              // [4][128]

    const int tid = threadIdx.x, lane = tid & 31, warp = tid >> 5;
    const int bid = blockIdx.x;
    const int grp = bid >> 5;
    const int lid = bid & 31;
    const int b0 = bid * RPB;
    const int m0 = grp * 128 + (lid >> 4) * 64;
    const int n0 = (lid & 15) * 64;
    // gates: 16 warps, 4x4 grid, warp tile 16x16
    const int wm4 = (warp >> 2) * 16, wn4 = (warp & 3) * 16;
    const int gID = lane >> 2, tig = lane & 3;

    if (tid < 256) {
        sw_h[tid] = __float2half_rn(wscore[tid]);
        sb[tid] = b_h2h[tid];
    }

    // preload Wcat B-slab once: 4096 uint4 / 512 thr = 8 each
#pragma unroll
    for (int i = 0; i < 8; i++) {
        int linear = tid + (i << 9);
        int row = linear >> 6, c8 = (linear & 63) << 3;
        *(uint4*)&Bs[row * BSTR + c8] =
            *(const uint4*)(g_Wcat_h + ((size_t)(n0 + row)) * XDIM + c8);
    }
    __syncthreads();

    __half2 swl2[4];
    {
        uint4 v = *(const uint4*)(sw_h + lane * 8);
        swl2[0] = *(__half2*)&v.x; swl2[1] = *(__half2*)&v.y;
        swl2[2] = *(__half2*)&v.z; swl2[3] = *(__half2*)&v.w;
    }

    for (int s = 0; s < NSTEP; s++) {
        // ==== LSTM(s-1) -> h : 4 rows x 256 j = 1024 items, 2/thread ====
        {
            const int r = tid >> 7, jb = tid & 127;
            const int row = b0 + r;
            if (s > 0) {
                const float* g = g_gates + (size_t)row * GDIM;
                float* cp = g_c + (size_t)row * HSZ;
#pragma unroll
                for (int jj = 0; jj < 2; jj++) {
                    int j = jb + (jj << 7);
                    float ig = fast_sigmoid(g[j]);
                    float fg = fast_sigmoid(g[j + 256]);
                    float gg = tanh_fast(g[j + 512]);
                    float og = fast_sigmoid(g[j + 768]);
                    float cn = fg * cp[j] + ig * gg;
                    float hn = og * tanh_fast(cn);
                    cp[j] = cn;
                    __half hh = __float2half_rn(hn);
                    sh[r * HSZ + j] = hh;
                    g_X_h[(size_t)row * XDIM + 256 + j] = hh;
                    g_hs_h[((size_t)row * NSTEP + (s - 1)) * HSZ + j] = hh;
                }
            } else {
                __half z = __float2half_rn(0.0f);
#pragma unroll
                for (int jj = 0; jj < 2; jj++) {
                    int j = jb + (jj << 7);
                    sh[r * HSZ + j] = z;
                    g_X_h[(size_t)row * XDIM + 256 + j] = z;
                }
            }
        }
        __syncthreads();

        // ==== projh partials: warp w covers k in [w*16, +16) ====
        {
            const int kb = warp << 4;
            __half2 acc2[RPB][4];
#pragma unroll
            for (int r = 0; r < RPB; r++)
#pragma unroll
                for (int p = 0; p < 4; p++)
                    acc2[r][p] = __floats2half2_rn(0.f, 0.f);

            const __half* WT = g_Wh2hT_h + (size_t)kb * HSZ + lane * 8;
#pragma unroll 4
            for (int k = 0; k < 16; k++) {
                uint4 wv = *(const uint4*)(WT + k * HSZ);
                __half2 wh[4];
                wh[0] = *(__half2*)&wv.x; wh[1] = *(__half2*)&wv.y;
                wh[2] = *(__half2*)&wv.z; wh[3] = *(__half2*)&wv.w;
#pragma unroll
                for (int r = 0; r < RPB; r++) {
                    __half2 hk2 = __half2half2(sh[r * HSZ + kb + k]);
#pragma unroll
                    for (int p = 0; p < 4; p++)
                        acc2[r][p] = __hfma2(wh[p], hk2, acc2[r][p]);
                }
            }
#pragma unroll
            for (int r = 0; r < RPB; r++) {
#pragma unroll
                for (int p = 0; p < 4; p++) {
                    float2 f = __half22float2(acc2[r][p]);
                    *(float2*)&red[((warp * RPB + r) * HSZ) + lane * 8 + 2 * p] = f;
                }
            }
        }
        __syncthreads();

        // ==== reduce 16 partials -> sp_h : thread owns (r, 2 j's) ====
        {
            const int r = tid >> 7, jb2 = (tid & 127) << 1;
            float2 sum = make_float2(0.f, 0.f);
#pragma unroll
            for (int w = 0; w < 16; w++) {
                float2 v = *(const float2*)&red[((w * RPB + r) * HSZ) + jb2];
                sum.x += v.x; sum.y += v.y;
            }
            float2 bv = *(const float2*)&sb[jb2];
            __half2 h0 = __floats2half2_rn(sum.x + bv.x, sum.y + bv.y);
            *(__half2*)&sp_h[r * HSZ + jb2] = h0;
        }
        __syncthreads();

        // ==== scores: 4 warps per row, 32 t each ====
        {
            const int r = warp >> 2;
            const int tb = (warp & 3) << 5;
            __half2 spl2[4];
            {
                uint4 v = *(const uint4*)(sp_h + r * HSZ + lane * 8);
                spl2[0] = *(__half2*)&v.x; spl2[1] = *(__half2*)&v.y;
                spl2[2] = *(__half2*)&v.z; spl2[3] = *(__half2*)&v.w;
            }
            const __half* pH = g_projH_h + ((size_t)(b0 + r) * TLEN + tb) * HSZ + lane * 8;
            for (int t = 0; t < 32; t += 4) {
                uint4 v[4];
#pragma unroll
                for (int u = 0; u < 4; u++) v[u] = *(const uint4*)(pH + (t + u) * HSZ);
                float ac[4];
#pragma unroll
                for (int u = 0; u < 4; u++) {
                    __half2 hv[4];
                    hv[0] = *(__half2*)&v[u].x; hv[1] = *(__half2*)&v[u].y;
                    hv[2] = *(__half2*)&v[u].z; hv[3] = *(__half2*)&v[u].w;
                    __half2 prod = __floats2half2_rn(0.f, 0.f);
#pragma unroll
                    for (int p = 0; p < 4; p++) {
                        __half2 th = tanh2(__hadd2(hv[p], spl2[p]));
                        prod = __hfma2(swl2[p], th, prod);
                    }
                    float2 f = __half22float2(prod);
                    ac[u] = f.x + f.y;
                }
#pragma unroll
                for (int u = 0; u < 4; u++) {
#pragma unroll
                    for (int o = 16; o; o >>= 1)
                        ac[u] += __shfl_xor_sync(0xffffffffu, ac[u], o);
                    if (lane == 0) se[r * TLEN + tb + t + u] = ac[u];
                }
            }
        }
        __syncthreads();

        // ==== softmax -> seh (warps 0..3) ====
        if (warp < RPB) {
            const float* sr = se + warp * TLEN;
            float v0 = sr[lane], v1 = sr[lane + 32];
            float v2 = sr[lane + 64], v3 = sr[lane + 96];
            float mx = fmaxf(fmaxf(v0, v1), fmaxf(v2, v3));
#pragma unroll
            for (int o = 16; o; o >>= 1) mx = fmaxf(mx, __shfl_xor_sync(0xffffffffu, mx, o));
            float e0 = __expf(v0 - mx), e1 = __expf(v1 - mx);
            float e2 = __expf(v2 - mx), e3 = __expf(v3 - mx);
            float sum = e0 + e1 + e2 + e3;
#pragma unroll
            for (int o = 16; o; o >>= 1) sum += __shfl_xor_sync(0xffffffffu, sum, o);
            float inv = 1.0f / sum;
            __half2* dr = seh + warp * TLEN;
            dr[lane]      = __float2half2_rn(e0 * inv);
            dr[lane + 32] = __float2half2_rn(e1 * inv);
            dr[lane + 64] = __float2half2_rn(e2 * inv);
            dr[lane + 96] = __float2half2_rn(e3 * inv);
        }
        __syncthreads();

        // ==== context: thread owns (r, 1 half2 col) ====
        {
            const int r = tid >> 7, ci = tid & 127;
            const __half2* bH = (const __half2*)(g_batchH_h + (size_t)(b0 + r) * TLEN * ISZ);
            const __half2* al = seh + r * TLEN;
            __half2 a0 = __floats2half2_rn(0.f, 0.f);
#pragma unroll 8
            for (int t = 0; t < TLEN; t++)
                a0 = __hfma2(al[t], bH[t * 128 + ci], a0);
            __half2* X2 = (__half2*)(g_X_h + (size_t)(b0 + r) * XDIM);
            X2[ci] = a0;
        }

        group_sync(grp);   // X ready within group

        // ==== gates tile = X[m0:+64] @ Wcat[n0:+64]^T, 16 warps ====
        {
#pragma unroll
            for (int i = 0; i < 8; i++) {
                int linear = tid + (i << 9);
                int row = linear >> 6, c8 = (linear & 63) << 3;
                *(uint4*)&As[row * BSTR + c8] =
                    *(const uint4*)(g_X_h + ((size_t)(m0 + row)) * XDIM + c8);
            }
            __syncthreads();

            float acc[2][4];
#pragma unroll
            for (int i = 0; i < 2; i++)
#pragma unroll
                for (int j = 0; j < 4; j++) acc[i][j] = 0.0f;

#pragma unroll 4
            for (int kk = 0; kk < 512; kk += 16) {
                uint32_t a0 = *(uint32_t*)&As[(wm4 + gID) * BSTR + kk + tig * 2];
                uint32_t a1 = *(uint32_t*)&As[(wm4 + gID + 8) * BSTR + kk + tig * 2];
                uint32_t a2 = *(uint32_t*)&As[(wm4 + gID) * BSTR + kk + 8 + tig * 2];
                uint32_t a3 = *(uint32_t*)&As[(wm4 + gID + 8) * BSTR + kk + 8 + tig * 2];
#pragma unroll
                for (int nt = 0; nt < 2; nt++) {
                    uint32_t bb0 = *(uint32_t*)&Bs[(wn4 + nt * 8 + gID) * BSTR + kk + tig * 2];
                    uint32_t bb1 = *(uint32_t*)&Bs[(wn4 + nt * 8 + gID) * BSTR + kk + 8 + tig * 2];
                    asm volatile(
                        "mma.sync.aligned.m16n8k16.row.col.f32.f16.f16.f32 "
                        "{%0,%1,%2,%3}, {%4,%5,%6,%7}, {%8,%9}, {%0,%1,%2,%3};"
                        : "+f"(acc[nt][0]), "+f"(acc[nt][1]),
                          "+f"(acc[nt][2]), "+f"(acc[nt][3])
                        : "r"(a0), "r"(a1), "r"(a2), "r"(a3), "r"(bb0), "r"(bb1));
                }
            }

            const int r0 = m0 + wm4 + gID, r1 = r0 + 8;
            int tgt0 = text[r0 * NSTEP + s];
            int tgt1 = text[r1 * NSTEP + s];
            const float* e0 = g_Wemb + (size_t)tgt0 * GDIM;
            const float* e1 = g_Wemb + (size_t)tgt1 * GDIM;
#pragma unroll
            for (int nt = 0; nt < 2; nt++) {
                int cbase = n0 + wn4 + nt * 8 + 2 * tig;
                float2 w0 = *(const float2*)(e0 + cbase);
                float2 w1 = *(const float2*)(e1 + cbase);
                float2 o0 = make_float2(acc[nt][0] + w0.x, acc[nt][1] + w0.y);
                float2 o1 = make_float2(acc[nt][2] + w1.x, acc[nt][3] + w1.y);
                *(float2*)&g_gates[(size_t)r0 * GDIM + cbase] = o0;
                *(float2*)&g_gates[(size_t)r1 * GDIM + cbase] = o1;
            }
        }

        group_sync(grp);   // gates ready within group
    }

    // final LSTM -> hs[25]
    {
        const int r = tid >> 7, jb = tid & 127;
        const int row = b0 + r;
        const float* g = g_gates + (size_t)row * GDIM;
        const float* cp = g_c + (size_t)row * HSZ;
#pragma unroll
        for (int jj = 0; jj < 2; jj++) {
            int j = jb + (jj << 7);
            float ig = fast_sigmoid(g[j]);
            float fg = fast_sigmoid(g[j + 256]);
            float gg = tanh_fast(g[j + 512]);
            float og = fast_sigmoid(g[j + 768]);
            float cn = fg * cp[j] + ig * gg;
            float hn = og * tanh_fast(cn);
            g_hs_h[((size_t)row * NSTEP + (NSTEP - 1)) * HSZ + j] = __float2half_rn(hn);
        }
    }
}

// ------------------------- launch -------------------------------------------
extern "C" void kernel_launch(void* const* d_in, const int* in_sizes, int n_in,
                              void* d_out, int out_size) {
    const float* batch_H = (const float*)d_in[0];
    const int*   text    = (const int*)d_in[1];
    const float* W_i2h   = (const float*)d_in[3];
    const float* W_h2h   = (const float*)d_in[4];
    const float* b_h2h   = (const float*)d_in[5];
    const float* W_score = (const float*)d_in[6];
    const float* W_ih    = (const float*)d_in[7];
    const float* W_hh    = (const float*)d_in[8];
    const float* b_ih    = (const float*)d_in[9];
    const float* b_hh    = (const float*)d_in[10];
    const float* W_gen   = (const float*)d_in[11];
    const float* b_gen   = (const float*)d_in[12];
    float* out = (float*)d_out;

    __half *projH_h, *Wi2h_h, *Wgen_h, *hs_h;
    cudaGetSymbolAddress((void**)&projH_h, g_projH_h);
    cudaGetSymbolAddress((void**)&Wi2h_h,  g_Wi2h_h);
    cudaGetSymbolAddress((void**)&Wgen_h,  g_Wgen_h);
    cudaGetSymbolAddress((void**)&hs_h,    g_hs_h);

    static bool attr_set = false;
    if (!attr_set) {
        cudaFuncSetAttribute(persistent_steps,
                             cudaFuncAttributeMaxDynamicSharedMemorySize,
                             SMEM_BYTES);
        attr_set = true;
    }

    init_kernel<<<2048, 256>>>(W_ih, W_hh, b_ih, b_hh, W_i2h, W_h2h, W_gen);

    hgemm2<0, true, false, true><<<dim3(4, 512), 256>>>(
        batch_H, Wi2h_h, projH_h, BSZ * TLEN, HSZ, ISZ, ISZ, ISZ, HSZ, nullptr);

    persistent_steps<<<NBLK, NTHR, SMEM_BYTES>>>(text, b_h2h, W_score);

    hgemm2<3, false, true, false><<<dim3(2, 104), 256>>>(
        hs_h, Wgen_h, out, BSZ * NSTEP, NCLS, HSZ, HSZ, HSZ, NCLS, b_gen);
}

// round 8
// speedup vs baseline: 4.2278x; 1.0380x over previous
#include <cuda_runtime.h>
#include <cuda_fp16.h>
#include <cstdint>

#define BSZ   512
#define TLEN  128
#define ISZ   256
#define HSZ   256
#define NCLS  100
#define NSTEP 26
#define XDIM  512
#define GDIM  1024
#define WIH_LD 356
#define BLANK_ID 3
#define RPB   4
#define NBLK  128
#define GRPBLK 32
#define NTHR  512
#define BSTR  520
#define TAIL_BYTES (2048 + 2048 + 512 + 1024 + 2048 + 2048)
#define SMEM_BYTES (4 * 64 * BSTR + TAIL_BYTES)

// ------------------------- device scratch -----------------------------------
__device__ uint8_t g_projH_f8[BSZ * TLEN * HSZ];    // e4m3, 16.7 MB
__device__ uint8_t g_batchH_f8[BSZ * TLEN * ISZ];   // e4m3, 16.7 MB
__device__ __half g_X_h[BSZ * XDIM];
__device__ float  g_gates[BSZ * GDIM];
__device__ float  g_c[BSZ * HSZ];
__device__ __half g_hs_h[BSZ * NSTEP * HSZ];
__device__ __half g_Wcat_h[GDIM * XDIM];
__device__ __half g_Wh2hT_h[HSZ * HSZ];
__device__ __half g_Wi2h_h[HSZ * ISZ];
__device__ __half g_Wgen_h[NCLS * HSZ];
__device__ float  g_Wemb[NCLS * GDIM];
__device__ unsigned g_count[4 * 32];
__device__ volatile unsigned g_epoch[4 * 32];

// ------------------------- fast math ----------------------------------------
__device__ __forceinline__ float tanh_fast(float x) {
    float y;
    asm("tanh.approx.f32 %0, %1;" : "=f"(y) : "f"(x));
    return y;
}
__device__ __forceinline__ float fast_sigmoid(float x) {
    return 0.5f * (1.0f + tanh_fast(0.5f * x));
}
__device__ __forceinline__ __half2 tanh2(__half2 x) {
    uint32_t xi = *(uint32_t*)&x, yo;
    asm("tanh.approx.f16x2 %0, %1;" : "=r"(yo) : "r"(xi));
    return *(__half2*)&yo;
}
__device__ __forceinline__ uint16_t h2_to_e4m3x2(__half2 h) {
    uint16_t r;
    asm("cvt.rn.satfinite.e4m3x2.f16x2 %0, %1;" : "=h"(r) : "r"(*(uint32_t*)&h));
    return r;
}
__device__ __forceinline__ __half2 e4m3x2_to_h2(uint16_t b) {
    uint32_t r;
    asm("cvt.rn.f16x2.e4m3x2 %0, %1;" : "=r"(r) : "h"(b));
    return *(__half2*)&r;
}

// ------------------------- group barrier (32 blocks) -------------------------
__device__ __forceinline__ void group_sync(int g) {
    __syncthreads();
    if (threadIdx.x == 0) {
        const int slot = g * 32;
        unsigned my = g_epoch[slot];
        __threadfence();
        unsigned old = atomicAdd(&g_count[slot], 1u);
        if (old == GRPBLK - 1) {
            g_count[slot] = 0;
            __threadfence();
            g_epoch[slot] = my + 1;
        } else {
            while (g_epoch[slot] == my) { __nanosleep(16); }
            __threadfence();
        }
    }
    __syncthreads();
}

// ------------------------- init ----------------------------------------------
__global__ void init_kernel(const float* __restrict__ W_ih,
                            const float* __restrict__ W_hh,
                            const float* __restrict__ b_ih,
                            const float* __restrict__ b_hh,
                            const float* __restrict__ W_i2h,
                            const float* __restrict__ W_h2h,
                            const float* __restrict__ W_gen) {
    int idx = blockIdx.x * 256 + threadIdx.x;
    if (idx < GDIM * XDIM) {
        int j = idx >> 9, k = idx & 511;
        float v = (k < 256) ? W_ih[j * WIH_LD + k] : W_hh[j * 256 + (k - 256)];
        g_Wcat_h[idx] = __float2half_rn(v);
    }
    if (idx < HSZ * HSZ) {
        int j = idx >> 8, k = idx & 255;
        g_Wh2hT_h[k * HSZ + j] = __float2half_rn(W_h2h[idx]);
        g_Wi2h_h[idx] = __float2half_rn(W_i2h[idx]);
    }
    if (idx < NCLS * HSZ) g_Wgen_h[idx] = __float2half_rn(W_gen[idx]);
    if (idx < NCLS * GDIM) {
        int cls = idx >> 10, c = idx & 1023;
        g_Wemb[idx] = W_ih[(size_t)c * WIH_LD + 256 + cls] + b_ih[c] + b_hh[c];
    }
    if (idx < BSZ * HSZ) g_c[idx] = 0.0f;
}

// ------------------------- fp16 MMA GEMM, tile 128x64 ------------------------
// OUTK: 0=float, 1=half, 2=e4m3.  MODE 0: plain  3: +bias, blank:=-1e4
template <int MODE, int OUTK, bool A_HALF, bool DUMP_FP8>
__global__ __launch_bounds__(256) void hgemm2(
    const void* __restrict__ Aptr, const __half* __restrict__ Bw,
    void* __restrict__ Cm,
    int M, int N, int K, int lda, int ldb, int ldc,
    const float* __restrict__ bias) {

    __shared__ __half As[128 * 40];
    __shared__ __half Bs[64 * 40];

    const int m0 = blockIdx.y * 128, n0 = blockIdx.x * 64;
    const int tid = threadIdx.x, lane = tid & 31, warp = tid >> 5;
    const int wm = (warp >> 1) * 32, wn = (warp & 1) * 32;
    const int gID = lane >> 2, tig = lane & 3;
    const int ar = tid >> 1, aseg = (tid & 1) << 4;
    const int br = tid >> 2, bseg = (tid & 3) << 3;

    float acc[2][4][4];
#pragma unroll
    for (int mf = 0; mf < 2; mf++)
#pragma unroll
        for (int i = 0; i < 4; i++)
#pragma unroll
            for (int j = 0; j < 4; j++) acc[mf][i][j] = 0.0f;

    auto loadA = [&](int k0, uint4& o0, uint4& o1) {
        if (A_HALF) {
            const __half* A = (const __half*)Aptr;
            const __half* p = A + (size_t)(m0 + ar) * lda + k0 + aseg;
            o0 = *(const uint4*)p;
            o1 = *(const uint4*)(p + 8);
        } else {
            const float* A = (const float*)Aptr;
            const float* p = A + (size_t)(m0 + ar) * lda + k0 + aseg;
            float4 f0 = *(const float4*)p;
            float4 f1 = *(const float4*)(p + 4);
            float4 f2 = *(const float4*)(p + 8);
            float4 f3 = *(const float4*)(p + 12);
            __half2 h;
            h = __floats2half2_rn(f0.x, f0.y); o0.x = *(uint32_t*)&h;
            h = __floats2half2_rn(f0.z, f0.w); o0.y = *(uint32_t*)&h;
            h = __floats2half2_rn(f1.x, f1.y); o0.z = *(uint32_t*)&h;
            h = __floats2half2_rn(f1.z, f1.w); o0.w = *(uint32_t*)&h;
            h = __floats2half2_rn(f2.x, f2.y); o1.x = *(uint32_t*)&h;
            h = __floats2half2_rn(f2.z, f2.w); o1.y = *(uint32_t*)&h;
            h = __floats2half2_rn(f3.x, f3.y); o1.z = *(uint32_t*)&h;
            h = __floats2half2_rn(f3.z, f3.w); o1.w = *(uint32_t*)&h;
        }
    };
    auto loadB = [&](int k0) -> uint4 {
        if (n0 + br < N)
            return *(const uint4*)(Bw + (size_t)(n0 + br) * ldb + k0 + bseg);
        return make_uint4(0u, 0u, 0u, 0u);
    };

    uint4 a0R, a1R, bR;
    loadA(0, a0R, a1R);
    bR = loadB(0);
    const int iters = K >> 5;

    for (int it = 0; it < iters; it++) {
        __syncthreads();
        *(uint4*)&As[ar * 40 + aseg] = a0R;
        *(uint4*)&As[ar * 40 + aseg + 8] = a1R;
        if (br < 64) *(uint4*)&Bs[br * 40 + bseg] = bR;
        if (DUMP_FP8 && blockIdx.x == 0) {
            // dump A (fp16 regs) as e4m3 bytes
            uint32_t p0 = h2_to_e4m3x2(*(__half2*)&a0R.x) |
                          ((uint32_t)h2_to_e4m3x2(*(__half2*)&a0R.y) << 16);
            uint32_t p1 = h2_to_e4m3x2(*(__half2*)&a0R.z) |
                          ((uint32_t)h2_to_e4m3x2(*(__half2*)&a0R.w) << 16);
            uint32_t p2 = h2_to_e4m3x2(*(__half2*)&a1R.x) |
                          ((uint32_t)h2_to_e4m3x2(*(__half2*)&a1R.y) << 16);
            uint32_t p3 = h2_to_e4m3x2(*(__half2*)&a1R.z) |
                          ((uint32_t)h2_to_e4m3x2(*(__half2*)&a1R.w) << 16);
            *(uint4*)(g_batchH_f8 + (size_t)(m0 + ar) * ISZ + it * 32 + aseg) =
                make_uint4(p0, p1, p2, p3);
        }
        __syncthreads();
        if (it + 1 < iters) {
            loadA((it + 1) << 5, a0R, a1R);
            bR = loadB((it + 1) << 5);
        }
#pragma unroll
        for (int kk = 0; kk < 32; kk += 16) {
            uint32_t af[2][4];
#pragma unroll
            for (int mf = 0; mf < 2; mf++) {
                int rb = wm + mf * 16 + gID;
                af[mf][0] = *(uint32_t*)&As[rb * 40 + kk + tig * 2];
                af[mf][1] = *(uint32_t*)&As[(rb + 8) * 40 + kk + tig * 2];
                af[mf][2] = *(uint32_t*)&As[rb * 40 + kk + 8 + tig * 2];
                af[mf][3] = *(uint32_t*)&As[(rb + 8) * 40 + kk + 8 + tig * 2];
            }
#pragma unroll
            for (int nt = 0; nt < 4; nt++) {
                uint32_t b0 = *(uint32_t*)&Bs[(wn + nt * 8 + gID) * 40 + kk + tig * 2];
                uint32_t b1 = *(uint32_t*)&Bs[(wn + nt * 8 + gID) * 40 + kk + 8 + tig * 2];
#pragma unroll
                for (int mf = 0; mf < 2; mf++) {
                    asm volatile(
                        "mma.sync.aligned.m16n8k16.row.col.f32.f16.f16.f32 "
                        "{%0,%1,%2,%3}, {%4,%5,%6,%7}, {%8,%9}, {%0,%1,%2,%3};"
                        : "+f"(acc[mf][nt][0]), "+f"(acc[mf][nt][1]),
                          "+f"(acc[mf][nt][2]), "+f"(acc[mf][nt][3])
                        : "r"(af[mf][0]), "r"(af[mf][1]), "r"(af[mf][2]),
                          "r"(af[mf][3]), "r"(b0), "r"(b1));
                }
            }
        }
    }

#pragma unroll
    for (int mf = 0; mf < 2; mf++) {
        const int r0 = m0 + wm + mf * 16 + gID, r1 = r0 + 8;
#pragma unroll
        for (int nt = 0; nt < 4; nt++) {
            int cb = n0 + wn + nt * 8 + 2 * tig;   // even; pair (cb, cb+1)
#pragma unroll
            for (int hr = 0; hr < 2; hr++) {
                int r = hr ? r1 : r0;
                if (r >= M) continue;
                if (cb >= N) continue;              // pairs never straddle N=100
                float v0 = acc[mf][nt][hr * 2 + 0];
                float v1 = acc[mf][nt][hr * 2 + 1];
                if (MODE == 3) {
                    v0 += bias[cb];
                    v1 += bias[cb + 1];
                    if (cb == BLANK_ID) v0 = -10000.0f;
                    if (cb + 1 == BLANK_ID) v1 = -10000.0f;
                }
                if (OUTK == 2) {
                    uint16_t pb = h2_to_e4m3x2(__floats2half2_rn(v0, v1));
                    *(uint16_t*)((uint8_t*)Cm + (size_t)r * ldc + cb) = pb;
                } else if (OUTK == 1) {
                    *(__half2*)((__half*)Cm + (size_t)r * ldc + cb) =
                        __floats2half2_rn(v0, v1);
                } else {
                    *(float2*)((float*)Cm + (size_t)r * ldc + cb) =
                        make_float2(v0, v1);
                }
            }
        }
    }
}

// ------------------------- persistent 26-step kernel (512 thr) ---------------
__global__ __launch_bounds__(NTHR, 1) void persistent_steps(
    const int* __restrict__ text, const float* __restrict__ b_h2h,
    const float* __restrict__ wscore) {

    extern __shared__ char dyn[];
    __half* Bs = (__half*)dyn;                         // [64][BSTR]
    __half* As = Bs + 64 * BSTR;                       // [64][BSTR] (phase B)
    float*  red = (float*)As;                          // [16][4][256] overlay
    char* tail = dyn + 4 * 64 * BSTR;
    __half*  sh   = (__half*)tail;                     // [4][256]
    __half*  sp_h = sh + 1024;                         // [4][256]
    __half*  sw_h = sp_h + 1024;                       // [256]
    float*   sb   = (float*)(sw_h + 256);              // [256]
    float*   se   = sb + 256;                          // [4][128]
    __half2* seh  = (__half2*)(se + 512);              // [4][128]

    const int tid = threadIdx.x, lane = tid & 31, warp = tid >> 5;
    const int bid = blockIdx.x;
    const int grp = bid >> 5;
    const int lid = bid & 31;
    const int b0 = bid * RPB;
    const int m0 = grp * 128 + (lid >> 4) * 64;
    const int n0 = (lid & 15) * 64;
    const int wm4 = (warp >> 2) * 16, wn4 = (warp & 3) * 16;
    const int gID = lane >> 2, tig = lane & 3;

    if (tid < 256) {
        sw_h[tid] = __float2half_rn(wscore[tid]);
        sb[tid] = b_h2h[tid];
    }

#pragma unroll
    for (int i = 0; i < 8; i++) {
        int linear = tid + (i << 9);
        int row = linear >> 6, c8 = (linear & 63) << 3;
        *(uint4*)&Bs[row * BSTR + c8] =
            *(const uint4*)(g_Wcat_h + ((size_t)(n0 + row)) * XDIM + c8);
    }
    __syncthreads();

    __half2 swl2[4];
    {
        uint4 v = *(const uint4*)(sw_h + lane * 8);
        swl2[0] = *(__half2*)&v.x; swl2[1] = *(__half2*)&v.y;
        swl2[2] = *(__half2*)&v.z; swl2[3] = *(__half2*)&v.w;
    }

    for (int s = 0; s < NSTEP; s++) {
        // ==== LSTM(s-1) -> h ====
        {
            const int r = tid >> 7, jb = tid & 127;
            const int row = b0 + r;
            if (s > 0) {
                const float* g = g_gates + (size_t)row * GDIM;
                float* cp = g_c + (size_t)row * HSZ;
#pragma unroll
                for (int jj = 0; jj < 2; jj++) {
                    int j = jb + (jj << 7);
                    float ig = fast_sigmoid(g[j]);
                    float fg = fast_sigmoid(g[j + 256]);
                    float gg = tanh_fast(g[j + 512]);
                    float og = fast_sigmoid(g[j + 768]);
                    float cn = fg * cp[j] + ig * gg;
                    float hn = og * tanh_fast(cn);
                    cp[j] = cn;
                    __half hh = __float2half_rn(hn);
                    sh[r * HSZ + j] = hh;
                    g_X_h[(size_t)row * XDIM + 256 + j] = hh;
                    g_hs_h[((size_t)row * NSTEP + (s - 1)) * HSZ + j] = hh;
                }
            } else {
                __half z = __float2half_rn(0.0f);
#pragma unroll
                for (int jj = 0; jj < 2; jj++) {
                    int j = jb + (jj << 7);
                    sh[r * HSZ + j] = z;
                    g_X_h[(size_t)row * XDIM + 256 + j] = z;
                }
            }
        }
        __syncthreads();

        // ==== projh partials: warp w covers k in [w*16, +16) ====
        {
            const int kb = warp << 4;
            __half2 acc2[RPB][4];
#pragma unroll
            for (int r = 0; r < RPB; r++)
#pragma unroll
                for (int p = 0; p < 4; p++)
                    acc2[r][p] = __floats2half2_rn(0.f, 0.f);

            const __half* WT = g_Wh2hT_h + (size_t)kb * HSZ + lane * 8;
#pragma unroll 4
            for (int k = 0; k < 16; k++) {
                uint4 wv = *(const uint4*)(WT + k * HSZ);
                __half2 wh[4];
                wh[0] = *(__half2*)&wv.x; wh[1] = *(__half2*)&wv.y;
                wh[2] = *(__half2*)&wv.z; wh[3] = *(__half2*)&wv.w;
#pragma unroll
                for (int r = 0; r < RPB; r++) {
                    __half2 hk2 = __half2half2(sh[r * HSZ + kb + k]);
#pragma unroll
                    for (int p = 0; p < 4; p++)
                        acc2[r][p] = __hfma2(wh[p], hk2, acc2[r][p]);
                }
            }
#pragma unroll
            for (int r = 0; r < RPB; r++) {
#pragma unroll
                for (int p = 0; p < 4; p++) {
                    float2 f = __half22float2(acc2[r][p]);
                    *(float2*)&red[((warp * RPB + r) * HSZ) + lane * 8 + 2 * p] = f;
                }
            }
        }
        __syncthreads();

        // ==== reduce 16 partials -> sp_h ====
        {
            const int r = tid >> 7, jb2 = (tid & 127) << 1;
            float2 sum = make_float2(0.f, 0.f);
#pragma unroll
            for (int w = 0; w < 16; w++) {
                float2 v = *(const float2*)&red[((w * RPB + r) * HSZ) + jb2];
                sum.x += v.x; sum.y += v.y;
            }
            float2 bv = *(const float2*)&sb[jb2];
            __half2 h0 = __floats2half2_rn(sum.x + bv.x, sum.y + bv.y);
            *(__half2*)&sp_h[r * HSZ + jb2] = h0;
        }
        __syncthreads();

        // ==== scores: 4 warps per row, 32 t each, fp8 projH ====
        {
            const int r = warp >> 2;
            const int tb = (warp & 3) << 5;
            __half2 spl2[4];
            {
                uint4 v = *(const uint4*)(sp_h + r * HSZ + lane * 8);
                spl2[0] = *(__half2*)&v.x; spl2[1] = *(__half2*)&v.y;
                spl2[2] = *(__half2*)&v.z; spl2[3] = *(__half2*)&v.w;
            }
            const uint8_t* pH = g_projH_f8 + ((size_t)(b0 + r) * TLEN + tb) * HSZ + lane * 8;
            for (int t = 0; t < 32; t += 8) {
                uint2 v[8];
#pragma unroll
                for (int u = 0; u < 8; u++)
                    v[u] = *(const uint2*)(pH + (t + u) * HSZ);
                float ac[8];
#pragma unroll
                for (int u = 0; u < 8; u++) {
                    __half2 d0 = e4m3x2_to_h2((uint16_t)(v[u].x & 0xffffu));
                    __half2 d1 = e4m3x2_to_h2((uint16_t)(v[u].x >> 16));
                    __half2 d2 = e4m3x2_to_h2((uint16_t)(v[u].y & 0xffffu));
                    __half2 d3 = e4m3x2_to_h2((uint16_t)(v[u].y >> 16));
                    __half2 prod = __floats2half2_rn(0.f, 0.f);
                    prod = __hfma2(swl2[0], tanh2(__hadd2(d0, spl2[0])), prod);
                    prod = __hfma2(swl2[1], tanh2(__hadd2(d1, spl2[1])), prod);
                    prod = __hfma2(swl2[2], tanh2(__hadd2(d2, spl2[2])), prod);
                    prod = __hfma2(swl2[3], tanh2(__hadd2(d3, spl2[3])), prod);
                    float2 f = __half22float2(prod);
                    ac[u] = f.x + f.y;
                }
#pragma unroll
                for (int u = 0; u < 8; u++) {
#pragma unroll
                    for (int o = 16; o; o >>= 1)
                        ac[u] += __shfl_xor_sync(0xffffffffu, ac[u], o);
                    if (lane == 0) se[r * TLEN + tb + t + u] = ac[u];
                }
            }
        }
        __syncthreads();

        // ==== softmax -> seh (warps 0..3) ====
        if (warp < RPB) {
            const float* sr = se + warp * TLEN;
            float v0 = sr[lane], v1 = sr[lane + 32];
            float v2 = sr[lane + 64], v3 = sr[lane + 96];
            float mx = fmaxf(fmaxf(v0, v1), fmaxf(v2, v3));
#pragma unroll
            for (int o = 16; o; o >>= 1) mx = fmaxf(mx, __shfl_xor_sync(0xffffffffu, mx, o));
            float e0 = __expf(v0 - mx), e1 = __expf(v1 - mx);
            float e2 = __expf(v2 - mx), e3 = __expf(v3 - mx);
            float sum = e0 + e1 + e2 + e3;
#pragma unroll
            for (int o = 16; o; o >>= 1) sum += __shfl_xor_sync(0xffffffffu, sum, o);
            float inv = 1.0f / sum;
            __half2* dr = seh + warp * TLEN;
            dr[lane]      = __float2half2_rn(e0 * inv);
            dr[lane + 32] = __float2half2_rn(e1 * inv);
            dr[lane + 64] = __float2half2_rn(e2 * inv);
            dr[lane + 96] = __float2half2_rn(e3 * inv);
        }
        __syncthreads();

        // ==== context: thread owns (r, 2 i's), fp8 batchH ====
        {
            const int r = tid >> 7, ci = tid & 127;
            const uint8_t* bH = g_batchH_f8 + (size_t)(b0 + r) * TLEN * ISZ + ci * 2;
            const __half2* al = seh + r * TLEN;
            __half2 a0 = __floats2half2_rn(0.f, 0.f);
#pragma unroll 8
            for (int t = 0; t < TLEN; t++) {
                uint16_t us = *(const uint16_t*)(bH + t * ISZ);
                a0 = __hfma2(al[t], e4m3x2_to_h2(us), a0);
            }
            __half2* X2 = (__half2*)(g_X_h + (size_t)(b0 + r) * XDIM);
            X2[ci] = a0;
        }

        group_sync(grp);   // X ready within group

        // ==== gates tile = X[m0:+64] @ Wcat[n0:+64]^T, 16 warps ====
        {
#pragma unroll
            for (int i = 0; i < 8; i++) {
                int linear = tid + (i << 9);
                int row = linear >> 6, c8 = (linear & 63) << 3;
                *(uint4*)&As[row * BSTR + c8] =
                    *(const uint4*)(g_X_h + ((size_t)(m0 + row)) * XDIM + c8);
            }
            __syncthreads();

            float acc[2][4];
#pragma unroll
            for (int i = 0; i < 2; i++)
#pragma unroll
                for (int j = 0; j < 4; j++) acc[i][j] = 0.0f;

#pragma unroll 4
            for (int kk = 0; kk < 512; kk += 16) {
                uint32_t a0 = *(uint32_t*)&As[(wm4 + gID) * BSTR + kk + tig * 2];
                uint32_t a1 = *(uint32_t*)&As[(wm4 + gID + 8) * BSTR + kk + tig * 2];
                uint32_t a2 = *(uint32_t*)&As[(wm4 + gID) * BSTR + kk + 8 + tig * 2];
                uint32_t a3 = *(uint32_t*)&As[(wm4 + gID + 8) * BSTR + kk + 8 + tig * 2];
#pragma unroll
                for (int nt = 0; nt < 2; nt++) {
                    uint32_t bb0 = *(uint32_t*)&Bs[(wn4 + nt * 8 + gID) * BSTR + kk + tig * 2];
                    uint32_t bb1 = *(uint32_t*)&Bs[(wn4 + nt * 8 + gID) * BSTR + kk + 8 + tig * 2];
                    asm volatile(
                        "mma.sync.aligned.m16n8k16.row.col.f32.f16.f16.f32 "
                        "{%0,%1,%2,%3}, {%4,%5,%6,%7}, {%8,%9}, {%0,%1,%2,%3};"
                        : "+f"(acc[nt][0]), "+f"(acc[nt][1]),
                          "+f"(acc[nt][2]), "+f"(acc[nt][3])
                        : "r"(a0), "r"(a1), "r"(a2), "r"(a3), "r"(bb0), "r"(bb1));
                }
            }

            const int r0 = m0 + wm4 + gID, r1 = r0 + 8;
            int tgt0 = text[r0 * NSTEP + s];
            int tgt1 = text[r1 * NSTEP + s];
            const float* e0 = g_Wemb + (size_t)tgt0 * GDIM;
            const float* e1 = g_Wemb + (size_t)tgt1 * GDIM;
#pragma unroll
            for (int nt = 0; nt < 2; nt++) {
                int cbase = n0 + wn4 + nt * 8 + 2 * tig;
                float2 w0 = *(const float2*)(e0 + cbase);
                float2 w1 = *(const float2*)(e1 + cbase);
                float2 o0 = make_float2(acc[nt][0] + w0.x, acc[nt][1] + w0.y);
                float2 o1 = make_float2(acc[nt][2] + w1.x, acc[nt][3] + w1.y);
                *(float2*)&g_gates[(size_t)r0 * GDIM + cbase] = o0;
                *(float2*)&g_gates[(size_t)r1 * GDIM + cbase] = o1;
            }
        }

        group_sync(grp);   // gates ready within group
    }

    // final LSTM -> hs[25]
    {
        const int r = tid >> 7, jb = tid & 127;
        const int row = b0 + r;
        const float* g = g_gates + (size_t)row * GDIM;
        const float* cp = g_c + (size_t)row * HSZ;
#pragma unroll
        for (int jj = 0; jj < 2; jj++) {
            int j = jb + (jj << 7);
            float ig = fast_sigmoid(g[j]);
            float fg = fast_sigmoid(g[j + 256]);
            float gg = tanh_fast(g[j + 512]);
            float og = fast_sigmoid(g[j + 768]);
            float cn = fg * cp[j] + ig * gg;
            float hn = og * tanh_fast(cn);
            g_hs_h[((size_t)row * NSTEP + (NSTEP - 1)) * HSZ + j] = __float2half_rn(hn);
        }
    }
}

// ------------------------- launch -------------------------------------------
extern "C" void kernel_launch(void* const* d_in, const int* in_sizes, int n_in,
                              void* d_out, int out_size) {
    const float* batch_H = (const float*)d_in[0];
    const int*   text    = (const int*)d_in[1];
    const float* W_i2h   = (const float*)d_in[3];
    const float* W_h2h   = (const float*)d_in[4];
    const float* b_h2h   = (const float*)d_in[5];
    const float* W_score = (const float*)d_in[6];
    const float* W_ih    = (const float*)d_in[7];
    const float* W_hh    = (const float*)d_in[8];
    const float* b_ih    = (const float*)d_in[9];
    const float* b_hh    = (const float*)d_in[10];
    const float* W_gen   = (const float*)d_in[11];
    const float* b_gen   = (const float*)d_in[12];
    float* out = (float*)d_out;

    uint8_t* projH_f8;
    __half *Wi2h_h, *Wgen_h, *hs_h;
    cudaGetSymbolAddress((void**)&projH_f8, g_projH_f8);
    cudaGetSymbolAddress((void**)&Wi2h_h,  g_Wi2h_h);
    cudaGetSymbolAddress((void**)&Wgen_h,  g_Wgen_h);
    cudaGetSymbolAddress((void**)&hs_h,    g_hs_h);

    static bool attr_set = false;
    if (!attr_set) {
        cudaFuncSetAttribute(persistent_steps,
                             cudaFuncAttributeMaxDynamicSharedMemorySize,
                             SMEM_BYTES);
        attr_set = true;
    }

    init_kernel<<<2048, 256>>>(W_ih, W_hh, b_ih, b_hh, W_i2h, W_h2h, W_gen);

    // proj_H = batch_H @ W_i2h^T -> e4m3 (+ batch_H e4m3 dump)
    hgemm2<0, 2, false, true><<<dim3(4, 512), 256>>>(
        batch_H, Wi2h_h, projH_f8, BSZ * TLEN, HSZ, ISZ, ISZ, ISZ, HSZ, nullptr);

    persistent_steps<<<NBLK, NTHR, SMEM_BYTES>>>(text, b_h2h, W_score);

    // logits = hs @ W_gen^T + b_gen, blank masked
    hgemm2<3, 0, true, false><<<dim3(2, 104), 256>>>(
        hs_h, Wgen_h, out, BSZ * NSTEP, NCLS, HSZ, HSZ, HSZ, NCLS, b_gen);
}

// round 9
// speedup vs baseline: 4.3078x; 1.0189x over previous
#include <cuda_runtime.h>
#include <cuda_fp16.h>
#include <cstdint>

#define BSZ   512
#define TLEN  128
#define ISZ   256
#define HSZ   256
#define NCLS  100
#define NSTEP 26
#define XDIM  512
#define GDIM  1024
#define WIH_LD 356
#define BLANK_ID 3
#define RPB   4
#define NBLK  128
#define GRPBLK 32
#define NTHR  512
#define XSTR  528            // gates smem row stride (bytes): conflict-free
#define TAIL_BYTES (2048 + 2048 + 512 + 1024 + 2048 + 2048)
#define SMEM_BYTES (2 * 64 * XSTR + TAIL_BYTES)

// ------------------------- device scratch -----------------------------------
__device__ uint8_t g_projH_f8[BSZ * TLEN * HSZ];
__device__ uint8_t g_batchH_f8[BSZ * TLEN * ISZ];
__device__ uint8_t g_X_f8[BSZ * XDIM];
__device__ float  g_gates[BSZ * GDIM];
__device__ float  g_c[BSZ * HSZ];
__device__ uint8_t g_hs_f8[BSZ * NSTEP * HSZ];
__device__ uint8_t g_Wcat_f8[GDIM * XDIM];     // x16 scaled
__device__ uint8_t g_Wi2h_f8[HSZ * ISZ];       // x16 scaled
__device__ uint8_t g_Wgen_f8[NCLS * HSZ];      // x16 scaled
__device__ __half g_Wh2hT_h[HSZ * HSZ];
__device__ float  g_Wemb[NCLS * GDIM];
__device__ unsigned g_count[4 * 32];
__device__ volatile unsigned g_epoch[4 * 32];

// ------------------------- fast math ----------------------------------------
__device__ __forceinline__ float tanh_fast(float x) {
    float y;
    asm("tanh.approx.f32 %0, %1;" : "=f"(y) : "f"(x));
    return y;
}
__device__ __forceinline__ float fast_sigmoid(float x) {
    return 0.5f * (1.0f + tanh_fast(0.5f * x));
}
__device__ __forceinline__ __half2 tanh2(__half2 x) {
    uint32_t xi = *(uint32_t*)&x, yo;
    asm("tanh.approx.f16x2 %0, %1;" : "=r"(yo) : "r"(xi));
    return *(__half2*)&yo;
}
__device__ __forceinline__ uint16_t h2_to_e4m3x2(__half2 h) {
    uint16_t r;
    asm("cvt.rn.satfinite.e4m3x2.f16x2 %0, %1;" : "=h"(r) : "r"(*(uint32_t*)&h));
    return r;
}
__device__ __forceinline__ __half2 e4m3x2_to_h2(uint16_t b) {
    uint32_t r;
    asm("cvt.rn.f16x2.e4m3x2 %0, %1;" : "=r"(r) : "h"(b));
    return *(__half2*)&r;
}
__device__ __forceinline__ uint8_t f32_to_e4m3(float v) {
    return (uint8_t)h2_to_e4m3x2(__floats2half2_rn(v, v));
}
__device__ __forceinline__ uint32_t pack_e4m3x4(float a, float b, float c, float d) {
    return (uint32_t)h2_to_e4m3x2(__floats2half2_rn(a, b)) |
           ((uint32_t)h2_to_e4m3x2(__floats2half2_rn(c, d)) << 16);
}
#define MMA_E4M3(acc, a0, a1, a2, a3, b0, b1)                                  \
    asm volatile(                                                              \
        "mma.sync.aligned.m16n8k32.row.col.f32.e4m3.e4m3.f32 "                 \
        "{%0,%1,%2,%3}, {%4,%5,%6,%7}, {%8,%9}, {%0,%1,%2,%3};"                \
        : "+f"(acc[0]), "+f"(acc[1]), "+f"(acc[2]), "+f"(acc[3])               \
        : "r"(a0), "r"(a1), "r"(a2), "r"(a3), "r"(b0), "r"(b1))

// ------------------------- group barrier (32 blocks) -------------------------
__device__ __forceinline__ void group_sync(int g) {
    __syncthreads();
    if (threadIdx.x == 0) {
        const int slot = g * 32;
        unsigned my = g_epoch[slot];
        __threadfence();
        unsigned old = atomicAdd(&g_count[slot], 1u);
        if (old == GRPBLK - 1) {
            g_count[slot] = 0;
            __threadfence();
            g_epoch[slot] = my + 1;
        } else {
            while (g_epoch[slot] == my) { __nanosleep(16); }
            __threadfence();
        }
    }
    __syncthreads();
}

// ------------------------- init ----------------------------------------------
__global__ void init_kernel(const float* __restrict__ W_ih,
                            const float* __restrict__ W_hh,
                            const float* __restrict__ b_ih,
                            const float* __restrict__ b_hh,
                            const float* __restrict__ W_i2h,
                            const float* __restrict__ W_h2h,
                            const float* __restrict__ W_gen) {
    int idx = blockIdx.x * 256 + threadIdx.x;
    if (idx < GDIM * XDIM) {
        int j = idx >> 9, k = idx & 511;
        float v = (k < 256) ? W_ih[j * WIH_LD + k] : W_hh[j * 256 + (k - 256)];
        g_Wcat_f8[idx] = f32_to_e4m3(v * 16.0f);
    }
    if (idx < HSZ * HSZ) {
        int j = idx >> 8, k = idx & 255;
        g_Wh2hT_h[k * HSZ + j] = __float2half_rn(W_h2h[idx]);
        g_Wi2h_f8[idx] = f32_to_e4m3(W_i2h[idx] * 16.0f);
    }
    if (idx < NCLS * HSZ) g_Wgen_f8[idx] = f32_to_e4m3(W_gen[idx] * 16.0f);
    if (idx < NCLS * GDIM) {
        int cls = idx >> 10, c = idx & 1023;
        g_Wemb[idx] = W_ih[(size_t)c * WIH_LD + 256 + cls] + b_ih[c] + b_hh[c];
    }
    if (idx < BSZ * HSZ) g_c[idx] = 0.0f;
}

// ------------------------- e4m3 MMA GEMM, tile 128x64  C = (A*B^T)/16 -------
// A [M,K] bytes or fp32 (A_FP32), B [N,K] e4m3 x16-scaled. K multiple of 64.
// MODE 0: plain -> e4m3 out   MODE 3: +bias, blank := -10000 -> fp32 out
template <int MODE, bool A_FP32, bool DUMP>
__global__ __launch_bounds__(256) void qgemm(
    const void* __restrict__ Aptr, const uint8_t* __restrict__ Bw,
    void* __restrict__ Cm,
    int M, int N, int K, int lda, int ldb, int ldc,
    const float* __restrict__ bias) {

    __shared__ uint8_t As[128 * 80];
    __shared__ uint8_t Bs[64 * 80];

    const int m0 = blockIdx.y * 128, n0 = blockIdx.x * 64;
    const int tid = threadIdx.x, lane = tid & 31, warp = tid >> 5;
    const int wm = (warp >> 1) * 32, wn = (warp & 1) * 32;
    const int gID = lane >> 2, tig = lane & 3;
    const int ar = tid >> 1, aoff = (tid & 1) << 5;   // 2 thr/row, 32B each
    const int br = tid >> 2, boff = (tid & 3) << 4;   // 4 thr/row, 16B each

    float acc[2][4][4];
#pragma unroll
    for (int mf = 0; mf < 2; mf++)
#pragma unroll
        for (int i = 0; i < 4; i++)
#pragma unroll
            for (int j = 0; j < 4; j++) acc[mf][i][j] = 0.0f;

    auto loadA = [&](int k0, uint4& o0, uint4& o1) {
        if (A_FP32) {
            const float* A = (const float*)Aptr;
            const float* p = A + (size_t)(m0 + ar) * lda + k0 + aoff;
            float4 f[8];
#pragma unroll
            for (int q = 0; q < 8; q++) f[q] = *(const float4*)(p + q * 4);
            o0.x = pack_e4m3x4(f[0].x, f[0].y, f[0].z, f[0].w);
            o0.y = pack_e4m3x4(f[1].x, f[1].y, f[1].z, f[1].w);
            o0.z = pack_e4m3x4(f[2].x, f[2].y, f[2].z, f[2].w);
            o0.w = pack_e4m3x4(f[3].x, f[3].y, f[3].z, f[3].w);
            o1.x = pack_e4m3x4(f[4].x, f[4].y, f[4].z, f[4].w);
            o1.y = pack_e4m3x4(f[5].x, f[5].y, f[5].z, f[5].w);
            o1.z = pack_e4m3x4(f[6].x, f[6].y, f[6].z, f[6].w);
            o1.w = pack_e4m3x4(f[7].x, f[7].y, f[7].z, f[7].w);
        } else {
            const uint8_t* A = (const uint8_t*)Aptr;
            const uint8_t* p = A + (size_t)(m0 + ar) * lda + k0 + aoff;
            o0 = *(const uint4*)p;
            o1 = *(const uint4*)(p + 16);
        }
    };
    auto loadB = [&](int k0) -> uint4 {
        if (n0 + br < N)
            return *(const uint4*)(Bw + (size_t)(n0 + br) * ldb + k0 + boff);
        return make_uint4(0u, 0u, 0u, 0u);
    };

    uint4 a0R, a1R, bR;
    loadA(0, a0R, a1R);
    bR = loadB(0);
    const int iters = K >> 6;

    for (int it = 0; it < iters; it++) {
        __syncthreads();
        *(uint4*)&As[ar * 80 + aoff] = a0R;
        *(uint4*)&As[ar * 80 + aoff + 16] = a1R;
        *(uint4*)&Bs[br * 80 + boff] = bR;
        if (DUMP && blockIdx.x == 0) {
            uint8_t* d = g_batchH_f8 + (size_t)(m0 + ar) * ISZ + it * 64 + aoff;
            *(uint4*)d = a0R;
            *(uint4*)(d + 16) = a1R;
        }
        __syncthreads();
        if (it + 1 < iters) {
            loadA((it + 1) << 6, a0R, a1R);
            bR = loadB((it + 1) << 6);
        }
#pragma unroll
        for (int kk = 0; kk < 64; kk += 32) {
            uint32_t af[2][4];
#pragma unroll
            for (int mf = 0; mf < 2; mf++) {
                int rb = wm + mf * 16 + gID;
                af[mf][0] = *(uint32_t*)&As[rb * 80 + kk + tig * 4];
                af[mf][1] = *(uint32_t*)&As[(rb + 8) * 80 + kk + tig * 4];
                af[mf][2] = *(uint32_t*)&As[rb * 80 + kk + 16 + tig * 4];
                af[mf][3] = *(uint32_t*)&As[(rb + 8) * 80 + kk + 16 + tig * 4];
            }
#pragma unroll
            for (int nt = 0; nt < 4; nt++) {
                uint32_t b0 = *(uint32_t*)&Bs[(wn + nt * 8 + gID) * 80 + kk + tig * 4];
                uint32_t b1 = *(uint32_t*)&Bs[(wn + nt * 8 + gID) * 80 + kk + 16 + tig * 4];
#pragma unroll
                for (int mf = 0; mf < 2; mf++)
                    MMA_E4M3(acc[mf][nt], af[mf][0], af[mf][1], af[mf][2],
                             af[mf][3], b0, b1);
            }
        }
    }

    const float sc = 1.0f / 16.0f;
#pragma unroll
    for (int mf = 0; mf < 2; mf++) {
        const int r0 = m0 + wm + mf * 16 + gID, r1 = r0 + 8;
#pragma unroll
        for (int nt = 0; nt < 4; nt++) {
            int cb = n0 + wn + nt * 8 + 2 * tig;
#pragma unroll
            for (int hr = 0; hr < 2; hr++) {
                int r = hr ? r1 : r0;
                if (r >= M || cb >= N) continue;
                float v0 = acc[mf][nt][hr * 2 + 0] * sc;
                float v1 = acc[mf][nt][hr * 2 + 1] * sc;
                if (MODE == 3) {
                    v0 += bias[cb];
                    v1 += bias[cb + 1];
                    if (cb == BLANK_ID) v0 = -10000.0f;
                    if (cb + 1 == BLANK_ID) v1 = -10000.0f;
                    *(float2*)((float*)Cm + (size_t)r * ldc + cb) =
                        make_float2(v0, v1);
                } else {
                    *(uint16_t*)((uint8_t*)Cm + (size_t)r * ldc + cb) =
                        h2_to_e4m3x2(__floats2half2_rn(v0, v1));
                }
            }
        }
    }
}

// ------------------------- persistent 26-step kernel (512 thr) ---------------
__global__ __launch_bounds__(NTHR, 1) void persistent_steps(
    const int* __restrict__ text, const float* __restrict__ b_h2h,
    const float* __restrict__ wscore) {

    extern __shared__ char dyn[];
    uint8_t* Bs8 = (uint8_t*)dyn;                       // [64][XSTR]
    uint8_t* As8 = Bs8 + 64 * XSTR;                     // [64][XSTR] (phase B)
    __half2* redh = (__half2*)As8;                      // [16][4][128] overlay
    char* tail = dyn + 2 * 64 * XSTR;
    __half*  sh   = (__half*)tail;                      // [4][256]
    __half*  sp_h = sh + 1024;                          // [4][256]
    __half*  sw_h = sp_h + 1024;                        // [256]
    float*   sb   = (float*)(sw_h + 256);               // [256]
    float*   se   = sb + 256;                           // [4][128]
    __half2* seh  = (__half2*)(se + 512);               // [4][128]

    const int tid = threadIdx.x, lane = tid & 31, warp = tid >> 5;
    const int bid = blockIdx.x;
    const int grp = bid >> 5;
    const int lid = bid & 31;
    const int b0 = bid * RPB;
    const int m0 = grp * 128 + (lid >> 4) * 64;
    const int n0 = (lid & 15) * 64;
    const int wm4 = (warp >> 2) * 16, wn4 = (warp & 3) * 16;
    const int gID = lane >> 2, tig = lane & 3;

    if (tid < 256) {
        sw_h[tid] = __float2half_rn(wscore[tid]);
        sb[tid] = b_h2h[tid];
    }

    // preload Wcat_f8 B-slab once: 64 rows x 512 B
#pragma unroll
    for (int i = 0; i < 4; i++) {
        int linear = tid + (i << 9);
        int row = linear >> 5, c16 = (linear & 31) << 4;
        *(uint4*)&Bs8[row * XSTR + c16] =
            *(const uint4*)(g_Wcat_f8 + ((size_t)(n0 + row)) * XDIM + c16);
    }
    __syncthreads();

    __half2 swl2[4];
    {
        uint4 v = *(const uint4*)(sw_h + lane * 8);
        swl2[0] = *(__half2*)&v.x; swl2[1] = *(__half2*)&v.y;
        swl2[2] = *(__half2*)&v.z; swl2[3] = *(__half2*)&v.w;
    }

    for (int s = 0; s < NSTEP; s++) {
        // ==== LSTM(s-1) -> h ====
        {
            const int r = tid >> 7, jb = tid & 127;
            const int row = b0 + r;
            if (s > 0) {
                const float* g = g_gates + (size_t)row * GDIM;
                float* cp = g_c + (size_t)row * HSZ;
#pragma unroll
                for (int jj = 0; jj < 2; jj++) {
                    int j = jb + (jj << 7);
                    float ig = fast_sigmoid(g[j]);
                    float fg = fast_sigmoid(g[j + 256]);
                    float gg = tanh_fast(g[j + 512]);
                    float og = fast_sigmoid(g[j + 768]);
                    float cn = fg * cp[j] + ig * gg;
                    float hn = og * tanh_fast(cn);
                    cp[j] = cn;
                    sh[r * HSZ + j] = __float2half_rn(hn);
                    uint8_t hb = f32_to_e4m3(hn);
                    g_X_f8[(size_t)row * XDIM + 256 + j] = hb;
                    g_hs_f8[((size_t)row * NSTEP + (s - 1)) * HSZ + j] = hb;
                }
            } else {
                __half z = __float2half_rn(0.0f);
#pragma unroll
                for (int jj = 0; jj < 2; jj++) {
                    int j = jb + (jj << 7);
                    sh[r * HSZ + j] = z;
                    g_X_f8[(size_t)row * XDIM + 256 + j] = 0;
                }
            }
        }
        __syncthreads();

        // ==== projh partials: warp w covers k in [w*16, +16) ====
        {
            const int kb = warp << 4;
            __half2 acc2[RPB][4];
#pragma unroll
            for (int r = 0; r < RPB; r++)
#pragma unroll
                for (int p = 0; p < 4; p++)
                    acc2[r][p] = __floats2half2_rn(0.f, 0.f);

            const __half* WT = g_Wh2hT_h + (size_t)kb * HSZ + lane * 8;
#pragma unroll 4
            for (int k = 0; k < 16; k++) {
                uint4 wv = *(const uint4*)(WT + k * HSZ);
                __half2 wh[4];
                wh[0] = *(__half2*)&wv.x; wh[1] = *(__half2*)&wv.y;
                wh[2] = *(__half2*)&wv.z; wh[3] = *(__half2*)&wv.w;
#pragma unroll
                for (int r = 0; r < RPB; r++) {
                    __half2 hk2 = __half2half2(sh[r * HSZ + kb + k]);
#pragma unroll
                    for (int p = 0; p < 4; p++)
                        acc2[r][p] = __hfma2(wh[p], hk2, acc2[r][p]);
                }
            }
#pragma unroll
            for (int r = 0; r < RPB; r++)
#pragma unroll
                for (int p = 0; p < 4; p++)
                    redh[((warp * RPB + r) << 7) + lane * 4 + p] = acc2[r][p];
        }
        __syncthreads();

        // ==== reduce 16 partials -> sp_h ====
        {
            const int r = tid >> 7, j2 = tid & 127;
            float2 sum = make_float2(0.f, 0.f);
#pragma unroll
            for (int w = 0; w < 16; w++) {
                float2 v = __half22float2(redh[(((w * RPB + r)) << 7) + j2]);
                sum.x += v.x; sum.y += v.y;
            }
            float2 bv = *(const float2*)&sb[j2 * 2];
            *(__half2*)&sp_h[r * HSZ + j2 * 2] =
                __floats2half2_rn(sum.x + bv.x, sum.y + bv.y);
        }
        __syncthreads();

        // ==== scores: 4 warps per row, 32 t each, fp8 projH ====
        {
            const int r = warp >> 2;
            const int tb = (warp & 3) << 5;
            __half2 spl2[4];
            {
                uint4 v = *(const uint4*)(sp_h + r * HSZ + lane * 8);
                spl2[0] = *(__half2*)&v.x; spl2[1] = *(__half2*)&v.y;
                spl2[2] = *(__half2*)&v.z; spl2[3] = *(__half2*)&v.w;
            }
            const uint8_t* pH = g_projH_f8 + ((size_t)(b0 + r) * TLEN + tb) * HSZ + lane * 8;
            for (int t = 0; t < 32; t += 8) {
                uint2 v[8];
#pragma unroll
                for (int u = 0; u < 8; u++)
                    v[u] = *(const uint2*)(pH + (t + u) * HSZ);
                float ac[8];
#pragma unroll
                for (int u = 0; u < 8; u++) {
                    __half2 d0 = e4m3x2_to_h2((uint16_t)(v[u].x & 0xffffu));
                    __half2 d1 = e4m3x2_to_h2((uint16_t)(v[u].x >> 16));
                    __half2 d2 = e4m3x2_to_h2((uint16_t)(v[u].y & 0xffffu));
                    __half2 d3 = e4m3x2_to_h2((uint16_t)(v[u].y >> 16));
                    __half2 prod = __floats2half2_rn(0.f, 0.f);
                    prod = __hfma2(swl2[0], tanh2(__hadd2(d0, spl2[0])), prod);
                    prod = __hfma2(swl2[1], tanh2(__hadd2(d1, spl2[1])), prod);
                    prod = __hfma2(swl2[2], tanh2(__hadd2(d2, spl2[2])), prod);
                    prod = __hfma2(swl2[3], tanh2(__hadd2(d3, spl2[3])), prod);
                    float2 f = __half22float2(prod);
                    ac[u] = f.x + f.y;
                }
#pragma unroll
                for (int u = 0; u < 8; u++) {
#pragma unroll
                    for (int o = 16; o; o >>= 1)
                        ac[u] += __shfl_xor_sync(0xffffffffu, ac[u], o);
                    if (lane == 0) se[r * TLEN + tb + t + u] = ac[u];
                }
            }
        }
        __syncthreads();

        // ==== softmax -> seh (warps 0..3) ====
        if (warp < RPB) {
            const float* sr = se + warp * TLEN;
            float v0 = sr[lane], v1 = sr[lane + 32];
            float v2 = sr[lane + 64], v3 = sr[lane + 96];
            float mx = fmaxf(fmaxf(v0, v1), fmaxf(v2, v3));
#pragma unroll
            for (int o = 16; o; o >>= 1) mx = fmaxf(mx, __shfl_xor_sync(0xffffffffu, mx, o));
            float e0 = __expf(v0 - mx), e1 = __expf(v1 - mx);
            float e2 = __expf(v2 - mx), e3 = __expf(v3 - mx);
            float sum = e0 + e1 + e2 + e3;
#pragma unroll
            for (int o = 16; o; o >>= 1) sum += __shfl_xor_sync(0xffffffffu, sum, o);
            float inv = 1.0f / sum;
            __half2* dr = seh + warp * TLEN;
            dr[lane]      = __float2half2_rn(e0 * inv);
            dr[lane + 32] = __float2half2_rn(e1 * inv);
            dr[lane + 64] = __float2half2_rn(e2 * inv);
            dr[lane + 96] = __float2half2_rn(e3 * inv);
        }
        __syncthreads();

        // ==== context: thread owns (r, 2 i's), fp8 batchH -> X e4m3 ====
        {
            const int r = tid >> 7, ci = tid & 127;
            const uint8_t* bH = g_batchH_f8 + (size_t)(b0 + r) * TLEN * ISZ + ci * 2;
            const __half2* al = seh + r * TLEN;
            __half2 a0 = __floats2half2_rn(0.f, 0.f);
#pragma unroll 8
            for (int t = 0; t < TLEN; t++) {
                uint16_t us = *(const uint16_t*)(bH + t * ISZ);
                a0 = __hfma2(al[t], e4m3x2_to_h2(us), a0);
            }
            *(uint16_t*)(g_X_f8 + (size_t)(b0 + r) * XDIM + ci * 2) =
                h2_to_e4m3x2(a0);
        }

        group_sync(grp);   // X ready within group

        // ==== gates tile = (X[m0:+64] @ Wcat[n0:+64]^T)/16, e4m3 MMA ====
        {
#pragma unroll
            for (int i = 0; i < 4; i++) {
                int linear = tid + (i << 9);
                int row = linear >> 5, c16 = (linear & 31) << 4;
                *(uint4*)&As8[row * XSTR + c16] =
                    *(const uint4*)(g_X_f8 + ((size_t)(m0 + row)) * XDIM + c16);
            }
            __syncthreads();

            float acc[2][4];
#pragma unroll
            for (int i = 0; i < 2; i++)
#pragma unroll
                for (int j = 0; j < 4; j++) acc[i][j] = 0.0f;

#pragma unroll 4
            for (int kk = 0; kk < 512; kk += 32) {
                uint32_t a0 = *(uint32_t*)&As8[(wm4 + gID) * XSTR + kk + tig * 4];
                uint32_t a1 = *(uint32_t*)&As8[(wm4 + gID + 8) * XSTR + kk + tig * 4];
                uint32_t a2 = *(uint32_t*)&As8[(wm4 + gID) * XSTR + kk + 16 + tig * 4];
                uint32_t a3 = *(uint32_t*)&As8[(wm4 + gID + 8) * XSTR + kk + 16 + tig * 4];
#pragma unroll
                for (int nt = 0; nt < 2; nt++) {
                    uint32_t b0 = *(uint32_t*)&Bs8[(wn4 + nt * 8 + gID) * XSTR + kk + tig * 4];
                    uint32_t b1 = *(uint32_t*)&Bs8[(wn4 + nt * 8 + gID) * XSTR + kk + 16 + tig * 4];
                    MMA_E4M3(acc[nt], a0, a1, a2, a3, b0, b1);
                }
            }

            const int r0 = m0 + wm4 + gID, r1 = r0 + 8;
            int tgt0 = text[r0 * NSTEP + s];
            int tgt1 = text[r1 * NSTEP + s];
            const float* e0 = g_Wemb + (size_t)tgt0 * GDIM;
            const float* e1 = g_Wemb + (size_t)tgt1 * GDIM;
            const float sc = 1.0f / 16.0f;
#pragma unroll
            for (int nt = 0; nt < 2; nt++) {
                int cbase = n0 + wn4 + nt * 8 + 2 * tig;
                float2 w0 = *(const float2*)(e0 + cbase);
                float2 w1 = *(const float2*)(e1 + cbase);
                float2 o0 = make_float2(acc[nt][0] * sc + w0.x, acc[nt][1] * sc + w0.y);
                float2 o1 = make_float2(acc[nt][2] * sc + w1.x, acc[nt][3] * sc + w1.y);
                *(float2*)&g_gates[(size_t)r0 * GDIM + cbase] = o0;
                *(float2*)&g_gates[(size_t)r1 * GDIM + cbase] = o1;
            }
        }

        group_sync(grp);   // gates ready within group
    }

    // final LSTM -> hs[25]
    {
        const int r = tid >> 7, jb = tid & 127;
        const int row = b0 + r;
        const float* g = g_gates + (size_t)row * GDIM;
        const float* cp = g_c + (size_t)row * HSZ;
#pragma unroll
        for (int jj = 0; jj < 2; jj++) {
            int j = jb + (jj << 7);
            float ig = fast_sigmoid(g[j]);
            float fg = fast_sigmoid(g[j + 256]);
            float gg = tanh_fast(g[j + 512]);
            float og = fast_sigmoid(g[j + 768]);
            float cn = fg * cp[j] + ig * gg;
            float hn = og * tanh_fast(cn);
            g_hs_f8[((size_t)row * NSTEP + (NSTEP - 1)) * HSZ + j] = f32_to_e4m3(hn);
        }
    }
}

// ------------------------- launch -------------------------------------------
extern "C" void kernel_launch(void* const* d_in, const int* in_sizes, int n_in,
                              void* d_out, int out_size) {
    const float* batch_H = (const float*)d_in[0];
    const int*   text    = (const int*)d_in[1];
    const float* W_i2h   = (const float*)d_in[3];
    const float* W_h2h   = (const float*)d_in[4];
    const float* b_h2h   = (const float*)d_in[5];
    const float* W_score = (const float*)d_in[6];
    const float* W_ih    = (const float*)d_in[7];
    const float* W_hh    = (const float*)d_in[8];
    const float* b_ih    = (const float*)d_in[9];
    const float* b_hh    = (const float*)d_in[10];
    const float* W_gen   = (const float*)d_in[11];
    const float* b_gen   = (const float*)d_in[12];
    float* out = (float*)d_out;

    uint8_t *projH_f8, *Wi2h_f8, *Wgen_f8, *hs_f8;
    cudaGetSymbolAddress((void**)&projH_f8, g_projH_f8);
    cudaGetSymbolAddress((void**)&Wi2h_f8,  g_Wi2h_f8);
    cudaGetSymbolAddress((void**)&Wgen_f8,  g_Wgen_f8);
    cudaGetSymbolAddress((void**)&hs_f8,    g_hs_f8);

    static bool attr_set = false;
    if (!attr_set) {
        cudaFuncSetAttribute(persistent_steps,
                             cudaFuncAttributeMaxDynamicSharedMemorySize,
                             SMEM_BYTES);
        attr_set = true;
    }

    init_kernel<<<2048, 256>>>(W_ih, W_hh, b_ih, b_hh, W_i2h, W_h2h, W_gen);

    // proj_H = (batch_H @ (16*W_i2h)^T)/16 -> e4m3 (+ batch_H e4m3 dump)
    qgemm<0, true, true><<<dim3(4, 512), 256>>>(
        batch_H, Wi2h_f8, projH_f8, BSZ * TLEN, HSZ, ISZ, ISZ, ISZ, HSZ, nullptr);

    persistent_steps<<<NBLK, NTHR, SMEM_BYTES>>>(text, b_h2h, W_score);

    // logits = (hs @ (16*W_gen)^T)/16 + b_gen, blank masked
    qgemm<3, false, false><<<dim3(2, 104), 256>>>(
        hs_f8, Wgen_f8, out, BSZ * NSTEP, NCLS, HSZ, HSZ, HSZ, NCLS, b_gen);
}

// round 11
// speedup vs baseline: 4.8968x; 1.1367x over previous
#include <cuda_runtime.h>
#include <cuda_fp16.h>
#include <cstdint>

#define BSZ   512
#define TLEN  128
#define ISZ   256
#define HSZ   256
#define NCLS  100
#define NSTEP 26
#define XDIM  512
#define GDIM  1024
#define WIH_LD 356
#define BLANK_ID 3
#define RPB   4
#define NBLK  128
#define GRPBLK 32
#define NTHR  512
#define XSTR  528            // gates smem slab row stride (bytes), 16-aligned
#define PHSTR 272            // projH smem row stride (bytes), 16-aligned
#define WISTR 264            // Wi2h staging stride (bytes), 8-aligned ONLY
#define TAIL_BYTES (2048 + 2048 + 512 + 1024 + 2048 + 2048)
#define SMEM_BYTES (512 * PHSTR + 2 * 64 * XSTR + TAIL_BYTES)   // 216576

// ------------------------- device scratch -----------------------------------
__device__ uint8_t g_batchH_f8[BSZ * TLEN * ISZ];
__device__ uint8_t g_X_f8[BSZ * XDIM];
__device__ float  g_gates[BSZ * GDIM];
__device__ float  g_c[BSZ * HSZ];
__device__ uint8_t g_hs_f8[BSZ * NSTEP * HSZ];
__device__ uint8_t g_Wcat_f8[GDIM * XDIM];     // x16 scaled
__device__ uint8_t g_Wi2h_f8[HSZ * ISZ];       // x16 scaled
__device__ uint8_t g_Wgen_f8[NCLS * HSZ];      // x16 scaled
__device__ __half g_Wh2hT_h[HSZ * HSZ];
__device__ float  g_Wemb[NCLS * GDIM];
__device__ unsigned g_count[4 * 32];
__device__ volatile unsigned g_epoch[4 * 32];

// ------------------------- fast math ----------------------------------------
__device__ __forceinline__ float tanh_fast(float x) {
    float y;
    asm("tanh.approx.f32 %0, %1;" : "=f"(y) : "f"(x));
    return y;
}
__device__ __forceinline__ float fast_sigmoid(float x) {
    return 0.5f * (1.0f + tanh_fast(0.5f * x));
}
__device__ __forceinline__ __half2 tanh2(__half2 x) {
    uint32_t xi = *(uint32_t*)&x, yo;
    asm("tanh.approx.f16x2 %0, %1;" : "=r"(yo) : "r"(xi));
    return *(__half2*)&yo;
}
__device__ __forceinline__ uint16_t h2_to_e4m3x2(__half2 h) {
    uint16_t r;
    asm("cvt.rn.satfinite.e4m3x2.f16x2 %0, %1;" : "=h"(r) : "r"(*(uint32_t*)&h));
    return r;
}
__device__ __forceinline__ __half2 e4m3x2_to_h2(uint16_t b) {
    uint32_t r;
    asm("cvt.rn.f16x2.e4m3x2 %0, %1;" : "=r"(r) : "h"(b));
    return *(__half2*)&r;
}
__device__ __forceinline__ uint8_t f32_to_e4m3(float v) {
    return (uint8_t)h2_to_e4m3x2(__floats2half2_rn(v, v));
}
__device__ __forceinline__ uint32_t pack_e4m3x4(float a, float b, float c, float d) {
    return (uint32_t)h2_to_e4m3x2(__floats2half2_rn(a, b)) |
           ((uint32_t)h2_to_e4m3x2(__floats2half2_rn(c, d)) << 16);
}
#define MMA_E4M3(acc, a0, a1, a2, a3, b0, b1)                                  \
    asm volatile(                                                              \
        "mma.sync.aligned.m16n8k32.row.col.f32.e4m3.e4m3.f32 "                 \
        "{%0,%1,%2,%3}, {%4,%5,%6,%7}, {%8,%9}, {%0,%1,%2,%3};"                \
        : "+f"(acc[0]), "+f"(acc[1]), "+f"(acc[2]), "+f"(acc[3])               \
        : "r"(a0), "r"(a1), "r"(a2), "r"(a3), "r"(b0), "r"(b1))

// ------------------------- group barrier (32 blocks) -------------------------
__device__ __forceinline__ void group_sync(int g) {
    __syncthreads();
    if (threadIdx.x == 0) {
        const int slot = g * 32;
        unsigned my = g_epoch[slot];
        __threadfence();
        unsigned old = atomicAdd(&g_count[slot], 1u);
        if (old == GRPBLK - 1) {
            g_count[slot] = 0;
            __threadfence();
            g_epoch[slot] = my + 1;
        } else {
            while (g_epoch[slot] == my) { __nanosleep(16); }
            __threadfence();
        }
    }
    __syncthreads();
}

// ------------------------- init ----------------------------------------------
__global__ void init_kernel(const float* __restrict__ W_ih,
                            const float* __restrict__ W_hh,
                            const float* __restrict__ b_ih,
                            const float* __restrict__ b_hh,
                            const float* __restrict__ W_i2h,
                            const float* __restrict__ W_h2h,
                            const float* __restrict__ W_gen) {
    int idx = blockIdx.x * 256 + threadIdx.x;
    if (idx < GDIM * XDIM) {
        int j = idx >> 9, k = idx & 511;
        float v = (k < 256) ? W_ih[j * WIH_LD + k] : W_hh[j * 256 + (k - 256)];
        g_Wcat_f8[idx] = f32_to_e4m3(v * 16.0f);
    }
    if (idx < HSZ * HSZ) {
        int j = idx >> 8, k = idx & 255;
        g_Wh2hT_h[k * HSZ + j] = __float2half_rn(W_h2h[idx]);
        g_Wi2h_f8[idx] = f32_to_e4m3(W_i2h[idx] * 16.0f);
    }
    if (idx < NCLS * HSZ) g_Wgen_f8[idx] = f32_to_e4m3(W_gen[idx] * 16.0f);
    if (idx < NCLS * GDIM) {
        int cls = idx >> 10, c = idx & 1023;
        g_Wemb[idx] = W_ih[(size_t)c * WIH_LD + 256 + cls] + b_ih[c] + b_hh[c];
    }
    if (idx < BSZ * HSZ) g_c[idx] = 0.0f;
}

// ------------------------- e4m3 MMA GEMM (logits), tile 128x64 ---------------
__global__ __launch_bounds__(256) void qgemm_logits(
    const uint8_t* __restrict__ Aptr, const uint8_t* __restrict__ Bw,
    float* __restrict__ Cm,
    int M, int N, int K, int lda, int ldb, int ldc,
    const float* __restrict__ bias) {

    __shared__ uint8_t As[128 * 80];
    __shared__ uint8_t Bs[64 * 80];

    const int m0 = blockIdx.y * 128, n0 = blockIdx.x * 64;
    const int tid = threadIdx.x, lane = tid & 31, warp = tid >> 5;
    const int wm = (warp >> 1) * 32, wn = (warp & 1) * 32;
    const int gID = lane >> 2, tig = lane & 3;
    const int ar = tid >> 1, aoff = (tid & 1) << 5;
    const int br = tid >> 2, boff = (tid & 3) << 4;

    float acc[2][4][4];
#pragma unroll
    for (int mf = 0; mf < 2; mf++)
#pragma unroll
        for (int i = 0; i < 4; i++)
#pragma unroll
            for (int j = 0; j < 4; j++) acc[mf][i][j] = 0.0f;

    auto loadA = [&](int k0, uint4& o0, uint4& o1) {
        const uint8_t* p = Aptr + (size_t)(m0 + ar) * lda + k0 + aoff;
        o0 = *(const uint4*)p;
        o1 = *(const uint4*)(p + 16);
    };
    auto loadB = [&](int k0) -> uint4 {
        if (n0 + br < N)
            return *(const uint4*)(Bw + (size_t)(n0 + br) * ldb + k0 + boff);
        return make_uint4(0u, 0u, 0u, 0u);
    };

    uint4 a0R, a1R, bR;
    loadA(0, a0R, a1R);
    bR = loadB(0);
    const int iters = K >> 6;

    for (int it = 0; it < iters; it++) {
        __syncthreads();
        *(uint4*)&As[ar * 80 + aoff] = a0R;
        *(uint4*)&As[ar * 80 + aoff + 16] = a1R;
        *(uint4*)&Bs[br * 80 + boff] = bR;
        __syncthreads();
        if (it + 1 < iters) {
            loadA((it + 1) << 6, a0R, a1R);
            bR = loadB((it + 1) << 6);
        }
#pragma unroll
        for (int kk = 0; kk < 64; kk += 32) {
            uint32_t af[2][4];
#pragma unroll
            for (int mf = 0; mf < 2; mf++) {
                int rb = wm + mf * 16 + gID;
                af[mf][0] = *(uint32_t*)&As[rb * 80 + kk + tig * 4];
                af[mf][1] = *(uint32_t*)&As[(rb + 8) * 80 + kk + tig * 4];
                af[mf][2] = *(uint32_t*)&As[rb * 80 + kk + 16 + tig * 4];
                af[mf][3] = *(uint32_t*)&As[(rb + 8) * 80 + kk + 16 + tig * 4];
            }
#pragma unroll
            for (int nt = 0; nt < 4; nt++) {
                uint32_t b0 = *(uint32_t*)&Bs[(wn + nt * 8 + gID) * 80 + kk + tig * 4];
                uint32_t b1 = *(uint32_t*)&Bs[(wn + nt * 8 + gID) * 80 + kk + 16 + tig * 4];
#pragma unroll
                for (int mf = 0; mf < 2; mf++)
                    MMA_E4M3(acc[mf][nt], af[mf][0], af[mf][1], af[mf][2],
                             af[mf][3], b0, b1);
            }
        }
    }

    const float sc = 1.0f / 16.0f;
#pragma unroll
    for (int mf = 0; mf < 2; mf++) {
        const int r0 = m0 + wm + mf * 16 + gID, r1 = r0 + 8;
#pragma unroll
        for (int nt = 0; nt < 4; nt++) {
            int cb = n0 + wn + nt * 8 + 2 * tig;
#pragma unroll
            for (int hr = 0; hr < 2; hr++) {
                int r = hr ? r1 : r0;
                if (r >= M || cb >= N) continue;
                float v0 = acc[mf][nt][hr * 2 + 0] * sc + bias[cb];
                float v1 = acc[mf][nt][hr * 2 + 1] * sc + bias[cb + 1];
                if (cb == BLANK_ID) v0 = -10000.0f;
                if (cb + 1 == BLANK_ID) v1 = -10000.0f;
                *(float2*)(Cm + (size_t)r * ldc + cb) = make_float2(v0, v1);
            }
        }
    }
}

// ------------------------- persistent kernel: prolog + 26 steps --------------
__global__ __launch_bounds__(NTHR, 1) void persistent_steps(
    const float* __restrict__ batch_H, const int* __restrict__ text,
    const float* __restrict__ b_h2h, const float* __restrict__ wscore) {

    extern __shared__ char dyn[];
    uint8_t* sPH = (uint8_t*)dyn;                       // [512][PHSTR]
    uint8_t* Bs8 = sPH + 512 * PHSTR;                   // [64][XSTR]
    uint8_t* As8 = Bs8 + 64 * XSTR;                     // [64][XSTR]
    __half2* redh = (__half2*)As8;                      // overlay (phase A)
    char* tail = (char*)(As8 + 64 * XSTR);
    __half*  sh   = (__half*)tail;                      // [4][256]
    __half*  sp_h = sh + 1024;                          // [4][256]
    __half*  sw_h = sp_h + 1024;                        // [256]
    float*   sb   = (float*)(sw_h + 256);               // [256]
    float*   se   = sb + 256;                           // [4][128]
    __half2* seh  = (__half2*)(se + 512);               // [4][128]

    const int tid = threadIdx.x, lane = tid & 31, warp = tid >> 5;
    const int bid = blockIdx.x;
    const int grp = bid >> 5;
    const int lid = bid & 31;
    const int b0 = bid * RPB;
    const int m0 = grp * 128 + (lid >> 4) * 64;
    const int n0 = (lid & 15) * 64;
    const int wm4 = (warp >> 2) * 16, wn4 = (warp & 3) * 16;
    const int gID = lane >> 2, tig = lane & 3;

    if (tid < 256) {
        sw_h[tid] = __float2half_rn(wscore[tid]);
        sb[tid] = b_h2h[tid];
    }

    // ========== PROLOG: projH slice -> sPH, batch_H -> g_batchH_f8 ==========
    {
        // stage Wi2h_f8 [256][256] into Bs8+As8 region, stride WISTR=264.
        // 264 is only 8-aligned -> use uint2 (8B) smem stores, NOT uint4.
        uint8_t* WB = Bs8;
#pragma unroll
        for (int i = 0; i < 8; i++) {
            int linear = tid + (i << 9);
            int row = linear >> 4, c = (linear & 15) << 4;
            uint4 v = *(const uint4*)(g_Wi2h_f8 + row * 256 + c);
            *(uint2*)&WB[row * WISTR + c] = make_uint2(v.x, v.y);
            *(uint2*)&WB[row * WISTR + c + 8] = make_uint2(v.z, v.w);
        }
        __syncthreads();

        const float* Abase = batch_H + (size_t)bid * 512 * ISZ;
        const int pwm = (warp >> 2) * 16;   // 0..48
        const int pwn = (warp & 3) * 64;    // 0..192
        const float sc = 1.0f / 16.0f;

        for (int mc = 0; mc < 8; mc++) {
            const int tb2 = mc * 64;
            float acc[8][4];
#pragma unroll
            for (int i = 0; i < 8; i++)
#pragma unroll
                for (int j = 0; j < 4; j++) acc[i][j] = 0.0f;

            const float* ar0 = Abase + (size_t)(tb2 + pwm + gID) * ISZ;
            const float* ar1 = ar0 + 8 * ISZ;

#pragma unroll 2
            for (int kk = 0; kk < 256; kk += 32) {
                float4 f;
                f = *(const float4*)(ar0 + kk + tig * 4);
                uint32_t a0 = pack_e4m3x4(f.x, f.y, f.z, f.w);
                f = *(const float4*)(ar1 + kk + tig * 4);
                uint32_t a1 = pack_e4m3x4(f.x, f.y, f.z, f.w);
                f = *(const float4*)(ar0 + kk + 16 + tig * 4);
                uint32_t a2 = pack_e4m3x4(f.x, f.y, f.z, f.w);
                f = *(const float4*)(ar1 + kk + 16 + tig * 4);
                uint32_t a3 = pack_e4m3x4(f.x, f.y, f.z, f.w);

                if (pwn == 0) {   // one warp-column dumps batchH as e4m3
                    uint8_t* d = g_batchH_f8 +
                        (size_t)(bid * 512 + tb2 + pwm + gID) * ISZ + kk + tig * 4;
                    *(uint32_t*)d = a0;
                    *(uint32_t*)(d + 16) = a2;
                    uint8_t* d1 = d + 8 * ISZ;
                    *(uint32_t*)d1 = a1;
                    *(uint32_t*)(d1 + 16) = a3;
                }
#pragma unroll
                for (int nt = 0; nt < 8; nt++) {
                    int n = pwn + nt * 8 + gID;
                    uint32_t b0 = *(uint32_t*)&WB[n * WISTR + kk + tig * 4];
                    uint32_t b1 = *(uint32_t*)&WB[n * WISTR + kk + 16 + tig * 4];
                    MMA_E4M3(acc[nt], a0, a1, a2, a3, b0, b1);
                }
            }
            // epilogue: /16, pack e4m3 pairs -> sPH
            const int r0 = tb2 + pwm + gID;
#pragma unroll
            for (int nt = 0; nt < 8; nt++) {
                int cb = pwn + nt * 8 + 2 * tig;
                *(uint16_t*)&sPH[r0 * PHSTR + cb] =
                    h2_to_e4m3x2(__floats2half2_rn(acc[nt][0] * sc, acc[nt][1] * sc));
                *(uint16_t*)&sPH[(r0 + 8) * PHSTR + cb] =
                    h2_to_e4m3x2(__floats2half2_rn(acc[nt][2] * sc, acc[nt][3] * sc));
            }
        }
        __syncthreads();

        // now load Wcat_f8 slab into Bs8 (overwrites WB low half)
#pragma unroll
        for (int i = 0; i < 4; i++) {
            int linear = tid + (i << 9);
            int row = linear >> 5, c16 = (linear & 31) << 4;
            *(uint4*)&Bs8[row * XSTR + c16] =
                *(const uint4*)(g_Wcat_f8 + ((size_t)(n0 + row)) * XDIM + c16);
        }
        __syncthreads();
    }

    __half2 swl2[4];
    {
        uint4 v = *(const uint4*)(sw_h + lane * 8);
        swl2[0] = *(__half2*)&v.x; swl2[1] = *(__half2*)&v.y;
        swl2[2] = *(__half2*)&v.z; swl2[3] = *(__half2*)&v.w;
    }

    for (int s = 0; s < NSTEP; s++) {
        // ==== LSTM(s-1) -> h ====
        {
            const int r = tid >> 7, jb = tid & 127;
            const int row = b0 + r;
            if (s > 0) {
                const float* g = g_gates + (size_t)row * GDIM;
                float* cp = g_c + (size_t)row * HSZ;
#pragma unroll
                for (int jj = 0; jj < 2; jj++) {
                    int j = jb + (jj << 7);
                    float ig = fast_sigmoid(g[j]);
                    float fg = fast_sigmoid(g[j + 256]);
                    float gg = tanh_fast(g[j + 512]);
                    float og = fast_sigmoid(g[j + 768]);
                    float cn = fg * cp[j] + ig * gg;
                    float hn = og * tanh_fast(cn);
                    cp[j] = cn;
                    sh[r * HSZ + j] = __float2half_rn(hn);
                    uint8_t hb = f32_to_e4m3(hn);
                    g_X_f8[(size_t)row * XDIM + 256 + j] = hb;
                    g_hs_f8[((size_t)row * NSTEP + (s - 1)) * HSZ + j] = hb;
                }
            } else {
                __half z = __float2half_rn(0.0f);
#pragma unroll
                for (int jj = 0; jj < 2; jj++) {
                    int j = jb + (jj << 7);
                    sh[r * HSZ + j] = z;
                    g_X_f8[(size_t)row * XDIM + 256 + j] = 0;
                }
            }
        }
        __syncthreads();

        // ==== projh partials: warp w covers k in [w*16, +16) ====
        {
            const int kb = warp << 4;
            __half2 acc2[RPB][4];
#pragma unroll
            for (int r = 0; r < RPB; r++)
#pragma unroll
                for (int p = 0; p < 4; p++)
                    acc2[r][p] = __floats2half2_rn(0.f, 0.f);

            const __half* WT = g_Wh2hT_h + (size_t)kb * HSZ + lane * 8;
#pragma unroll 4
            for (int k = 0; k < 16; k++) {
                uint4 wv = *(const uint4*)(WT + k * HSZ);
                __half2 wh[4];
                wh[0] = *(__half2*)&wv.x; wh[1] = *(__half2*)&wv.y;
                wh[2] = *(__half2*)&wv.z; wh[3] = *(__half2*)&wv.w;
#pragma unroll
                for (int r = 0; r < RPB; r++) {
                    __half2 hk2 = __half2half2(sh[r * HSZ + kb + k]);
#pragma unroll
                    for (int p = 0; p < 4; p++)
                        acc2[r][p] = __hfma2(wh[p], hk2, acc2[r][p]);
                }
            }
#pragma unroll
            for (int r = 0; r < RPB; r++)
#pragma unroll
                for (int p = 0; p < 4; p++)
                    redh[((warp * RPB + r) << 7) + lane * 4 + p] = acc2[r][p];
        }
        __syncthreads();

        // ==== reduce 16 partials -> sp_h ====
        {
            const int r = tid >> 7, j2 = tid & 127;
            float2 sum = make_float2(0.f, 0.f);
#pragma unroll
            for (int w = 0; w < 16; w++) {
                float2 v = __half22float2(redh[(((w * RPB + r)) << 7) + j2]);
                sum.x += v.x; sum.y += v.y;
            }
            float2 bv = *(const float2*)&sb[j2 * 2];
            *(__half2*)&sp_h[r * HSZ + j2 * 2] =
                __floats2half2_rn(sum.x + bv.x, sum.y + bv.y);
        }
        __syncthreads();

        // ==== scores: 4 warps per row, 32 t each, projH from SMEM ====
        {
            const int r = warp >> 2;
            const int tb = (warp & 3) << 5;
            __half2 spl2[4];
            {
                uint4 v = *(const uint4*)(sp_h + r * HSZ + lane * 8);
                spl2[0] = *(__half2*)&v.x; spl2[1] = *(__half2*)&v.y;
                spl2[2] = *(__half2*)&v.z; spl2[3] = *(__half2*)&v.w;
            }
            const uint8_t* pH = sPH + (size_t)(r * TLEN + tb) * PHSTR + lane * 8;
            for (int t = 0; t < 32; t += 8) {
                uint2 v[8];
#pragma unroll
                for (int u = 0; u < 8; u++)
                    v[u] = *(const uint2*)(pH + (t + u) * PHSTR);
                float ac[8];
#pragma unroll
                for (int u = 0; u < 8; u++) {
                    __half2 d0 = e4m3x2_to_h2((uint16_t)(v[u].x & 0xffffu));
                    __half2 d1 = e4m3x2_to_h2((uint16_t)(v[u].x >> 16));
                    __half2 d2 = e4m3x2_to_h2((uint16_t)(v[u].y & 0xffffu));
                    __half2 d3 = e4m3x2_to_h2((uint16_t)(v[u].y >> 16));
                    __half2 prod = __floats2half2_rn(0.f, 0.f);
                    prod = __hfma2(swl2[0], tanh2(__hadd2(d0, spl2[0])), prod);
                    prod = __hfma2(swl2[1], tanh2(__hadd2(d1, spl2[1])), prod);
                    prod = __hfma2(swl2[2], tanh2(__hadd2(d2, spl2[2])), prod);
                    prod = __hfma2(swl2[3], tanh2(__hadd2(d3, spl2[3])), prod);
                    float2 f = __half22float2(prod);
                    ac[u] = f.x + f.y;
                }
#pragma unroll
                for (int u = 0; u < 8; u++) {
#pragma unroll
                    for (int o = 16; o; o >>= 1)
                        ac[u] += __shfl_xor_sync(0xffffffffu, ac[u], o);
                    if (lane == 0) se[r * TLEN + tb + t + u] = ac[u];
                }
            }
        }
        __syncthreads();

        // ==== softmax -> seh (warps 0..3) ====
        if (warp < RPB) {
            const float* sr = se + warp * TLEN;
            float v0 = sr[lane], v1 = sr[lane + 32];
            float v2 = sr[lane + 64], v3 = sr[lane + 96];
            float mx = fmaxf(fmaxf(v0, v1), fmaxf(v2, v3));
#pragma unroll
            for (int o = 16; o; o >>= 1) mx = fmaxf(mx, __shfl_xor_sync(0xffffffffu, mx, o));
            float e0 = __expf(v0 - mx), e1 = __expf(v1 - mx);
            float e2 = __expf(v2 - mx), e3 = __expf(v3 - mx);
            float sum = e0 + e1 + e2 + e3;
#pragma unroll
            for (int o = 16; o; o >>= 1) sum += __shfl_xor_sync(0xffffffffu, sum, o);
            float inv = 1.0f / sum;
            __half2* dr = seh + warp * TLEN;
            dr[lane]      = __float2half2_rn(e0 * inv);
            dr[lane + 32] = __float2half2_rn(e1 * inv);
            dr[lane + 64] = __float2half2_rn(e2 * inv);
            dr[lane + 96] = __float2half2_rn(e3 * inv);
        }
        __syncthreads();

        // ==== context: thread owns (r, 2 i's), fp8 batchH -> X e4m3 ====
        {
            const int r = tid >> 7, ci = tid & 127;
            const uint8_t* bH = g_batchH_f8 + (size_t)(b0 + r) * TLEN * ISZ + ci * 2;
            const __half2* al = seh + r * TLEN;
            __half2 a0 = __floats2half2_rn(0.f, 0.f);
#pragma unroll 8
            for (int t = 0; t < TLEN; t++) {
                uint16_t us = *(const uint16_t*)(bH + t * ISZ);
                a0 = __hfma2(al[t], e4m3x2_to_h2(us), a0);
            }
            *(uint16_t*)(g_X_f8 + (size_t)(b0 + r) * XDIM + ci * 2) =
                h2_to_e4m3x2(a0);
        }

        group_sync(grp);   // X ready within group

        // ==== gates tile = (X[m0:+64] @ Wcat[n0:+64]^T)/16, e4m3 MMA ====
        {
#pragma unroll
            for (int i = 0; i < 4; i++) {
                int linear = tid + (i << 9);
                int row = linear >> 5, c16 = (linear & 31) << 4;
                *(uint4*)&As8[row * XSTR + c16] =
                    *(const uint4*)(g_X_f8 + ((size_t)(m0 + row)) * XDIM + c16);
            }
            __syncthreads();

            float acc[2][4];
#pragma unroll
            for (int i = 0; i < 2; i++)
#pragma unroll
                for (int j = 0; j < 4; j++) acc[i][j] = 0.0f;

#pragma unroll 4
            for (int kk = 0; kk < 512; kk += 32) {
                uint32_t a0 = *(uint32_t*)&As8[(wm4 + gID) * XSTR + kk + tig * 4];
                uint32_t a1 = *(uint32_t*)&As8[(wm4 + gID + 8) * XSTR + kk + tig * 4];
                uint32_t a2 = *(uint32_t*)&As8[(wm4 + gID) * XSTR + kk + 16 + tig * 4];
                uint32_t a3 = *(uint32_t*)&As8[(wm4 + gID + 8) * XSTR + kk + 16 + tig * 4];
#pragma unroll
                for (int nt = 0; nt < 2; nt++) {
                    uint32_t b0 = *(uint32_t*)&Bs8[(wn4 + nt * 8 + gID) * XSTR + kk + tig * 4];
                    uint32_t b1 = *(uint32_t*)&Bs8[(wn4 + nt * 8 + gID) * XSTR + kk + 16 + tig * 4];
                    MMA_E4M3(acc[nt], a0, a1, a2, a3, b0, b1);
                }
            }

            const int r0 = m0 + wm4 + gID, r1 = r0 + 8;
            int tgt0 = text[r0 * NSTEP + s];
            int tgt1 = text[r1 * NSTEP + s];
            const float* e0 = g_Wemb + (size_t)tgt0 * GDIM;
            const float* e1 = g_Wemb + (size_t)tgt1 * GDIM;
            const float sc = 1.0f / 16.0f;
#pragma unroll
            for (int nt = 0; nt < 2; nt++) {
                int cbase = n0 + wn4 + nt * 8 + 2 * tig;
                float2 w0 = *(const float2*)(e0 + cbase);
                float2 w1 = *(const float2*)(e1 + cbase);
                float2 o0 = make_float2(acc[nt][0] * sc + w0.x, acc[nt][1] * sc + w0.y);
                float2 o1 = make_float2(acc[nt][2] * sc + w1.x, acc[nt][3] * sc + w1.y);
                *(float2*)&g_gates[(size_t)r0 * GDIM + cbase] = o0;
                *(float2*)&g_gates[(size_t)r1 * GDIM + cbase] = o1;
            }
        }

        group_sync(grp);   // gates ready within group
    }

    // final LSTM -> hs[25]
    {
        const int r = tid >> 7, jb = tid & 127;
        const int row = b0 + r;
        const float* g = g_gates + (size_t)row * GDIM;
        const float* cp = g_c + (size_t)row * HSZ;
#pragma unroll
        for (int jj = 0; jj < 2; jj++) {
            int j = jb + (jj << 7);
            float ig = fast_sigmoid(g[j]);
            float fg = fast_sigmoid(g[j + 256]);
            float gg = tanh_fast(g[j + 512]);
            float og = fast_sigmoid(g[j + 768]);
            float cn = fg * cp[j] + ig * gg;
            float hn = og * tanh_fast(cn);
            g_hs_f8[((size_t)row * NSTEP + (NSTEP - 1)) * HSZ + j] = f32_to_e4m3(hn);
        }
    }
}

// ------------------------- launch -------------------------------------------
extern "C" void kernel_launch(void* const* d_in, const int* in_sizes, int n_in,
                              void* d_out, int out_size) {
    const float* batch_H = (const float*)d_in[0];
    const int*   text    = (const int*)d_in[1];
    const float* W_i2h   = (const float*)d_in[3];
    const float* W_h2h   = (const float*)d_in[4];
    const float* b_h2h   = (const float*)d_in[5];
    const float* W_score = (const float*)d_in[6];
    const float* W_ih    = (const float*)d_in[7];
    const float* W_hh    = (const float*)d_in[8];
    const float* b_ih    = (const float*)d_in[9];
    const float* b_hh    = (const float*)d_in[10];
    const float* W_gen   = (const float*)d_in[11];
    const float* b_gen   = (const float*)d_in[12];
    float* out = (float*)d_out;

    uint8_t *Wgen_f8, *hs_f8;
    cudaGetSymbolAddress((void**)&Wgen_f8, g_Wgen_f8);
    cudaGetSymbolAddress((void**)&hs_f8,   g_hs_f8);

    static bool attr_set = false;
    if (!attr_set) {
        cudaFuncSetAttribute(persistent_steps,
                             cudaFuncAttributeMaxDynamicSharedMemorySize,
                             SMEM_BYTES);
        attr_set = true;
    }

    init_kernel<<<2048, 256>>>(W_ih, W_hh, b_ih, b_hh, W_i2h, W_h2h, W_gen);

    // prolog GEMM fused into the persistent kernel (projH lives in smem)
    persistent_steps<<<NBLK, NTHR, SMEM_BYTES>>>(batch_H, text, b_h2h, W_score);

    // logits = (hs @ (16*W_gen)^T)/16 + b_gen, blank masked
    qgemm_logits<<<dim3(2, 104), 256>>>(
        hs_f8, Wgen_f8, out, BSZ * NSTEP, NCLS, HSZ, HSZ, HSZ, NCLS, b_gen);
}

// round 12
// speedup vs baseline: 5.4001x; 1.1028x over previous
#include <cuda_runtime.h>
#include <cuda_fp16.h>
#include <cstdint>

#define BSZ   512
#define TLEN  128
#define ISZ   256
#define HSZ   256
#define NCLS  100
#define NSTEP 26
#define XDIM  512
#define GDIM  1024
#define WIH_LD 356
#define BLANK_ID 3
#define RPB   4
#define NBLK  128
#define GRPBLK 32
#define NTHR  512
#define XSTR  528            // gates smem slab row stride (bytes), 16-aligned
#define PHSTR 272            // projH smem row stride (bytes), 16-aligned
#define WISTR 264            // Wi2h staging stride (bytes), 8-aligned ONLY
#define CSTR  136            // context-combine row stride (half2), bank-safe
#define TAIL_BYTES (2048 + 2048 + 512 + 1024 + 2048 + 2048)
#define SMEM_BYTES (512 * PHSTR + 2 * 64 * XSTR + TAIL_BYTES)   // 216576

// ------------------------- device scratch -----------------------------------
__device__ uint8_t g_batchH_f8[BSZ * TLEN * ISZ];
__device__ uint8_t g_X_f8[BSZ * XDIM];
__device__ float  g_gates[BSZ * GDIM];
__device__ float  g_c[BSZ * HSZ];
__device__ uint8_t g_hs_f8[BSZ * NSTEP * HSZ];
__device__ uint8_t g_Wcat_f8[GDIM * XDIM];     // x16 scaled
__device__ uint8_t g_Wi2h_f8[HSZ * ISZ];       // x16 scaled
__device__ uint8_t g_Wgen_f8[NCLS * HSZ];      // x16 scaled
__device__ __half g_Wh2hT_h[HSZ * HSZ];
__device__ float  g_Wemb[NCLS * GDIM];
__device__ unsigned g_count[4 * 32];
__device__ volatile unsigned g_epoch[4 * 32];

// ------------------------- fast math ----------------------------------------
__device__ __forceinline__ float tanh_fast(float x) {
    float y;
    asm("tanh.approx.f32 %0, %1;" : "=f"(y) : "f"(x));
    return y;
}
__device__ __forceinline__ float fast_sigmoid(float x) {
    return 0.5f * (1.0f + tanh_fast(0.5f * x));
}
__device__ __forceinline__ __half2 tanh2(__half2 x) {
    uint32_t xi = *(uint32_t*)&x, yo;
    asm("tanh.approx.f16x2 %0, %1;" : "=r"(yo) : "r"(xi));
    return *(__half2*)&yo;
}
__device__ __forceinline__ uint16_t h2_to_e4m3x2(__half2 h) {
    uint16_t r;
    asm("cvt.rn.satfinite.e4m3x2.f16x2 %0, %1;" : "=h"(r) : "r"(*(uint32_t*)&h));
    return r;
}
__device__ __forceinline__ __half2 e4m3x2_to_h2(uint16_t b) {
    uint32_t r;
    asm("cvt.rn.f16x2.e4m3x2 %0, %1;" : "=r"(r) : "h"(b));
    return *(__half2*)&r;
}
__device__ __forceinline__ uint8_t f32_to_e4m3(float v) {
    return (uint8_t)h2_to_e4m3x2(__floats2half2_rn(v, v));
}
__device__ __forceinline__ uint32_t pack_e4m3x4(float a, float b, float c, float d) {
    return (uint32_t)h2_to_e4m3x2(__floats2half2_rn(a, b)) |
           ((uint32_t)h2_to_e4m3x2(__floats2half2_rn(c, d)) << 16);
}
#define MMA_E4M3(acc, a0, a1, a2, a3, b0, b1)                                  \
    asm volatile(                                                              \
        "mma.sync.aligned.m16n8k32.row.col.f32.e4m3.e4m3.f32 "                 \
        "{%0,%1,%2,%3}, {%4,%5,%6,%7}, {%8,%9}, {%0,%1,%2,%3};"                \
        : "+f"(acc[0]), "+f"(acc[1]), "+f"(acc[2]), "+f"(acc[3])               \
        : "r"(a0), "r"(a1), "r"(a2), "r"(a3), "r"(b0), "r"(b1))

// ------------------------- group barrier (32 blocks) -------------------------
__device__ __forceinline__ void group_sync(int g) {
    __syncthreads();
    if (threadIdx.x == 0) {
        const int slot = g * 32;
        unsigned my = g_epoch[slot];
        __threadfence();
        unsigned old = atomicAdd(&g_count[slot], 1u);
        if (old == GRPBLK - 1) {
            g_count[slot] = 0;
            __threadfence();
            g_epoch[slot] = my + 1;
        } else {
            while (g_epoch[slot] == my) { __nanosleep(16); }
            __threadfence();
        }
    }
    __syncthreads();
}

// ------------------------- init ----------------------------------------------
__global__ void init_kernel(const float* __restrict__ W_ih,
                            const float* __restrict__ W_hh,
                            const float* __restrict__ b_ih,
                            const float* __restrict__ b_hh,
                            const float* __restrict__ W_i2h,
                            const float* __restrict__ W_h2h,
                            const float* __restrict__ W_gen) {
    int idx = blockIdx.x * 256 + threadIdx.x;
    if (idx < GDIM * XDIM) {
        int j = idx >> 9, k = idx & 511;
        float v = (k < 256) ? W_ih[j * WIH_LD + k] : W_hh[j * 256 + (k - 256)];
        g_Wcat_f8[idx] = f32_to_e4m3(v * 16.0f);
    }
    if (idx < HSZ * HSZ) {
        int j = idx >> 8, k = idx & 255;
        g_Wh2hT_h[k * HSZ + j] = __float2half_rn(W_h2h[idx]);
        g_Wi2h_f8[idx] = f32_to_e4m3(W_i2h[idx] * 16.0f);
    }
    if (idx < NCLS * HSZ) g_Wgen_f8[idx] = f32_to_e4m3(W_gen[idx] * 16.0f);
    if (idx < NCLS * GDIM) {
        int cls = idx >> 10, c = idx & 1023;
        g_Wemb[idx] = W_ih[(size_t)c * WIH_LD + 256 + cls] + b_ih[c] + b_hh[c];
    }
    if (idx < BSZ * HSZ) g_c[idx] = 0.0f;
}

// ------------------------- e4m3 MMA GEMM (logits), tile 128x64 ---------------
__global__ __launch_bounds__(256) void qgemm_logits(
    const uint8_t* __restrict__ Aptr, const uint8_t* __restrict__ Bw,
    float* __restrict__ Cm,
    int M, int N, int K, int lda, int ldb, int ldc,
    const float* __restrict__ bias) {

    __shared__ uint8_t As[128 * 80];
    __shared__ uint8_t Bs[64 * 80];

    const int m0 = blockIdx.y * 128, n0 = blockIdx.x * 64;
    const int tid = threadIdx.x, lane = tid & 31, warp = tid >> 5;
    const int wm = (warp >> 1) * 32, wn = (warp & 1) * 32;
    const int gID = lane >> 2, tig = lane & 3;
    const int ar = tid >> 1, aoff = (tid & 1) << 5;
    const int br = tid >> 2, boff = (tid & 3) << 4;

    float acc[2][4][4];
#pragma unroll
    for (int mf = 0; mf < 2; mf++)
#pragma unroll
        for (int i = 0; i < 4; i++)
#pragma unroll
            for (int j = 0; j < 4; j++) acc[mf][i][j] = 0.0f;

    auto loadA = [&](int k0, uint4& o0, uint4& o1) {
        const uint8_t* p = Aptr + (size_t)(m0 + ar) * lda + k0 + aoff;
        o0 = *(const uint4*)p;
        o1 = *(const uint4*)(p + 16);
    };
    auto loadB = [&](int k0) -> uint4 {
        if (n0 + br < N)
            return *(const uint4*)(Bw + (size_t)(n0 + br) * ldb + k0 + boff);
        return make_uint4(0u, 0u, 0u, 0u);
    };

    uint4 a0R, a1R, bR;
    loadA(0, a0R, a1R);
    bR = loadB(0);
    const int iters = K >> 6;

    for (int it = 0; it < iters; it++) {
        __syncthreads();
        *(uint4*)&As[ar * 80 + aoff] = a0R;
        *(uint4*)&As[ar * 80 + aoff + 16] = a1R;
        *(uint4*)&Bs[br * 80 + boff] = bR;
        __syncthreads();
        if (it + 1 < iters) {
            loadA((it + 1) << 6, a0R, a1R);
            bR = loadB((it + 1) << 6);
        }
#pragma unroll
        for (int kk = 0; kk < 64; kk += 32) {
            uint32_t af[2][4];
#pragma unroll
            for (int mf = 0; mf < 2; mf++) {
                int rb = wm + mf * 16 + gID;
                af[mf][0] = *(uint32_t*)&As[rb * 80 + kk + tig * 4];
                af[mf][1] = *(uint32_t*)&As[(rb + 8) * 80 + kk + tig * 4];
                af[mf][2] = *(uint32_t*)&As[rb * 80 + kk + 16 + tig * 4];
                af[mf][3] = *(uint32_t*)&As[(rb + 8) * 80 + kk + 16 + tig * 4];
            }
#pragma unroll
            for (int nt = 0; nt < 4; nt++) {
                uint32_t b0 = *(uint32_t*)&Bs[(wn + nt * 8 + gID) * 80 + kk + tig * 4];
                uint32_t b1 = *(uint32_t*)&Bs[(wn + nt * 8 + gID) * 80 + kk + 16 + tig * 4];
#pragma unroll
                for (int mf = 0; mf < 2; mf++)
                    MMA_E4M3(acc[mf][nt], af[mf][0], af[mf][1], af[mf][2],
                             af[mf][3], b0, b1);
            }
        }
    }

    const float sc = 1.0f / 16.0f;
#pragma unroll
    for (int mf = 0; mf < 2; mf++) {
        const int r0 = m0 + wm + mf * 16 + gID, r1 = r0 + 8;
#pragma unroll
        for (int nt = 0; nt < 4; nt++) {
            int cb = n0 + wn + nt * 8 + 2 * tig;
#pragma unroll
            for (int hr = 0; hr < 2; hr++) {
                int r = hr ? r1 : r0;
                if (r >= M || cb >= N) continue;
                float v0 = acc[mf][nt][hr * 2 + 0] * sc + bias[cb];
                float v1 = acc[mf][nt][hr * 2 + 1] * sc + bias[cb + 1];
                if (cb == BLANK_ID) v0 = -10000.0f;
                if (cb + 1 == BLANK_ID) v1 = -10000.0f;
                *(float2*)(Cm + (size_t)r * ldc + cb) = make_float2(v0, v1);
            }
        }
    }
}

// ------------------------- persistent kernel: prolog + 26 steps --------------
__global__ __launch_bounds__(NTHR, 1) void persistent_steps(
    const float* __restrict__ batch_H, const int* __restrict__ text,
    const float* __restrict__ b_h2h, const float* __restrict__ wscore) {

    extern __shared__ char dyn[];
    uint8_t* sPH = (uint8_t*)dyn;                       // [512][PHSTR]
    uint8_t* Bs8 = sPH + 512 * PHSTR;                   // [64][XSTR]
    uint8_t* As8 = Bs8 + 64 * XSTR;                     // [64][XSTR]
    __half2* redh = (__half2*)As8;                      // overlay (phase A)
    char* tail = (char*)(As8 + 64 * XSTR);
    __half*  sh   = (__half*)tail;                      // [4][256]
    __half*  sp_h = sh + 1024;                          // [4][256]
    __half*  sw_h = sp_h + 1024;                        // [256]
    float*   sb   = (float*)(sw_h + 256);               // [256]
    float*   se   = sb + 256;                           // [4][128]
    __half2* seh  = (__half2*)(se + 512);               // [4][128]

    const int tid = threadIdx.x, lane = tid & 31, warp = tid >> 5;
    const int bid = blockIdx.x;
    const int grp = bid >> 5;
    const int lid = bid & 31;
    const int b0 = bid * RPB;
    const int m0 = grp * 128 + (lid >> 4) * 64;
    const int n0 = (lid & 15) * 64;
    const int wm4 = (warp >> 2) * 16, wn4 = (warp & 3) * 16;
    const int gID = lane >> 2, tig = lane & 3;

    if (tid < 256) {
        sw_h[tid] = __float2half_rn(wscore[tid]);
        sb[tid] = b_h2h[tid];
    }

    // ========== PROLOG: projH slice -> sPH, batch_H -> g_batchH_f8 ==========
    {
        uint8_t* WB = Bs8;
#pragma unroll
        for (int i = 0; i < 8; i++) {
            int linear = tid + (i << 9);
            int row = linear >> 4, c = (linear & 15) << 4;
            uint4 v = *(const uint4*)(g_Wi2h_f8 + row * 256 + c);
            *(uint2*)&WB[row * WISTR + c] = make_uint2(v.x, v.y);
            *(uint2*)&WB[row * WISTR + c + 8] = make_uint2(v.z, v.w);
        }
        __syncthreads();

        const float* Abase = batch_H + (size_t)bid * 512 * ISZ;
        const int pwm = (warp >> 2) * 16;
        const int pwn = (warp & 3) * 64;
        const float sc = 1.0f / 16.0f;

        for (int mc = 0; mc < 8; mc++) {
            const int tb2 = mc * 64;
            float acc[8][4];
#pragma unroll
            for (int i = 0; i < 8; i++)
#pragma unroll
                for (int j = 0; j < 4; j++) acc[i][j] = 0.0f;

            const float* ar0 = Abase + (size_t)(tb2 + pwm + gID) * ISZ;
            const float* ar1 = ar0 + 8 * ISZ;

#pragma unroll 2
            for (int kk = 0; kk < 256; kk += 32) {
                float4 f;
                f = *(const float4*)(ar0 + kk + tig * 4);
                uint32_t a0 = pack_e4m3x4(f.x, f.y, f.z, f.w);
                f = *(const float4*)(ar1 + kk + tig * 4);
                uint32_t a1 = pack_e4m3x4(f.x, f.y, f.z, f.w);
                f = *(const float4*)(ar0 + kk + 16 + tig * 4);
                uint32_t a2 = pack_e4m3x4(f.x, f.y, f.z, f.w);
                f = *(const float4*)(ar1 + kk + 16 + tig * 4);
                uint32_t a3 = pack_e4m3x4(f.x, f.y, f.z, f.w);

                if (pwn == 0) {
                    uint8_t* d = g_batchH_f8 +
                        (size_t)(bid * 512 + tb2 + pwm + gID) * ISZ + kk + tig * 4;
                    *(uint32_t*)d = a0;
                    *(uint32_t*)(d + 16) = a2;
                    uint8_t* d1 = d + 8 * ISZ;
                    *(uint32_t*)d1 = a1;
                    *(uint32_t*)(d1 + 16) = a3;
                }
#pragma unroll
                for (int nt = 0; nt < 8; nt++) {
                    int n = pwn + nt * 8 + gID;
                    uint32_t b0 = *(uint32_t*)&WB[n * WISTR + kk + tig * 4];
                    uint32_t b1 = *(uint32_t*)&WB[n * WISTR + kk + 16 + tig * 4];
                    MMA_E4M3(acc[nt], a0, a1, a2, a3, b0, b1);
                }
            }
            const int r0 = tb2 + pwm + gID;
#pragma unroll
            for (int nt = 0; nt < 8; nt++) {
                int cb = pwn + nt * 8 + 2 * tig;
                *(uint16_t*)&sPH[r0 * PHSTR + cb] =
                    h2_to_e4m3x2(__floats2half2_rn(acc[nt][0] * sc, acc[nt][1] * sc));
                *(uint16_t*)&sPH[(r0 + 8) * PHSTR + cb] =
                    h2_to_e4m3x2(__floats2half2_rn(acc[nt][2] * sc, acc[nt][3] * sc));
            }
        }
        __syncthreads();

#pragma unroll
        for (int i = 0; i < 4; i++) {
            int linear = tid + (i << 9);
            int row = linear >> 5, c16 = (linear & 31) << 4;
            *(uint4*)&Bs8[row * XSTR + c16] =
                *(const uint4*)(g_Wcat_f8 + ((size_t)(n0 + row)) * XDIM + c16);
        }
        __syncthreads();
    }

    __half2 swl2[4];
    {
        uint4 v = *(const uint4*)(sw_h + lane * 8);
        swl2[0] = *(__half2*)&v.x; swl2[1] = *(__half2*)&v.y;
        swl2[2] = *(__half2*)&v.z; swl2[3] = *(__half2*)&v.w;
    }

    for (int s = 0; s < NSTEP; s++) {
        // ==== LSTM(s-1) -> h : float2 loads, 2 consecutive cells/thread ====
        {
            const int r = tid >> 7, jb = tid & 127;   // j = 2*jb, 2*jb+1
            const int row = b0 + r;
            const int j2 = jb * 2;
            if (s > 0) {
                const float* g = g_gates + (size_t)row * GDIM;
                float* cp = g_c + (size_t)row * HSZ;
                float2 gi = *(const float2*)&g[j2];
                float2 gf = *(const float2*)&g[j2 + 256];
                float2 gg = *(const float2*)&g[j2 + 512];
                float2 go = *(const float2*)&g[j2 + 768];
                float2 co = *(const float2*)&cp[j2];
                float cn0 = fast_sigmoid(gf.x) * co.x +
                            fast_sigmoid(gi.x) * tanh_fast(gg.x);
                float cn1 = fast_sigmoid(gf.y) * co.y +
                            fast_sigmoid(gi.y) * tanh_fast(gg.y);
                float hn0 = fast_sigmoid(go.x) * tanh_fast(cn0);
                float hn1 = fast_sigmoid(go.y) * tanh_fast(cn1);
                *(float2*)&cp[j2] = make_float2(cn0, cn1);
                __half2 hh = __floats2half2_rn(hn0, hn1);
                *(__half2*)&sh[r * HSZ + j2] = hh;
                uint16_t hb = h2_to_e4m3x2(hh);
                *(uint16_t*)(g_X_f8 + (size_t)row * XDIM + 256 + j2) = hb;
                *(uint16_t*)(g_hs_f8 + ((size_t)row * NSTEP + (s - 1)) * HSZ + j2) = hb;
            } else {
                *(__half2*)&sh[r * HSZ + j2] = __floats2half2_rn(0.f, 0.f);
                *(uint16_t*)(g_X_f8 + (size_t)row * XDIM + 256 + j2) = 0;
            }
        }
        __syncthreads();

        // ==== projh partials: warp w covers k in [w*16, +16) ====
        {
            const int kb = warp << 4;
            __half2 acc2[RPB][4];
#pragma unroll
            for (int r = 0; r < RPB; r++)
#pragma unroll
                for (int p = 0; p < 4; p++)
                    acc2[r][p] = __floats2half2_rn(0.f, 0.f);

            const __half* WT = g_Wh2hT_h + (size_t)kb * HSZ + lane * 8;
#pragma unroll 4
            for (int k = 0; k < 16; k++) {
                uint4 wv = *(const uint4*)(WT + k * HSZ);
                __half2 wh[4];
                wh[0] = *(__half2*)&wv.x; wh[1] = *(__half2*)&wv.y;
                wh[2] = *(__half2*)&wv.z; wh[3] = *(__half2*)&wv.w;
#pragma unroll
                for (int r = 0; r < RPB; r++) {
                    __half2 hk2 = __half2half2(sh[r * HSZ + kb + k]);
#pragma unroll
                    for (int p = 0; p < 4; p++)
                        acc2[r][p] = __hfma2(wh[p], hk2, acc2[r][p]);
                }
            }
#pragma unroll
            for (int r = 0; r < RPB; r++)
#pragma unroll
                for (int p = 0; p < 4; p++)
                    redh[((warp * RPB + r) << 7) + lane * 4 + p] = acc2[r][p];
        }
        __syncthreads();

        // ==== reduce 16 partials -> sp_h ====
        {
            const int r = tid >> 7, j2 = tid & 127;
            float2 sum = make_float2(0.f, 0.f);
#pragma unroll
            for (int w = 0; w < 16; w++) {
                float2 v = __half22float2(redh[(((w * RPB + r)) << 7) + j2]);
                sum.x += v.x; sum.y += v.y;
            }
            float2 bv = *(const float2*)&sb[j2 * 2];
            *(__half2*)&sp_h[r * HSZ + j2 * 2] =
                __floats2half2_rn(sum.x + bv.x, sum.y + bv.y);
        }
        __syncthreads();

        // ==== scores: 4 warps/row, 32 t each, smem projH, packed reduce ====
        {
            const int r = warp >> 2;
            const int tb = (warp & 3) << 5;
            __half2 spl2[4];
            {
                uint4 v = *(const uint4*)(sp_h + r * HSZ + lane * 8);
                spl2[0] = *(__half2*)&v.x; spl2[1] = *(__half2*)&v.y;
                spl2[2] = *(__half2*)&v.z; spl2[3] = *(__half2*)&v.w;
            }
            const uint8_t* pH = sPH + (size_t)(r * TLEN + tb) * PHSTR + lane * 8;
            for (int t = 0; t < 32; t += 8) {
                uint2 v[8];
#pragma unroll
                for (int u = 0; u < 8; u++)
                    v[u] = *(const uint2*)(pH + (t + u) * PHSTR);
                float ac[8];
#pragma unroll
                for (int u = 0; u < 8; u++) {
                    __half2 d0 = e4m3x2_to_h2((uint16_t)(v[u].x & 0xffffu));
                    __half2 d1 = e4m3x2_to_h2((uint16_t)(v[u].x >> 16));
                    __half2 d2 = e4m3x2_to_h2((uint16_t)(v[u].y & 0xffffu));
                    __half2 d3 = e4m3x2_to_h2((uint16_t)(v[u].y >> 16));
                    __half2 prod = __floats2half2_rn(0.f, 0.f);
                    prod = __hfma2(swl2[0], tanh2(__hadd2(d0, spl2[0])), prod);
                    prod = __hfma2(swl2[1], tanh2(__hadd2(d1, spl2[1])), prod);
                    prod = __hfma2(swl2[2], tanh2(__hadd2(d2, spl2[2])), prod);
                    prod = __hfma2(swl2[3], tanh2(__hadd2(d3, spl2[3])), prod);
                    float2 f = __half22float2(prod);
                    ac[u] = f.x + f.y;
                }
                // packed reduction: pairs (u, u+1) as half2, 5-stage butterfly
#pragma unroll
                for (int u = 0; u < 8; u += 2) {
                    __half2 pk = __floats2half2_rn(ac[u], ac[u + 1]);
                    uint32_t pu = *(uint32_t*)&pk;
#pragma unroll
                    for (int o = 16; o; o >>= 1) {
                        uint32_t other = __shfl_xor_sync(0xffffffffu, pu, o);
                        __half2 a = *(__half2*)&pu, b2 = *(__half2*)&other;
                        __half2 s2 = __hadd2(a, b2);
                        pu = *(uint32_t*)&s2;
                    }
                    if (lane == 0) {
                        float2 f = __half22float2(*(__half2*)&pu);
                        se[r * TLEN + tb + t + u] = f.x;
                        se[r * TLEN + tb + t + u + 1] = f.y;
                    }
                }
            }
        }
        __syncthreads();

        // ==== softmax -> seh (warps 0..3) ====
        if (warp < RPB) {
            const float* sr = se + warp * TLEN;
            float v0 = sr[lane], v1 = sr[lane + 32];
            float v2 = sr[lane + 64], v3 = sr[lane + 96];
            float mx = fmaxf(fmaxf(v0, v1), fmaxf(v2, v3));
#pragma unroll
            for (int o = 16; o; o >>= 1) mx = fmaxf(mx, __shfl_xor_sync(0xffffffffu, mx, o));
            float e0 = __expf(v0 - mx), e1 = __expf(v1 - mx);
            float e2 = __expf(v2 - mx), e3 = __expf(v3 - mx);
            float sum = e0 + e1 + e2 + e3;
#pragma unroll
            for (int o = 16; o; o >>= 1) sum += __shfl_xor_sync(0xffffffffu, sum, o);
            float inv = 1.0f / sum;
            __half2* dr = seh + warp * TLEN;
            dr[lane]      = __float2half2_rn(e0 * inv);
            dr[lane + 32] = __float2half2_rn(e1 * inv);
            dr[lane + 64] = __float2half2_rn(e2 * inv);
            dr[lane + 96] = __float2half2_rn(e3 * inv);
        }
        __syncthreads();

        // ==== context: vectorized 8B loads, 4-way t-split ====
        {
            const int r = tid >> 7;
            const int t127 = tid & 127;
            const int ci8 = t127 & 31;          // 8-i column group
            const int tq = t127 >> 5;           // t quarter
            const uint8_t* bH = g_batchH_f8 + (size_t)(b0 + r) * TLEN * ISZ + ci8 * 8;
            const __half2* al = seh + r * TLEN + tq * 32;
            const uint8_t* bHt = bH + tq * 32 * ISZ;
            __half2 a0 = __floats2half2_rn(0.f, 0.f);
            __half2 a1 = a0, a2 = a0, a3 = a0;
#pragma unroll 8
            for (int t = 0; t < 32; t++) {
                uint2 v = *(const uint2*)(bHt + t * ISZ);
                __half2 alv = al[t];
                a0 = __hfma2(alv, e4m3x2_to_h2((uint16_t)(v.x & 0xffffu)), a0);
                a1 = __hfma2(alv, e4m3x2_to_h2((uint16_t)(v.x >> 16)), a1);
                a2 = __hfma2(alv, e4m3x2_to_h2((uint16_t)(v.y & 0xffffu)), a2);
                a3 = __hfma2(alv, e4m3x2_to_h2((uint16_t)(v.y >> 16)), a3);
            }
            // store partials: redh[(tq*4+p)*CSTR + r*32 + ci8]
            int base = r * 32 + ci8;
            redh[(tq * 4 + 0) * CSTR + base] = a0;
            redh[(tq * 4 + 1) * CSTR + base] = a1;
            redh[(tq * 4 + 2) * CSTR + base] = a2;
            redh[(tq * 4 + 3) * CSTR + base] = a3;
        }
        __syncthreads();
        {
            // combine: thread owns (r, ci2 in [0,128)) -> i pair (ci8*8 + p*2)
            const int r = tid >> 7, ci2 = tid & 127;
            const int ci8 = ci2 >> 2, p = ci2 & 3;
            const int base = r * 32 + ci8;
            __half2 s0 = redh[(0 * 4 + p) * CSTR + base];
            __half2 s1 = redh[(1 * 4 + p) * CSTR + base];
            __half2 s2 = redh[(2 * 4 + p) * CSTR + base];
            __half2 s3 = redh[(3 * 4 + p) * CSTR + base];
            __half2 sum = __hadd2(__hadd2(s0, s1), __hadd2(s2, s3));
            *(uint16_t*)(g_X_f8 + (size_t)(b0 + r) * XDIM + ci8 * 8 + p * 2) =
                h2_to_e4m3x2(sum);
        }

        group_sync(grp);   // X ready within group

        // ==== gates tile = (X[m0:+64] @ Wcat[n0:+64]^T)/16, e4m3 MMA ====
        {
#pragma unroll
            for (int i = 0; i < 4; i++) {
                int linear = tid + (i << 9);
                int row = linear >> 5, c16 = (linear & 31) << 4;
                *(uint4*)&As8[row * XSTR + c16] =
                    *(const uint4*)(g_X_f8 + ((size_t)(m0 + row)) * XDIM + c16);
            }
            __syncthreads();

            float acc[2][4];
#pragma unroll
            for (int i = 0; i < 2; i++)
#pragma unroll
                for (int j = 0; j < 4; j++) acc[i][j] = 0.0f;

#pragma unroll 4
            for (int kk = 0; kk < 512; kk += 32) {
                uint32_t a0 = *(uint32_t*)&As8[(wm4 + gID) * XSTR + kk + tig * 4];
                uint32_t a1 = *(uint32_t*)&As8[(wm4 + gID + 8) * XSTR + kk + tig * 4];
                uint32_t a2 = *(uint32_t*)&As8[(wm4 + gID) * XSTR + kk + 16 + tig * 4];
                uint32_t a3 = *(uint32_t*)&As8[(wm4 + gID + 8) * XSTR + kk + 16 + tig * 4];
#pragma unroll
                for (int nt = 0; nt < 2; nt++) {
                    uint32_t b0 = *(uint32_t*)&Bs8[(wn4 + nt * 8 + gID) * XSTR + kk + tig * 4];
                    uint32_t b1 = *(uint32_t*)&Bs8[(wn4 + nt * 8 + gID) * XSTR + kk + 16 + tig * 4];
                    MMA_E4M3(acc[nt], a0, a1, a2, a3, b0, b1);
                }
            }

            const int r0 = m0 + wm4 + gID, r1 = r0 + 8;
            int tgt0 = text[r0 * NSTEP + s];
            int tgt1 = text[r1 * NSTEP + s];
            const float* e0 = g_Wemb + (size_t)tgt0 * GDIM;
            const float* e1 = g_Wemb + (size_t)tgt1 * GDIM;
            const float sc = 1.0f / 16.0f;
#pragma unroll
            for (int nt = 0; nt < 2; nt++) {
                int cbase = n0 + wn4 + nt * 8 + 2 * tig;
                float2 w0 = *(const float2*)(e0 + cbase);
                float2 w1 = *(const float2*)(e1 + cbase);
                float2 o0 = make_float2(acc[nt][0] * sc + w0.x, acc[nt][1] * sc + w0.y);
                float2 o1 = make_float2(acc[nt][2] * sc + w1.x, acc[nt][3] * sc + w1.y);
                *(float2*)&g_gates[(size_t)r0 * GDIM + cbase] = o0;
                *(float2*)&g_gates[(size_t)r1 * GDIM + cbase] = o1;
            }
        }

        group_sync(grp);   // gates ready within group
    }

    // final LSTM -> hs[25]
    {
        const int r = tid >> 7, jb = tid & 127;
        const int row = b0 + r;
        const int j2 = jb * 2;
        const float* g = g_gates + (size_t)row * GDIM;
        const float* cp = g_c + (size_t)row * HSZ;
        float2 gi = *(const float2*)&g[j2];
        float2 gf = *(const float2*)&g[j2 + 256];
        float2 gg = *(const float2*)&g[j2 + 512];
        float2 go = *(const float2*)&g[j2 + 768];
        float2 co = *(const float2*)&cp[j2];
        float cn0 = fast_sigmoid(gf.x) * co.x + fast_sigmoid(gi.x) * tanh_fast(gg.x);
        float cn1 = fast_sigmoid(gf.y) * co.y + fast_sigmoid(gi.y) * tanh_fast(gg.y);
        float hn0 = fast_sigmoid(go.x) * tanh_fast(cn0);
        float hn1 = fast_sigmoid(go.y) * tanh_fast(cn1);
        *(uint16_t*)(g_hs_f8 + ((size_t)row * NSTEP + (NSTEP - 1)) * HSZ + j2) =
            h2_to_e4m3x2(__floats2half2_rn(hn0, hn1));
    }
}

// ------------------------- launch -------------------------------------------
extern "C" void kernel_launch(void* const* d_in, const int* in_sizes, int n_in,
                              void* d_out, int out_size) {
    const float* batch_H = (const float*)d_in[0];
    const int*   text    = (const int*)d_in[1];
    const float* W_i2h   = (const float*)d_in[3];
    const float* W_h2h   = (const float*)d_in[4];
    const float* b_h2h   = (const float*)d_in[5];
    const float* W_score = (const float*)d_in[6];
    const float* W_ih    = (const float*)d_in[7];
    const float* W_hh    = (const float*)d_in[8];
    const float* b_ih    = (const float*)d_in[9];
    const float* b_hh    = (const float*)d_in[10];
    const float* W_gen   = (const float*)d_in[11];
    const float* b_gen   = (const float*)d_in[12];
    float* out = (float*)d_out;

    uint8_t *Wgen_f8, *hs_f8;
    cudaGetSymbolAddress((void**)&Wgen_f8, g_Wgen_f8);
    cudaGetSymbolAddress((void**)&hs_f8,   g_hs_f8);

    static bool attr_set = false;
    if (!attr_set) {
        cudaFuncSetAttribute(persistent_steps,
                             cudaFuncAttributeMaxDynamicSharedMemorySize,
                             SMEM_BYTES);
        attr_set = true;
    }

    init_kernel<<<2048, 256>>>(W_ih, W_hh, b_ih, b_hh, W_i2h, W_h2h, W_gen);

    persistent_steps<<<NBLK, NTHR, SMEM_BYTES>>>(batch_H, text, b_h2h, W_score);

    qgemm_logits<<<dim3(2, 104), 256>>>(
        hs_f8, Wgen_f8, out, BSZ * NSTEP, NCLS, HSZ, HSZ, HSZ, NCLS, b_gen);
}